// round 1
// baseline (speedup 1.0000x reference)
#include <cuda_runtime.h>
#include <math.h>
#include <stdint.h>
#include <stddef.h>

#define B_SZ   8
#define NTOK   1024
#define NHEAD  16
#define DHEAD  64
#define DMODEL 1024
#define SCALE  0.125f   // 64^-0.5

// Scratch (device globals: allocation-free per harness rules)
__device__ float g_q[(size_t)B_SZ * NHEAD * NTOK * DHEAD];  // [B,H,N,d], pre-scaled
__device__ float g_k[(size_t)B_SZ * NHEAD * NTOK * DHEAD];  // [B,H,N,d]
__device__ float g_v[(size_t)B_SZ * NHEAD * NTOK * DHEAD];  // [B,H,N,d]
__device__ float g_z[(size_t)B_SZ * NTOK * DMODEL];         // [B,N,C]

// ---------------------------------------------------------------------------
// Tiled GEMM: C[m,n] = sum_k A[m,k] * W[n,k] + bias[n]
//   A: [M,K] row-major, W: [N,K] row-major (torch Linear weight layout).
//   BM=BN=64, BK=16, 256 threads, 4x4 per-thread register tile.
// EPI==0: A = x, scatter into g_q/g_k/g_v (Q pre-scaled).
// EPI==1: A = g_z (ignores A arg), write out[m*N + n].
// ---------------------------------------------------------------------------
template <int EPI>
__global__ __launch_bounds__(256) void gemm_kernel(const float* __restrict__ A,
                                                   const float* __restrict__ W,
                                                   const float* __restrict__ bias,
                                                   float* __restrict__ out,
                                                   int M, int N, int K)
{
    __shared__ float As[16][68];   // As[k][row], padded
    __shared__ float Ws[16][68];   // Ws[k][col], padded

    const float* Ap = (EPI == 1) ? g_z : A;

    const int tid  = threadIdx.x;
    const int tx   = tid & 15;
    const int ty   = tid >> 4;
    const int row0 = blockIdx.y * 64;
    const int col0 = blockIdx.x * 64;
    const int lrow = tid >> 2;         // 0..63
    const int lk   = (tid & 3) << 2;   // 0,4,8,12

    float acc[4][4] = {};

    for (int k0 = 0; k0 < K; k0 += 16) {
        float4 a4 = *(const float4*)&Ap[(size_t)(row0 + lrow) * K + k0 + lk];
        float4 w4 = *(const float4*)&W [(size_t)(col0 + lrow) * K + k0 + lk];
        As[lk + 0][lrow] = a4.x; As[lk + 1][lrow] = a4.y;
        As[lk + 2][lrow] = a4.z; As[lk + 3][lrow] = a4.w;
        Ws[lk + 0][lrow] = w4.x; Ws[lk + 1][lrow] = w4.y;
        Ws[lk + 2][lrow] = w4.z; Ws[lk + 3][lrow] = w4.w;
        __syncthreads();

        #pragma unroll
        for (int k = 0; k < 16; k++) {
            float4 av = *(const float4*)&As[k][ty << 2];
            float4 wv = *(const float4*)&Ws[k][tx << 2];
            float a[4] = {av.x, av.y, av.z, av.w};
            float w[4] = {wv.x, wv.y, wv.z, wv.w};
            #pragma unroll
            for (int i = 0; i < 4; i++)
                #pragma unroll
                for (int j = 0; j < 4; j++)
                    acc[i][j] = fmaf(a[i], w[j], acc[i][j]);
        }
        __syncthreads();
    }

    #pragma unroll
    for (int i = 0; i < 4; i++) {
        int m = row0 + (ty << 2) + i;
        #pragma unroll
        for (int j = 0; j < 4; j++) {
            int c = col0 + (tx << 2) + j;
            float val = acc[i][j] + bias[c];
            if (EPI == 0) {
                int b = m >> 10, t = m & 1023;
                int part = c >> 10, hc = c & 1023;
                size_t idx = (((size_t)(b * NHEAD) + (hc >> 6)) * NTOK + t) * DHEAD + (hc & 63);
                if (part == 0)      g_q[idx] = val * SCALE;
                else if (part == 1) g_k[idx] = val;
                else                g_v[idx] = val;
            } else {
                out[(size_t)m * N + c] = val;
            }
        }
    }
}

// ---------------------------------------------------------------------------
// Flash-style attention: one CTA per (b*h, 64-query block).
// Online softmax in registers; K/V streamed in 64-token tiles; P staged in smem.
// Dynamic smem: 4 * 64 * 68 * 4 = 69632 bytes.
// ---------------------------------------------------------------------------
__global__ __launch_bounds__(256) void attn_kernel()
{
    extern __shared__ float sm[];
    float (*Qs)[68] = reinterpret_cast<float(*)[68]>(sm);                 // Q[row][d]
    float (*Ks)[68] = reinterpret_cast<float(*)[68]>(sm + 64 * 68);       // K[key][d]
    float (*Vs)[68] = reinterpret_cast<float(*)[68]>(sm + 2 * 64 * 68);   // V[key][d]
    float (*Ps)[68] = reinterpret_cast<float(*)[68]>(sm + 3 * 64 * 68);   // P[row][key]

    const int bh   = blockIdx.x;   // b*16 + h
    const int qblk = blockIdx.y;   // 0..15

    const float* Qg = g_q + ((size_t)bh * NTOK + qblk * 64) * DHEAD;
    const float* Kg = g_k + (size_t)bh * NTOK * DHEAD;
    const float* Vg = g_v + (size_t)bh * NTOK * DHEAD;

    const int tid  = threadIdx.x;
    const int tx   = tid & 15;
    const int ty   = tid >> 4;
    const int lrow = tid >> 2;          // 0..63
    const int lcol = (tid & 3) << 4;    // 0,16,32,48

    // Load Q tile once
    #pragma unroll
    for (int i = 0; i < 4; i++)
        *(float4*)&Qs[lrow][lcol + i * 4] =
            *(const float4*)&Qg[lrow * DHEAD + lcol + i * 4];

    float o[4][4] = {};
    float rm[4], rl[4];
    #pragma unroll
    for (int i = 0; i < 4; i++) { rm[i] = -INFINITY; rl[i] = 0.f; }

    for (int kt = 0; kt < 16; kt++) {
        const float* Kt = Kg + kt * 64 * DHEAD;
        const float* Vt = Vg + kt * 64 * DHEAD;
        #pragma unroll
        for (int i = 0; i < 4; i++) {
            *(float4*)&Ks[lrow][lcol + i * 4] = *(const float4*)&Kt[lrow * DHEAD + lcol + i * 4];
            *(float4*)&Vs[lrow][lcol + i * 4] = *(const float4*)&Vt[lrow * DHEAD + lcol + i * 4];
        }
        __syncthreads();

        // S = Q K^T (Q already scaled)
        float s[4][4] = {};
        #pragma unroll 8
        for (int d = 0; d < 64; d += 4) {
            float4 k4[4];
            #pragma unroll
            for (int j = 0; j < 4; j++) k4[j] = *(const float4*)&Ks[(tx << 2) + j][d];
            #pragma unroll
            for (int i = 0; i < 4; i++) {
                float4 q4 = *(const float4*)&Qs[(ty << 2) + i][d];
                #pragma unroll
                for (int j = 0; j < 4; j++) {
                    s[i][j] = fmaf(q4.x, k4[j].x, s[i][j]);
                    s[i][j] = fmaf(q4.y, k4[j].y, s[i][j]);
                    s[i][j] = fmaf(q4.z, k4[j].z, s[i][j]);
                    s[i][j] = fmaf(q4.w, k4[j].w, s[i][j]);
                }
            }
        }

        // Online softmax update (row reductions over the 16-lane tx group)
        #pragma unroll
        for (int i = 0; i < 4; i++) {
            float tm = fmaxf(fmaxf(s[i][0], s[i][1]), fmaxf(s[i][2], s[i][3]));
            tm = fmaxf(tm, __shfl_xor_sync(0xffffffffu, tm, 1));
            tm = fmaxf(tm, __shfl_xor_sync(0xffffffffu, tm, 2));
            tm = fmaxf(tm, __shfl_xor_sync(0xffffffffu, tm, 4));
            tm = fmaxf(tm, __shfl_xor_sync(0xffffffffu, tm, 8));
            float nm    = fmaxf(rm[i], tm);
            float alpha = __expf(rm[i] - nm);
            rm[i] = nm;
            float p0 = __expf(s[i][0] - nm);
            float p1 = __expf(s[i][1] - nm);
            float p2 = __expf(s[i][2] - nm);
            float p3 = __expf(s[i][3] - nm);
            float rs = p0 + p1 + p2 + p3;
            rs += __shfl_xor_sync(0xffffffffu, rs, 1);
            rs += __shfl_xor_sync(0xffffffffu, rs, 2);
            rs += __shfl_xor_sync(0xffffffffu, rs, 4);
            rs += __shfl_xor_sync(0xffffffffu, rs, 8);
            rl[i] = rl[i] * alpha + rs;
            #pragma unroll
            for (int j = 0; j < 4; j++) o[i][j] *= alpha;
            *(float4*)&Ps[(ty << 2) + i][tx << 2] = make_float4(p0, p1, p2, p3);
        }
        __syncthreads();

        // O += P V
        #pragma unroll 4
        for (int k = 0; k < 64; k += 4) {
            float4 vv[4];
            #pragma unroll
            for (int kk = 0; kk < 4; kk++) vv[kk] = *(const float4*)&Vs[k + kk][tx << 2];
            float vf[4][4] = {
                {vv[0].x, vv[0].y, vv[0].z, vv[0].w},
                {vv[1].x, vv[1].y, vv[1].z, vv[1].w},
                {vv[2].x, vv[2].y, vv[2].z, vv[2].w},
                {vv[3].x, vv[3].y, vv[3].z, vv[3].w}};
            #pragma unroll
            for (int i = 0; i < 4; i++) {
                float4 pp = *(const float4*)&Ps[(ty << 2) + i][k];
                float pe[4] = {pp.x, pp.y, pp.z, pp.w};
                #pragma unroll
                for (int j = 0; j < 4; j++) {
                    float acc = o[i][j];
                    #pragma unroll
                    for (int kk = 0; kk < 4; kk++) acc = fmaf(pe[kk], vf[kk][j], acc);
                    o[i][j] = acc;
                }
            }
        }
        __syncthreads();
    }

    // Normalize and write z in [B,N,C] layout
    const int b = bh >> 4, h = bh & 15;
    #pragma unroll
    for (int i = 0; i < 4; i++) {
        float inv = 1.0f / rl[i];
        int t = qblk * 64 + (ty << 2) + i;
        float4 ov = make_float4(o[i][0] * inv, o[i][1] * inv, o[i][2] * inv, o[i][3] * inv);
        *(float4*)&g_z[((size_t)b * NTOK + t) * DMODEL + h * DHEAD + (tx << 2)] = ov;
    }
}

// ---------------------------------------------------------------------------
extern "C" void kernel_launch(void* const* d_in, const int* in_sizes, int n_in,
                              void* d_out, int out_size)
{
    const float* x      = (const float*)d_in[0];
    const float* qkv_w  = (const float*)d_in[1];
    const float* qkv_b  = (const float*)d_in[2];
    const float* proj_w = (const float*)d_in[3];
    const float* proj_b = (const float*)d_in[4];
    float* out = (float*)d_out;

    const int M = B_SZ * NTOK;  // 8192

    // Attention kernel needs 69632 B dynamic smem (> 48KB default)
    cudaFuncSetAttribute(attn_kernel, cudaFuncAttributeMaxDynamicSharedMemorySize, 69632);

    dim3 blk(256);

    // 1) QKV GEMM + scatter to q/k/v (q pre-scaled)
    gemm_kernel<0><<<dim3(3 * DMODEL / 64, M / 64), blk>>>(x, qkv_w, qkv_b, nullptr,
                                                           M, 3 * DMODEL, DMODEL);

    // 2) Attention
    attn_kernel<<<dim3(B_SZ * NHEAD, NTOK / 64), blk, 69632>>>();

    // 3) Output projection
    gemm_kernel<1><<<dim3(DMODEL / 64, M / 64), blk>>>(nullptr, proj_w, proj_b, out,
                                                       M, DMODEL, DMODEL);
}

// round 2
// speedup vs baseline: 3.0704x; 3.0704x over previous
#include <cuda_runtime.h>
#include <cuda_bf16.h>
#include <math.h>
#include <stdint.h>
#include <stddef.h>

#define B_SZ   8
#define NTOK   1024
#define NHEAD  16
#define DHEAD  64
#define DMODEL 1024
#define SCALE  0.125f

// fp32 scratch (device globals: allocation-free per harness rules)
__device__ float g_q[(size_t)B_SZ * NHEAD * NTOK * DHEAD];
__device__ float g_k[(size_t)B_SZ * NHEAD * NTOK * DHEAD];
__device__ float g_v[(size_t)B_SZ * NHEAD * NTOK * DHEAD];
__device__ float g_z[(size_t)B_SZ * NTOK * DMODEL];

// ---------------------------------------------------------------------------
// helpers
// ---------------------------------------------------------------------------
__device__ __forceinline__ uint32_t smem_u32(const void* p) {
    return (uint32_t)__cvta_generic_to_shared(p);
}

__device__ __forceinline__ void ldsm4(uint32_t& r0, uint32_t& r1, uint32_t& r2, uint32_t& r3,
                                      uint32_t a) {
    asm volatile("ldmatrix.sync.aligned.m8n8.x4.shared.b16 {%0,%1,%2,%3}, [%4];"
                 : "=r"(r0), "=r"(r1), "=r"(r2), "=r"(r3) : "r"(a));
}

__device__ __forceinline__ void ldsm4t(uint32_t& r0, uint32_t& r1, uint32_t& r2, uint32_t& r3,
                                       uint32_t a) {
    asm volatile("ldmatrix.sync.aligned.m8n8.x4.trans.shared.b16 {%0,%1,%2,%3}, [%4];"
                 : "=r"(r0), "=r"(r1), "=r"(r2), "=r"(r3) : "r"(a));
}

__device__ __forceinline__ void mma16816(float* c,
                                         uint32_t a0, uint32_t a1, uint32_t a2, uint32_t a3,
                                         uint32_t b0, uint32_t b1) {
    asm volatile(
        "mma.sync.aligned.m16n8k16.row.col.f32.bf16.bf16.f32 "
        "{%0,%1,%2,%3},{%4,%5,%6,%7},{%8,%9},{%0,%1,%2,%3};"
        : "+f"(c[0]), "+f"(c[1]), "+f"(c[2]), "+f"(c[3])
        : "r"(a0), "r"(a1), "r"(a2), "r"(a3), "r"(b0), "r"(b1));
}

__device__ __forceinline__ uint32_t bpack(float a, float b) {
    __nv_bfloat162 h = __float22bfloat162_rn(make_float2(a, b));
    return *reinterpret_cast<uint32_t*>(&h);
}

// split two floats into hi/lo bf16x2 register pairs
__device__ __forceinline__ void splitpack(float a, float b, uint32_t& hi, uint32_t& lo) {
    __nv_bfloat162 h = __float22bfloat162_rn(make_float2(a, b));
    float ra = a - __bfloat162float(h.x);
    float rb = b - __bfloat162float(h.y);
    __nv_bfloat162 l = __float22bfloat162_rn(make_float2(ra, rb));
    hi = *reinterpret_cast<uint32_t*>(&h);
    lo = *reinterpret_cast<uint32_t*>(&l);
}

// split 4 consecutive floats into hi/lo bf16 smem arrays
__device__ __forceinline__ void split4(float4 v, __nv_bfloat16* hp, __nv_bfloat16* lp) {
    __nv_bfloat162 h01 = __float22bfloat162_rn(make_float2(v.x, v.y));
    __nv_bfloat162 h23 = __float22bfloat162_rn(make_float2(v.z, v.w));
    __nv_bfloat162 l01 = __float22bfloat162_rn(make_float2(v.x - __bfloat162float(h01.x),
                                                           v.y - __bfloat162float(h01.y)));
    __nv_bfloat162 l23 = __float22bfloat162_rn(make_float2(v.z - __bfloat162float(h23.x),
                                                           v.w - __bfloat162float(h23.y)));
    *reinterpret_cast<__nv_bfloat162*>(hp)     = h01;
    *reinterpret_cast<__nv_bfloat162*>(hp + 2) = h23;
    *reinterpret_cast<__nv_bfloat162*>(lp)     = l01;
    *reinterpret_cast<__nv_bfloat162*>(lp + 2) = l23;
}

__device__ __forceinline__ float redmax4(float v) {
    v = fmaxf(v, __shfl_xor_sync(0xffffffffu, v, 1));
    v = fmaxf(v, __shfl_xor_sync(0xffffffffu, v, 2));
    return v;
}
__device__ __forceinline__ float redsum4(float v) {
    v += __shfl_xor_sync(0xffffffffu, v, 1);
    v += __shfl_xor_sync(0xffffffffu, v, 2);
    return v;
}

// ---------------------------------------------------------------------------
// bf16x3 tensor-core GEMM: C[m,n] = sum_k A[m,k]*W[n,k] + bias[n]
// CTA 128x128, BK=32, 256 threads (8 warps as 2x4, warp tile 64x32).
// EPI==0: A = x, scatter to g_q/g_k/g_v (q pre-scaled).  EPI==1: A = g_z -> out.
// ---------------------------------------------------------------------------
template <int EPI>
__global__ __launch_bounds__(256) void mma_gemm(const float* __restrict__ A,
                                                const float* __restrict__ W,
                                                const float* __restrict__ bias,
                                                float* __restrict__ out,
                                                int M, int N, int K)
{
    // k-stride padded 32 -> 40 (80B row stride: conflict-free for ldmatrix)
    __shared__ __align__(16) __nv_bfloat16 sAh[128 * 40];
    __shared__ __align__(16) __nv_bfloat16 sAl[128 * 40];
    __shared__ __align__(16) __nv_bfloat16 sWh[128 * 40];
    __shared__ __align__(16) __nv_bfloat16 sWl[128 * 40];

    const float* Ap = (EPI == 1) ? g_z : A;

    const int tid  = threadIdx.x;
    const int lane = tid & 31;
    const int warp = tid >> 5;
    const int wm   = warp >> 2;   // 0..1
    const int wn   = warp & 3;    // 0..3
    const int row0 = blockIdx.y * 128;
    const int col0 = blockIdx.x * 128;

    const int lr = tid >> 1;            // 0..127
    const int lc = (tid & 1) * 16;      // 0 / 16

    float acc[4][4][4] = {};

    // per-lane ldmatrix address components
    const int a_row  = wm * 64 + (lane & 15);
    const int a_koff = (lane >> 4) << 3;
    const int b_n    = wn * 32 + (lane & 7) + ((lane >> 4) << 3);
    const int b_koff = ((lane >> 3) & 1) << 3;

    for (int k0 = 0; k0 < K; k0 += 32) {
        #pragma unroll
        for (int i = 0; i < 4; i++) {
            int c = lc + i * 4;
            float4 a4 = *(const float4*)&Ap[(size_t)(row0 + lr) * K + k0 + c];
            float4 w4 = *(const float4*)&W [(size_t)(col0 + lr) * K + k0 + c];
            split4(a4, &sAh[lr * 40 + c], &sAl[lr * 40 + c]);
            split4(w4, &sWh[lr * 40 + c], &sWl[lr * 40 + c]);
        }
        __syncthreads();

        #pragma unroll
        for (int ks = 0; ks < 32; ks += 16) {
            uint32_t ah[4][4], al[4][4];
            #pragma unroll
            for (int mt = 0; mt < 4; mt++) {
                int off = (a_row + mt * 16) * 40 + ks + a_koff;
                ldsm4(ah[mt][0], ah[mt][1], ah[mt][2], ah[mt][3], smem_u32(&sAh[off]));
                ldsm4(al[mt][0], al[mt][1], al[mt][2], al[mt][3], smem_u32(&sAl[off]));
            }
            uint32_t bh[4][2], bl[4][2];
            #pragma unroll
            for (int p = 0; p < 2; p++) {
                int off = (b_n + p * 16) * 40 + ks + b_koff;
                uint32_t r0, r1, r2, r3;
                ldsm4(r0, r1, r2, r3, smem_u32(&sWh[off]));
                bh[2 * p][0] = r0; bh[2 * p][1] = r1;
                bh[2 * p + 1][0] = r2; bh[2 * p + 1][1] = r3;
                ldsm4(r0, r1, r2, r3, smem_u32(&sWl[off]));
                bl[2 * p][0] = r0; bl[2 * p][1] = r1;
                bl[2 * p + 1][0] = r2; bl[2 * p + 1][1] = r3;
            }
            #pragma unroll
            for (int mt = 0; mt < 4; mt++) {
                #pragma unroll
                for (int nt = 0; nt < 4; nt++) {
                    mma16816(acc[mt][nt], ah[mt][0], ah[mt][1], ah[mt][2], ah[mt][3],
                             bh[nt][0], bh[nt][1]);
                    mma16816(acc[mt][nt], ah[mt][0], ah[mt][1], ah[mt][2], ah[mt][3],
                             bl[nt][0], bl[nt][1]);
                    mma16816(acc[mt][nt], al[mt][0], al[mt][1], al[mt][2], al[mt][3],
                             bh[nt][0], bh[nt][1]);
                }
            }
        }
        __syncthreads();
    }

    // epilogue
    const int r  = lane >> 2;
    const int cq = (lane & 3) * 2;
    #pragma unroll
    for (int mt = 0; mt < 4; mt++) {
        int m0 = row0 + wm * 64 + mt * 16 + r;
        #pragma unroll
        for (int nt = 0; nt < 4; nt++) {
            int n = col0 + wn * 32 + nt * 8 + cq;
            float b0 = bias[n], b1 = bias[n + 1];
            float v00 = acc[mt][nt][0] + b0, v01 = acc[mt][nt][1] + b1;
            float v10 = acc[mt][nt][2] + b0, v11 = acc[mt][nt][3] + b1;
            if (EPI == 0) {
                #pragma unroll
                for (int e = 0; e < 4; e++) {
                    int m = m0 + (e >> 1) * 8;
                    int c = n + (e & 1);
                    float val = (e == 0) ? v00 : (e == 1) ? v01 : (e == 2) ? v10 : v11;
                    int b    = m >> 10, t = m & 1023;
                    int part = c >> 10, hc = c & 1023;
                    size_t idx = (((size_t)(b * NHEAD) + (hc >> 6)) * NTOK + t) * DHEAD + (hc & 63);
                    if (part == 0)      g_q[idx] = val * SCALE;
                    else if (part == 1) g_k[idx] = val;
                    else                g_v[idx] = val;
                }
            } else {
                *(float2*)&out[(size_t)m0 * N + n]       = make_float2(v00, v01);
                *(float2*)&out[(size_t)(m0 + 8) * N + n] = make_float2(v10, v11);
            }
        }
    }
}

// ---------------------------------------------------------------------------
// bf16x3 tensor-core flash attention.
// CTA = (qblock of 128 rows, bh). 8 warps x 16 query rows each.
// K/V streamed in 128-key tiles, split fp32 -> bf16 hi/lo in smem.
// Softmax fully warp-local; P fragments built from S accumulator registers.
// Dynamic smem: 6 * 128*72 bf16 = 110592 B.
// ---------------------------------------------------------------------------
__global__ __launch_bounds__(256) void mma_attn()
{
    extern __shared__ __align__(16) __nv_bfloat16 smbuf[];
    __nv_bfloat16* sQh = smbuf;
    __nv_bfloat16* sQl = smbuf + 9216;
    __nv_bfloat16* sKh = smbuf + 18432;
    __nv_bfloat16* sKl = smbuf + 27648;
    __nv_bfloat16* sVh = smbuf + 36864;
    __nv_bfloat16* sVl = smbuf + 46080;

    const int qb = blockIdx.x;      // 0..7
    const int bh = blockIdx.y;      // 0..127

    const float* Qg = g_q + ((size_t)bh * NTOK + qb * 128) * DHEAD;
    const float* Kg = g_k + (size_t)bh * NTOK * DHEAD;
    const float* Vg = g_v + (size_t)bh * NTOK * DHEAD;

    const int tid  = threadIdx.x;
    const int lane = tid & 31;
    const int w    = tid >> 5;      // 0..7

    const int lr = tid >> 1;        // 0..127
    const int lc = (tid & 1) * 32;  // 0 / 32

    // ---- load Q tile once, split to smem ----
    #pragma unroll
    for (int i = 0; i < 8; i++) {
        int c = lc + i * 4;
        float4 q4 = *(const float4*)&Qg[lr * DHEAD + c];
        split4(q4, &sQh[lr * 72 + c], &sQl[lr * 72 + c]);
    }
    __syncthreads();

    // ---- preload Q fragments (A-frags) into registers ----
    uint32_t qh[4][4], ql[4][4];
    {
        int qrow = w * 16 + (lane & 15);
        int qoff = (lane >> 4) << 3;
        #pragma unroll
        for (int kk = 0; kk < 4; kk++) {
            int off = qrow * 72 + kk * 16 + qoff;
            ldsm4(qh[kk][0], qh[kk][1], qh[kk][2], qh[kk][3], smem_u32(&sQh[off]));
            ldsm4(ql[kk][0], ql[kk][1], ql[kk][2], ql[kk][3], smem_u32(&sQl[off]));
        }
    }

    // K B-frag (non-trans) lane address components
    const int k_nloc = (lane & 7) + ((lane >> 4) << 3);
    const int k_koff = ((lane >> 3) & 1) << 3;
    const uint32_t bKh = smem_u32(sKh) + (uint32_t)(k_nloc * 72 + k_koff) * 2;
    const uint32_t bKl = smem_u32(sKl) + (uint32_t)(k_nloc * 72 + k_koff) * 2;
    // V B-frag (trans) lane address components
    const int v_krl = (lane & 7) + (((lane >> 3) & 1) << 3);
    const int v_dc  = (lane >> 4) << 3;
    const uint32_t bVh = smem_u32(sVh) + (uint32_t)(v_krl * 72 + v_dc) * 2;
    const uint32_t bVl = smem_u32(sVl) + (uint32_t)(v_krl * 72 + v_dc) * 2;

    float O[8][4] = {};
    float rm0 = -INFINITY, rm1 = -INFINITY, rl0 = 0.f, rl1 = 0.f;

    for (int kb = 0; kb < 8; kb++) {
        __syncthreads();   // protect smem reuse from previous iteration
        #pragma unroll
        for (int i = 0; i < 8; i++) {
            int c = lc + i * 4;
            float4 k4 = *(const float4*)&Kg[(kb * 128 + lr) * DHEAD + c];
            float4 v4 = *(const float4*)&Vg[(kb * 128 + lr) * DHEAD + c];
            split4(k4, &sKh[lr * 72 + c], &sKl[lr * 72 + c]);
            split4(v4, &sVh[lr * 72 + c], &sVl[lr * 72 + c]);
        }
        __syncthreads();

        // ---- S = Q K^T (bf16x3) ----
        float s[16][4] = {};
        #pragma unroll
        for (int p = 0; p < 8; p++) {
            #pragma unroll
            for (int kk = 0; kk < 4; kk++) {
                uint32_t off = (uint32_t)(p * 16 * 72 + kk * 16) * 2;
                uint32_t r0, r1, r2, r3, t0, t1, t2, t3;
                ldsm4(r0, r1, r2, r3, bKh + off);
                ldsm4(t0, t1, t2, t3, bKl + off);
                mma16816(s[2 * p],     qh[kk][0], qh[kk][1], qh[kk][2], qh[kk][3], r0, r1);
                mma16816(s[2 * p],     qh[kk][0], qh[kk][1], qh[kk][2], qh[kk][3], t0, t1);
                mma16816(s[2 * p],     ql[kk][0], ql[kk][1], ql[kk][2], ql[kk][3], r0, r1);
                mma16816(s[2 * p + 1], qh[kk][0], qh[kk][1], qh[kk][2], qh[kk][3], r2, r3);
                mma16816(s[2 * p + 1], qh[kk][0], qh[kk][1], qh[kk][2], qh[kk][3], t2, t3);
                mma16816(s[2 * p + 1], ql[kk][0], ql[kk][1], ql[kk][2], ql[kk][3], r2, r3);
            }
        }

        // ---- online softmax (rows r = lane/4 and r+8, warp-local) ----
        float mx0 = -INFINITY, mx1 = -INFINITY;
        #pragma unroll
        for (int j = 0; j < 16; j++) {
            mx0 = fmaxf(mx0, fmaxf(s[j][0], s[j][1]));
            mx1 = fmaxf(mx1, fmaxf(s[j][2], s[j][3]));
        }
        mx0 = redmax4(mx0); mx1 = redmax4(mx1);
        float nm0 = fmaxf(rm0, mx0), nm1 = fmaxf(rm1, mx1);
        float al0 = __expf(rm0 - nm0), al1 = __expf(rm1 - nm1);
        rm0 = nm0; rm1 = nm1;
        float sm0 = 0.f, sm1 = 0.f;
        #pragma unroll
        for (int j = 0; j < 16; j++) {
            s[j][0] = __expf(s[j][0] - nm0);
            s[j][1] = __expf(s[j][1] - nm0);
            s[j][2] = __expf(s[j][2] - nm1);
            s[j][3] = __expf(s[j][3] - nm1);
            sm0 += s[j][0] + s[j][1];
            sm1 += s[j][2] + s[j][3];
        }
        sm0 = redsum4(sm0); sm1 = redsum4(sm1);
        rl0 = rl0 * al0 + sm0;
        rl1 = rl1 * al1 + sm1;
        #pragma unroll
        for (int nt = 0; nt < 8; nt++) {
            O[nt][0] *= al0; O[nt][1] *= al0;
            O[nt][2] *= al1; O[nt][3] *= al1;
        }

        // ---- O += P V (bf16x3), P frags straight from S registers ----
        #pragma unroll
        for (int kk = 0; kk < 8; kk++) {
            uint32_t ph[4], pl[4];
            splitpack(s[2 * kk][0],     s[2 * kk][1],     ph[0], pl[0]);
            splitpack(s[2 * kk][2],     s[2 * kk][3],     ph[1], pl[1]);
            splitpack(s[2 * kk + 1][0], s[2 * kk + 1][1], ph[2], pl[2]);
            splitpack(s[2 * kk + 1][2], s[2 * kk + 1][3], ph[3], pl[3]);
            #pragma unroll
            for (int pd = 0; pd < 4; pd++) {
                uint32_t off = (uint32_t)(kk * 16 * 72 + pd * 16) * 2;
                uint32_t v0, v1, v2, v3, u0, u1, u2, u3;
                ldsm4t(v0, v1, v2, v3, bVh + off);
                ldsm4t(u0, u1, u2, u3, bVl + off);
                mma16816(O[2 * pd],     ph[0], ph[1], ph[2], ph[3], v0, v1);
                mma16816(O[2 * pd],     ph[0], ph[1], ph[2], ph[3], u0, u1);
                mma16816(O[2 * pd],     pl[0], pl[1], pl[2], pl[3], v0, v1);
                mma16816(O[2 * pd + 1], ph[0], ph[1], ph[2], ph[3], v2, v3);
                mma16816(O[2 * pd + 1], ph[0], ph[1], ph[2], ph[3], u2, u3);
                mma16816(O[2 * pd + 1], pl[0], pl[1], pl[2], pl[3], v2, v3);
            }
        }
    }

    // ---- normalize, write z [B,N,C] ----
    float inv0 = 1.0f / rl0, inv1 = 1.0f / rl1;
    const int b = bh >> 4, h = bh & 15;
    const int t0 = qb * 128 + w * 16 + (lane >> 2);
    const int cq = (lane & 3) * 2;
    #pragma unroll
    for (int nt = 0; nt < 8; nt++) {
        int d = h * 64 + nt * 8 + cq;
        *(float2*)&g_z[((size_t)b * NTOK + t0) * DMODEL + d] =
            make_float2(O[nt][0] * inv0, O[nt][1] * inv0);
        *(float2*)&g_z[((size_t)b * NTOK + t0 + 8) * DMODEL + d] =
            make_float2(O[nt][2] * inv1, O[nt][3] * inv1);
    }
}

// ---------------------------------------------------------------------------
extern "C" void kernel_launch(void* const* d_in, const int* in_sizes, int n_in,
                              void* d_out, int out_size)
{
    const float* x      = (const float*)d_in[0];
    const float* qkv_w  = (const float*)d_in[1];
    const float* qkv_b  = (const float*)d_in[2];
    const float* proj_w = (const float*)d_in[3];
    const float* proj_b = (const float*)d_in[4];
    float* out = (float*)d_out;

    const int M = B_SZ * NTOK;  // 8192

    cudaFuncSetAttribute(mma_attn, cudaFuncAttributeMaxDynamicSharedMemorySize, 110592);

    dim3 blk(256);

    // 1) QKV GEMM (bf16x3 tensor cores) + scatter
    mma_gemm<0><<<dim3(3 * DMODEL / 128, M / 128), blk>>>(x, qkv_w, qkv_b, nullptr,
                                                          M, 3 * DMODEL, DMODEL);

    // 2) Flash attention (bf16x3 tensor cores)
    mma_attn<<<dim3(NTOK / 128, B_SZ * NHEAD), blk, 110592>>>();

    // 3) Output projection (bf16x3 tensor cores)
    mma_gemm<1><<<dim3(DMODEL / 128, M / 128), blk>>>(nullptr, proj_w, proj_b, out,
                                                      M, DMODEL, DMODEL);
}

// round 4
// speedup vs baseline: 3.6448x; 1.1871x over previous
#include <cuda_runtime.h>
#include <cuda_bf16.h>
#include <math.h>
#include <stdint.h>
#include <stddef.h>

#define B_SZ   8
#define NTOK   1024
#define NHEAD  16
#define DHEAD  64
#define DMODEL 1024
#define SCALE  0.125f

// ---------------------------------------------------------------------------
// Persistent bf16 hi/lo scratch (device globals: allocation-free)
// ---------------------------------------------------------------------------
#define MK ((size_t)B_SZ * NTOK * DMODEL)        // 8388608
#define QKV_W_N ((size_t)3 * DMODEL * DMODEL)    // 3145728
#define PROJ_W_N ((size_t)DMODEL * DMODEL)       // 1048576
#define HSZ ((size_t)B_SZ * NHEAD * NTOK * DHEAD)

__device__ __nv_bfloat16 g_xh[MK],  g_xl[MK];
__device__ __nv_bfloat16 g_qwh[QKV_W_N], g_qwl[QKV_W_N];
__device__ __nv_bfloat16 g_pwh[PROJ_W_N], g_pwl[PROJ_W_N];
__device__ __nv_bfloat16 g_qh[HSZ], g_ql[HSZ];
__device__ __nv_bfloat16 g_kh[HSZ], g_kl[HSZ];
__device__ __nv_bfloat16 g_vh[HSZ], g_vl[HSZ];
__device__ __nv_bfloat16 g_zh[MK],  g_zl[MK];

// ---------------------------------------------------------------------------
// helpers
// ---------------------------------------------------------------------------
__device__ __forceinline__ uint32_t smem_u32(const void* p) {
    return (uint32_t)__cvta_generic_to_shared(p);
}
__device__ __forceinline__ void cpa16(uint32_t dst, const void* src) {
    asm volatile("cp.async.cg.shared.global [%0], [%1], 16;" :: "r"(dst), "l"(src));
}
__device__ __forceinline__ void cp_commit() {
    asm volatile("cp.async.commit_group;");
}
template <int N>
__device__ __forceinline__ void cp_wait() {
    asm volatile("cp.async.wait_group %0;" :: "n"(N));
}
__device__ __forceinline__ void ldsm4(uint32_t& r0, uint32_t& r1, uint32_t& r2, uint32_t& r3,
                                      uint32_t a) {
    asm volatile("ldmatrix.sync.aligned.m8n8.x4.shared.b16 {%0,%1,%2,%3}, [%4];"
                 : "=r"(r0), "=r"(r1), "=r"(r2), "=r"(r3) : "r"(a));
}
__device__ __forceinline__ void ldsm4t(uint32_t& r0, uint32_t& r1, uint32_t& r2, uint32_t& r3,
                                       uint32_t a) {
    asm volatile("ldmatrix.sync.aligned.m8n8.x4.trans.shared.b16 {%0,%1,%2,%3}, [%4];"
                 : "=r"(r0), "=r"(r1), "=r"(r2), "=r"(r3) : "r"(a));
}
__device__ __forceinline__ void mma16816(float* c,
                                         uint32_t a0, uint32_t a1, uint32_t a2, uint32_t a3,
                                         uint32_t b0, uint32_t b1) {
    asm volatile(
        "mma.sync.aligned.m16n8k16.row.col.f32.bf16.bf16.f32 "
        "{%0,%1,%2,%3},{%4,%5,%6,%7},{%8,%9},{%0,%1,%2,%3};"
        : "+f"(c[0]), "+f"(c[1]), "+f"(c[2]), "+f"(c[3])
        : "r"(a0), "r"(a1), "r"(a2), "r"(a3), "r"(b0), "r"(b1));
}
__device__ __forceinline__ void splitpack(float a, float b, uint32_t& hi, uint32_t& lo) {
    __nv_bfloat162 h = __float22bfloat162_rn(make_float2(a, b));
    float ra = a - __bfloat162float(h.x);
    float rb = b - __bfloat162float(h.y);
    __nv_bfloat162 l = __float22bfloat162_rn(make_float2(ra, rb));
    hi = *reinterpret_cast<uint32_t*>(&h);
    lo = *reinterpret_cast<uint32_t*>(&l);
}
__device__ __forceinline__ void split4(float4 v, __nv_bfloat16* hp, __nv_bfloat16* lp) {
    __nv_bfloat162 h01 = __float22bfloat162_rn(make_float2(v.x, v.y));
    __nv_bfloat162 h23 = __float22bfloat162_rn(make_float2(v.z, v.w));
    __nv_bfloat162 l01 = __float22bfloat162_rn(make_float2(v.x - __bfloat162float(h01.x),
                                                           v.y - __bfloat162float(h01.y)));
    __nv_bfloat162 l23 = __float22bfloat162_rn(make_float2(v.z - __bfloat162float(h23.x),
                                                           v.w - __bfloat162float(h23.y)));
    *reinterpret_cast<__nv_bfloat162*>(hp)     = h01;
    *reinterpret_cast<__nv_bfloat162*>(hp + 2) = h23;
    *reinterpret_cast<__nv_bfloat162*>(lp)     = l01;
    *reinterpret_cast<__nv_bfloat162*>(lp + 2) = l23;
}
__device__ __forceinline__ float redmax4(float v) {
    v = fmaxf(v, __shfl_xor_sync(0xffffffffu, v, 1));
    v = fmaxf(v, __shfl_xor_sync(0xffffffffu, v, 2));
    return v;
}
__device__ __forceinline__ float redsum4(float v) {
    v += __shfl_xor_sync(0xffffffffu, v, 1);
    v += __shfl_xor_sync(0xffffffffu, v, 2);
    return v;
}

// ---------------------------------------------------------------------------
// one-time fp32 -> bf16 hi/lo split
// ---------------------------------------------------------------------------
__global__ __launch_bounds__(256) void split_kernel(const float* __restrict__ src,
                                                    __nv_bfloat16* __restrict__ hi,
                                                    __nv_bfloat16* __restrict__ lo,
                                                    int n4)
{
    int i = blockIdx.x * blockDim.x + threadIdx.x;
    if (i < n4) {
        float4 v = reinterpret_cast<const float4*>(src)[i];
        split4(v, hi + 4 * (size_t)i, lo + 4 * (size_t)i);
    }
}

// ---------------------------------------------------------------------------
// Pipelined bf16x3 GEMM: C[m,n] = sum_k A[m,k]*W[n,k] + bias[n]
// CTA 128x128, BK=32, 256 threads, 2-stage cp.async double buffer.
// Stage layout (bf16 elems): Ah[128*40] | Al | Wh | Wl  (20480 elems = 40960 B)
// EPI==0: scatter to q/k/v bf16 hi/lo (q pre-scaled). EPI==1: out fp32.
// ---------------------------------------------------------------------------
template <int EPI>
__global__ __launch_bounds__(256, 2) void mma_gemm(const __nv_bfloat16* __restrict__ Ah,
                                                   const __nv_bfloat16* __restrict__ Al,
                                                   const __nv_bfloat16* __restrict__ Wh,
                                                   const __nv_bfloat16* __restrict__ Wl,
                                                   const float* __restrict__ bias,
                                                   float* __restrict__ out,
                                                   int M, int N, int K)
{
    extern __shared__ __align__(16) __nv_bfloat16 sm[];

    const int tid  = threadIdx.x;
    const int lane = tid & 31;
    const int warp = tid >> 5;
    const int wm   = warp >> 2;
    const int wn   = warp & 3;
    const int row0 = blockIdx.y * 128;
    const int col0 = blockIdx.x * 128;

    const uint32_t smb = smem_u32(sm);

    const int ch0_row = tid >> 2;
    const int ch0_c   = (tid & 3) * 8;

    auto load_stage = [&](int s, int k0) {
        uint32_t base = smb + s * 40960u;
        #pragma unroll
        for (int i = 0; i < 2; i++) {
            int row = ch0_row + i * 64;
            int c   = ch0_c;
            size_t ga = (size_t)(row0 + row) * K + k0 + c;
            size_t gw = (size_t)(col0 + row) * K + k0 + c;
            uint32_t d = base + (uint32_t)(row * 40 + c) * 2;
            cpa16(d,          Ah + ga);
            cpa16(d + 10240u, Al + ga);
            cpa16(d + 20480u, Wh + gw);
            cpa16(d + 30720u, Wl + gw);
        }
    };

    float acc[4][4][4] = {};

    const int a_row  = wm * 64 + (lane & 15);
    const int a_koff = (lane >> 4) << 3;
    const int b_n    = wn * 32 + (lane & 7) + ((lane >> 4) << 3);
    const int b_koff = ((lane >> 3) & 1) << 3;

    const int NK = K / 32;
    load_stage(0, 0);
    cp_commit();

    for (int it = 0; it < NK; it++) {
        if (it + 1 < NK) {
            load_stage((it + 1) & 1, (it + 1) * 32);
            cp_commit();
            cp_wait<1>();
        } else {
            cp_wait<0>();
        }
        __syncthreads();

        uint32_t stb = smb + (uint32_t)(it & 1) * 40960u;
        #pragma unroll
        for (int ks = 0; ks < 32; ks += 16) {
            uint32_t ah[4][4], al[4][4];
            #pragma unroll
            for (int mt = 0; mt < 4; mt++) {
                uint32_t off = stb + (uint32_t)((a_row + mt * 16) * 40 + ks + a_koff) * 2;
                ldsm4(ah[mt][0], ah[mt][1], ah[mt][2], ah[mt][3], off);
                ldsm4(al[mt][0], al[mt][1], al[mt][2], al[mt][3], off + 10240u);
            }
            uint32_t bh[4][2], bl[4][2];
            #pragma unroll
            for (int p = 0; p < 2; p++) {
                uint32_t off = stb + 20480u + (uint32_t)((b_n + p * 16) * 40 + ks + b_koff) * 2;
                uint32_t r0, r1, r2, r3;
                ldsm4(r0, r1, r2, r3, off);
                bh[2 * p][0] = r0; bh[2 * p][1] = r1;
                bh[2 * p + 1][0] = r2; bh[2 * p + 1][1] = r3;
                ldsm4(r0, r1, r2, r3, off + 10240u);
                bl[2 * p][0] = r0; bl[2 * p][1] = r1;
                bl[2 * p + 1][0] = r2; bl[2 * p + 1][1] = r3;
            }
            #pragma unroll
            for (int mt = 0; mt < 4; mt++) {
                #pragma unroll
                for (int nt = 0; nt < 4; nt++) {
                    mma16816(acc[mt][nt], ah[mt][0], ah[mt][1], ah[mt][2], ah[mt][3],
                             bh[nt][0], bh[nt][1]);
                    mma16816(acc[mt][nt], ah[mt][0], ah[mt][1], ah[mt][2], ah[mt][3],
                             bl[nt][0], bl[nt][1]);
                    mma16816(acc[mt][nt], al[mt][0], al[mt][1], al[mt][2], al[mt][3],
                             bh[nt][0], bh[nt][1]);
                }
            }
        }
        __syncthreads();
    }

    // epilogue
    const int r  = lane >> 2;
    const int cq = (lane & 3) * 2;
    #pragma unroll
    for (int mt = 0; mt < 4; mt++) {
        int m0 = row0 + wm * 64 + mt * 16 + r;
        #pragma unroll
        for (int nt = 0; nt < 4; nt++) {
            int n = col0 + wn * 32 + nt * 8 + cq;
            float b0 = bias[n], b1 = bias[n + 1];
            float v00 = acc[mt][nt][0] + b0, v01 = acc[mt][nt][1] + b1;
            float v10 = acc[mt][nt][2] + b0, v11 = acc[mt][nt][3] + b1;
            if (EPI == 0) {
                #pragma unroll
                for (int e = 0; e < 4; e++) {
                    int m = m0 + (e >> 1) * 8;
                    int c = n + (e & 1);
                    float val = (e == 0) ? v00 : (e == 1) ? v01 : (e == 2) ? v10 : v11;
                    int b    = m >> 10, t = m & 1023;
                    int part = c >> 10, hc = c & 1023;
                    size_t idx = (((size_t)(b * NHEAD) + (hc >> 6)) * NTOK + t) * DHEAD + (hc & 63);
                    if (part == 0) val *= SCALE;
                    __nv_bfloat16 hi = __float2bfloat16_rn(val);
                    __nv_bfloat16 lo = __float2bfloat16_rn(val - __bfloat162float(hi));
                    if (part == 0)      { g_qh[idx] = hi; g_ql[idx] = lo; }
                    else if (part == 1) { g_kh[idx] = hi; g_kl[idx] = lo; }
                    else                { g_vh[idx] = hi; g_vl[idx] = lo; }
                }
            } else {
                *(float2*)&out[(size_t)m0 * N + n]       = make_float2(v00, v01);
                *(float2*)&out[(size_t)(m0 + 8) * N + n] = make_float2(v10, v11);
            }
        }
    }
}

// ---------------------------------------------------------------------------
// Pipelined bf16x3 flash attention.
// smem (bf16 elems): Qh[128*72] @0 | Ql @9216 | stages @18432+s*36864:
//   Kh | Kl(+9216) | Vh(+18432) | Vl(+27648).  Total 92160 elems = 184320 B.
// ---------------------------------------------------------------------------
__global__ __launch_bounds__(256) void mma_attn()
{
    extern __shared__ __align__(16) __nv_bfloat16 smbuf[];

    const int qb = blockIdx.x;      // 0..7
    const int bh = blockIdx.y;      // 0..127

    const __nv_bfloat16* Qh = g_qh + ((size_t)bh * NTOK + qb * 128) * DHEAD;
    const __nv_bfloat16* Ql = g_ql + ((size_t)bh * NTOK + qb * 128) * DHEAD;
    const __nv_bfloat16* Kh = g_kh + (size_t)bh * NTOK * DHEAD;
    const __nv_bfloat16* Kl = g_kl + (size_t)bh * NTOK * DHEAD;
    const __nv_bfloat16* Vh = g_vh + (size_t)bh * NTOK * DHEAD;
    const __nv_bfloat16* Vl = g_vl + (size_t)bh * NTOK * DHEAD;

    const int tid  = threadIdx.x;
    const int lane = tid & 31;
    const int w    = tid >> 5;

    const uint32_t smb = smem_u32(smbuf);

    // ---- Q load: 1024 16B-chunks per array, 4 per thread ----
    {
        #pragma unroll
        for (int i = 0; i < 4; i++) {
            int ch = tid + i * 256;
            int row = ch >> 3, c = (ch & 7) * 8;
            uint32_t d = smb + (uint32_t)(row * 72 + c) * 2;
            cpa16(d,          Qh + row * 64 + c);
            cpa16(d + 18432u, Ql + row * 64 + c);
        }
        cp_commit();
    }

    auto load_kv = [&](int s, int kb) {
        uint32_t base = smb + 36864u + (uint32_t)s * 73728u;
        #pragma unroll
        for (int i = 0; i < 4; i++) {
            int ch = tid + i * 256;
            int row = ch >> 3, c = (ch & 7) * 8;
            size_t g = (size_t)(kb * 128 + row) * 64 + c;
            uint32_t d = base + (uint32_t)(row * 72 + c) * 2;
            cpa16(d,          Kh + g);
            cpa16(d + 18432u, Kl + g);
            cpa16(d + 36864u, Vh + g);
            cpa16(d + 55296u, Vl + g);
        }
    };

    load_kv(0, 0);
    cp_commit();

    const int k_nloc = (lane & 7) + ((lane >> 4) << 3);
    const int k_koff = ((lane >> 3) & 1) << 3;
    const int v_krl  = (lane & 7) + (((lane >> 3) & 1) << 3);
    const int v_dc   = (lane >> 4) << 3;

    uint32_t qh[4][4], ql[4][4];
    float O[8][4] = {};
    float rm0 = -INFINITY, rm1 = -INFINITY, rl0 = 0.f, rl1 = 0.f;

    for (int kb = 0; kb < 8; kb++) {
        if (kb + 1 < 8) {
            load_kv((kb + 1) & 1, kb + 1);
            cp_commit();
            cp_wait<1>();
        } else {
            cp_wait<0>();
        }
        __syncthreads();

        if (kb == 0) {
            int qrow = w * 16 + (lane & 15);
            int qoff = (lane >> 4) << 3;
            #pragma unroll
            for (int kk = 0; kk < 4; kk++) {
                uint32_t off = smb + (uint32_t)(qrow * 72 + kk * 16 + qoff) * 2;
                ldsm4(qh[kk][0], qh[kk][1], qh[kk][2], qh[kk][3], off);
                ldsm4(ql[kk][0], ql[kk][1], ql[kk][2], ql[kk][3], off + 18432u);
            }
        }

        uint32_t stb = smb + 36864u + (uint32_t)(kb & 1) * 73728u;
        uint32_t bKh = stb + (uint32_t)(k_nloc * 72 + k_koff) * 2;
        uint32_t bVh = stb + 36864u + (uint32_t)(v_krl * 72 + v_dc) * 2;

        // ---- S = Q K^T ----
        float s[16][4] = {};
        #pragma unroll
        for (int p = 0; p < 8; p++) {
            #pragma unroll
            for (int kk = 0; kk < 4; kk++) {
                uint32_t off = (uint32_t)(p * 16 * 72 + kk * 16) * 2;
                uint32_t r0, r1, r2, r3, t0, t1, t2, t3;
                ldsm4(r0, r1, r2, r3, bKh + off);
                ldsm4(t0, t1, t2, t3, bKh + off + 18432u);
                mma16816(s[2 * p],     qh[kk][0], qh[kk][1], qh[kk][2], qh[kk][3], r0, r1);
                mma16816(s[2 * p],     qh[kk][0], qh[kk][1], qh[kk][2], qh[kk][3], t0, t1);
                mma16816(s[2 * p],     ql[kk][0], ql[kk][1], ql[kk][2], ql[kk][3], r0, r1);
                mma16816(s[2 * p + 1], qh[kk][0], qh[kk][1], qh[kk][2], qh[kk][3], r2, r3);
                mma16816(s[2 * p + 1], qh[kk][0], qh[kk][1], qh[kk][2], qh[kk][3], t2, t3);
                mma16816(s[2 * p + 1], ql[kk][0], ql[kk][1], ql[kk][2], ql[kk][3], r2, r3);
            }
        }

        // ---- online softmax (warp-local) ----
        float mx0 = -INFINITY, mx1 = -INFINITY;
        #pragma unroll
        for (int j = 0; j < 16; j++) {
            mx0 = fmaxf(mx0, fmaxf(s[j][0], s[j][1]));
            mx1 = fmaxf(mx1, fmaxf(s[j][2], s[j][3]));
        }
        mx0 = redmax4(mx0); mx1 = redmax4(mx1);
        float nm0 = fmaxf(rm0, mx0), nm1 = fmaxf(rm1, mx1);
        float al0 = __expf(rm0 - nm0), al1 = __expf(rm1 - nm1);
        rm0 = nm0; rm1 = nm1;
        float sm0 = 0.f, sm1 = 0.f;
        #pragma unroll
        for (int j = 0; j < 16; j++) {
            s[j][0] = __expf(s[j][0] - nm0);
            s[j][1] = __expf(s[j][1] - nm0);
            s[j][2] = __expf(s[j][2] - nm1);
            s[j][3] = __expf(s[j][3] - nm1);
            sm0 += s[j][0] + s[j][1];
            sm1 += s[j][2] + s[j][3];
        }
        sm0 = redsum4(sm0); sm1 = redsum4(sm1);
        rl0 = rl0 * al0 + sm0;
        rl1 = rl1 * al1 + sm1;
        #pragma unroll
        for (int nt = 0; nt < 8; nt++) {
            O[nt][0] *= al0; O[nt][1] *= al0;
            O[nt][2] *= al1; O[nt][3] *= al1;
        }

        // ---- O += P V ----
        #pragma unroll
        for (int kk = 0; kk < 8; kk++) {
            uint32_t ph[4], pl[4];
            splitpack(s[2 * kk][0],     s[2 * kk][1],     ph[0], pl[0]);
            splitpack(s[2 * kk][2],     s[2 * kk][3],     ph[1], pl[1]);
            splitpack(s[2 * kk + 1][0], s[2 * kk + 1][1], ph[2], pl[2]);
            splitpack(s[2 * kk + 1][2], s[2 * kk + 1][3], ph[3], pl[3]);
            #pragma unroll
            for (int pd = 0; pd < 4; pd++) {
                uint32_t off = (uint32_t)(kk * 16 * 72 + pd * 16) * 2;
                uint32_t v0, v1, v2, v3, u0, u1, u2, u3;
                ldsm4t(v0, v1, v2, v3, bVh + off);
                ldsm4t(u0, u1, u2, u3, bVh + off + 18432u);
                mma16816(O[2 * pd],     ph[0], ph[1], ph[2], ph[3], v0, v1);
                mma16816(O[2 * pd],     ph[0], ph[1], ph[2], ph[3], u0, u1);
                mma16816(O[2 * pd],     pl[0], pl[1], pl[2], pl[3], v0, v1);
                mma16816(O[2 * pd + 1], ph[0], ph[1], ph[2], ph[3], v2, v3);
                mma16816(O[2 * pd + 1], ph[0], ph[1], ph[2], ph[3], u2, u3);
                mma16816(O[2 * pd + 1], pl[0], pl[1], pl[2], pl[3], v2, v3);
            }
        }
        __syncthreads();
    }

    // ---- normalize, write z hi/lo bf16 [B,N,C] ----
    float inv0 = 1.0f / rl0, inv1 = 1.0f / rl1;
    const int b = bh >> 4, h = bh & 15;
    const int t0 = qb * 128 + w * 16 + (lane >> 2);
    const int cq = (lane & 3) * 2;
    #pragma unroll
    for (int nt = 0; nt < 8; nt++) {
        int d = h * 64 + nt * 8 + cq;
        size_t i0 = ((size_t)b * NTOK + t0) * DMODEL + d;
        size_t i1 = ((size_t)b * NTOK + t0 + 8) * DMODEL + d;
        uint32_t zh, zl;
        splitpack(O[nt][0] * inv0, O[nt][1] * inv0, zh, zl);
        *(uint32_t*)&g_zh[i0] = zh;
        *(uint32_t*)&g_zl[i0] = zl;
        splitpack(O[nt][2] * inv1, O[nt][3] * inv1, zh, zl);
        *(uint32_t*)&g_zh[i1] = zh;
        *(uint32_t*)&g_zl[i1] = zl;
    }
}

// ---------------------------------------------------------------------------
extern "C" void kernel_launch(void* const* d_in, const int* in_sizes, int n_in,
                              void* d_out, int out_size)
{
    const float* x      = (const float*)d_in[0];
    const float* qkv_w  = (const float*)d_in[1];
    const float* qkv_b  = (const float*)d_in[2];
    const float* proj_w = (const float*)d_in[3];
    const float* proj_b = (const float*)d_in[4];
    float* out = (float*)d_out;

    const int M = B_SZ * NTOK;  // 8192

    cudaFuncSetAttribute(mma_attn, cudaFuncAttributeMaxDynamicSharedMemorySize, 184320);
    cudaFuncSetAttribute(mma_gemm<0>, cudaFuncAttributeMaxDynamicSharedMemorySize, 81920);
    cudaFuncSetAttribute(mma_gemm<1>, cudaFuncAttributeMaxDynamicSharedMemorySize, 81920);

    __nv_bfloat16 *xh, *xl, *qwh, *qwl, *pwh, *pwl, *zh, *zl;
    cudaGetSymbolAddress((void**)&xh,  g_xh);
    cudaGetSymbolAddress((void**)&xl,  g_xl);
    cudaGetSymbolAddress((void**)&qwh, g_qwh);
    cudaGetSymbolAddress((void**)&qwl, g_qwl);
    cudaGetSymbolAddress((void**)&pwh, g_pwh);
    cudaGetSymbolAddress((void**)&pwl, g_pwl);
    cudaGetSymbolAddress((void**)&zh,  g_zh);
    cudaGetSymbolAddress((void**)&zl,  g_zl);

    dim3 blk(256);

    // 0) pre-split inputs/weights to bf16 hi/lo
    split_kernel<<<(int)(MK / 4 / 256), blk>>>(x, xh, xl, (int)(MK / 4));
    split_kernel<<<(int)(QKV_W_N / 4 / 256), blk>>>(qkv_w, qwh, qwl, (int)(QKV_W_N / 4));
    split_kernel<<<(int)(PROJ_W_N / 4 / 256), blk>>>(proj_w, pwh, pwl, (int)(PROJ_W_N / 4));

    // 1) QKV GEMM -> q/k/v bf16 hi/lo
    mma_gemm<0><<<dim3(3 * DMODEL / 128, M / 128), blk, 81920>>>(
        xh, xl, qwh, qwl, qkv_b, nullptr, M, 3 * DMODEL, DMODEL);

    // 2) Flash attention -> z bf16 hi/lo
    mma_attn<<<dim3(NTOK / 128, B_SZ * NHEAD), blk, 184320>>>();

    // 3) Output projection (A = z hi/lo) -> out fp32
    mma_gemm<1><<<dim3(DMODEL / 128, M / 128), blk, 81920>>>(
        zh, zl, pwh, pwl, proj_b, out, M, DMODEL, DMODEL);
}

// round 6
// speedup vs baseline: 4.1238x; 1.1314x over previous
#include <cuda_runtime.h>
#include <cuda_bf16.h>
#include <math.h>
#include <stdint.h>
#include <stddef.h>

#define B_SZ   8
#define NTOK   1024
#define NHEAD  16
#define DHEAD  64
#define DMODEL 1024
#define SCALE  0.125f

#define MK ((size_t)B_SZ * NTOK * DMODEL)
#define QKV_W_N ((size_t)3 * DMODEL * DMODEL)
#define PROJ_W_N ((size_t)DMODEL * DMODEL)
#define HSZ ((size_t)B_SZ * NHEAD * NTOK * DHEAD)

// All operand storage is pre-tiled into 128-row x 64-k SW128-swizzled 16KB
// blocks so every smem fill is a single cp.async.bulk.
__device__ __align__(1024) __nv_bfloat16 g_xh[MK],  g_xl[MK];
__device__ __align__(1024) __nv_bfloat16 g_qwh[QKV_W_N], g_qwl[QKV_W_N];
__device__ __align__(1024) __nv_bfloat16 g_pwh[PROJ_W_N], g_pwl[PROJ_W_N];
__device__ __align__(1024) __nv_bfloat16 g_zh[MK],  g_zl[MK];
// q/k/v: per (b,h) 8 chunks of 128 tokens x 64 d, swizzled within chunk
__device__ __align__(1024) __nv_bfloat16 g_qh[HSZ], g_ql[HSZ];
__device__ __align__(1024) __nv_bfloat16 g_kh[HSZ], g_kl[HSZ];
__device__ __align__(1024) __nv_bfloat16 g_vh[HSZ], g_vl[HSZ];

// ---------------------------------------------------------------------------
// helpers
// ---------------------------------------------------------------------------
__device__ __forceinline__ uint32_t smem_u32(const void* p) {
    return (uint32_t)__cvta_generic_to_shared(p);
}
__device__ __forceinline__ uint32_t swz128(uint32_t b) {   // Swizzle<3,4,3>
    return b ^ ((b >> 3) & 0x70);
}
__device__ __forceinline__ void bulkcp(uint32_t dst, const void* src, uint32_t bytes,
                                       uint32_t mbar) {
    asm volatile(
        "cp.async.bulk.shared::cta.global.mbarrier::complete_tx::bytes [%0], [%1], %2, [%3];"
        :: "r"(dst), "l"(src), "r"(bytes), "r"(mbar) : "memory");
}
__device__ __forceinline__ void mbar_init(uint32_t mbar, uint32_t cnt) {
    asm volatile("mbarrier.init.shared.b64 [%0], %1;" :: "r"(mbar), "r"(cnt) : "memory");
}
__device__ __forceinline__ void mbar_expect_tx(uint32_t mbar, uint32_t bytes) {
    asm volatile("mbarrier.arrive.expect_tx.shared.b64 _, [%0], %1;"
                 :: "r"(mbar), "r"(bytes) : "memory");
}
__device__ __forceinline__ void mbar_wait(uint32_t mbar, uint32_t phase) {
    asm volatile(
        "{\n\t.reg .pred P;\n\t"
        "W_%=:\n\t"
        "mbarrier.try_wait.parity.acquire.cta.shared::cta.b64 P, [%0], %1, 0x989680;\n\t"
        "@P bra D_%=;\n\t"
        "bra W_%=;\n\t"
        "D_%=:\n\t}"
        :: "r"(mbar), "r"(phase) : "memory");
}
__device__ __forceinline__ void ldsm4(uint32_t& r0, uint32_t& r1, uint32_t& r2, uint32_t& r3,
                                      uint32_t a) {
    asm volatile("ldmatrix.sync.aligned.m8n8.x4.shared.b16 {%0,%1,%2,%3}, [%4];"
                 : "=r"(r0), "=r"(r1), "=r"(r2), "=r"(r3) : "r"(a));
}
__device__ __forceinline__ void ldsm4t(uint32_t& r0, uint32_t& r1, uint32_t& r2, uint32_t& r3,
                                       uint32_t a) {
    asm volatile("ldmatrix.sync.aligned.m8n8.x4.trans.shared.b16 {%0,%1,%2,%3}, [%4];"
                 : "=r"(r0), "=r"(r1), "=r"(r2), "=r"(r3) : "r"(a));
}
__device__ __forceinline__ void mma16816(float* c,
                                         uint32_t a0, uint32_t a1, uint32_t a2, uint32_t a3,
                                         uint32_t b0, uint32_t b1) {
    asm volatile(
        "mma.sync.aligned.m16n8k16.row.col.f32.bf16.bf16.f32 "
        "{%0,%1,%2,%3},{%4,%5,%6,%7},{%8,%9},{%0,%1,%2,%3};"
        : "+f"(c[0]), "+f"(c[1]), "+f"(c[2]), "+f"(c[3])
        : "r"(a0), "r"(a1), "r"(a2), "r"(a3), "r"(b0), "r"(b1));
}
__device__ __forceinline__ void splitpack(float a, float b, uint32_t& hi, uint32_t& lo) {
    __nv_bfloat162 h = __float22bfloat162_rn(make_float2(a, b));
    float ra = a - __bfloat162float(h.x);
    float rb = b - __bfloat162float(h.y);
    __nv_bfloat162 l = __float22bfloat162_rn(make_float2(ra, rb));
    hi = *reinterpret_cast<uint32_t*>(&h);
    lo = *reinterpret_cast<uint32_t*>(&l);
}
__device__ __forceinline__ void split4(float4 v, __nv_bfloat16* hp, __nv_bfloat16* lp) {
    __nv_bfloat162 h01 = __float22bfloat162_rn(make_float2(v.x, v.y));
    __nv_bfloat162 h23 = __float22bfloat162_rn(make_float2(v.z, v.w));
    __nv_bfloat162 l01 = __float22bfloat162_rn(make_float2(v.x - __bfloat162float(h01.x),
                                                           v.y - __bfloat162float(h01.y)));
    __nv_bfloat162 l23 = __float22bfloat162_rn(make_float2(v.z - __bfloat162float(h23.x),
                                                           v.w - __bfloat162float(h23.y)));
    *reinterpret_cast<__nv_bfloat162*>(hp)     = h01;
    *reinterpret_cast<__nv_bfloat162*>(hp + 2) = h23;
    *reinterpret_cast<__nv_bfloat162*>(lp)     = l01;
    *reinterpret_cast<__nv_bfloat162*>(lp + 2) = l23;
}
__device__ __forceinline__ float redmax4(float v) {
    v = fmaxf(v, __shfl_xor_sync(0xffffffffu, v, 1));
    v = fmaxf(v, __shfl_xor_sync(0xffffffffu, v, 2));
    return v;
}
__device__ __forceinline__ float redsum4(float v) {
    v += __shfl_xor_sync(0xffffffffu, v, 1);
    v += __shfl_xor_sync(0xffffffffu, v, 2);
    return v;
}

// ---------------------------------------------------------------------------
// fp32 -> bf16 hi/lo split into tiled+swizzled 128x64 blocks (K = 1024).
// Block (rb, kc) at byte offset (rb*16 + kc)*16384; element (r, kk) at
// swz128(r*128 + kk*2) within the block.
// ---------------------------------------------------------------------------
__global__ __launch_bounds__(256) void split_tiled(const float* __restrict__ src,
                                                   __nv_bfloat16* __restrict__ hi,
                                                   __nv_bfloat16* __restrict__ lo,
                                                   int n4)
{
    int i = blockIdx.x * blockDim.x + threadIdx.x;
    if (i >= n4) return;
    float4 v = reinterpret_cast<const float4*>(src)[i];
    int row = i >> 8;            // 256 float4 per row
    int k4  = i & 255;
    int kc  = k4 >> 4;
    int kk  = (k4 << 2) & 63;
    int rb  = row >> 7;
    int r   = row & 127;
    size_t base = ((size_t)rb * 16 + kc) * 16384;
    uint32_t sw = swz128((uint32_t)(r * 128 + kk * 2));
    split4(v, (__nv_bfloat16*)((char*)hi + base + sw),
              (__nv_bfloat16*)((char*)lo + base + sw));
}

// ---------------------------------------------------------------------------
// bf16x3 GEMM (mma.sync) with cp.async.bulk 2-stage pipeline.
// CTA 128x128, K-chunks of 64. Stage = Ah|Al|Wh|Wl 16KB each = 64KB.
// EPI==0: bias, scatter q/k/v swizzled chunks (q pre-scaled). EPI==1: fp32 out.
// ---------------------------------------------------------------------------
template <int EPI>
__global__ __launch_bounds__(256) void blk_gemm(const __nv_bfloat16* __restrict__ Ah,
                                                const __nv_bfloat16* __restrict__ Al,
                                                const __nv_bfloat16* __restrict__ Wh,
                                                const __nv_bfloat16* __restrict__ Wl,
                                                const float* __restrict__ bias,
                                                float* __restrict__ out,
                                                int N)
{
    __shared__ __align__(16) uint64_t mbar[2];
    extern __shared__ __align__(16) char dyn[];

    const int tid  = threadIdx.x;
    const int lane = tid & 31;
    const int warp = tid >> 5;
    const int wm   = warp >> 2;
    const int wn   = warp & 3;
    const int mb   = blockIdx.y;
    const int nb   = blockIdx.x;

    const uint32_t dynb = (smem_u32(dyn) + 127u) & ~127u;
    const uint32_t fullb[2] = {smem_u32(&mbar[0]), smem_u32(&mbar[1])};

    if (tid == 0) { mbar_init(fullb[0], 1); mbar_init(fullb[1], 1); }
    __syncthreads();

    const char* pAh = (const char*)Ah + (size_t)mb * 16 * 16384;
    const char* pAl = (const char*)Al + (size_t)mb * 16 * 16384;
    const char* pWh = (const char*)Wh + (size_t)nb * 16 * 16384;
    const char* pWl = (const char*)Wl + (size_t)nb * 16 * 16384;

    auto load_chunk = [&](int s, int c) {
        uint32_t st = dynb + (uint32_t)s * 65536u;
        uint32_t fb = fullb[s];
        mbar_expect_tx(fb, 65536u);
        bulkcp(st,          pAh + (size_t)c * 16384, 16384, fb);
        bulkcp(st + 16384u, pAl + (size_t)c * 16384, 16384, fb);
        bulkcp(st + 32768u, pWh + (size_t)c * 16384, 16384, fb);
        bulkcp(st + 49152u, pWl + (size_t)c * 16384, 16384, fb);
    };

    if (tid == 0) { load_chunk(0, 0); load_chunk(1, 1); }

    float acc[4][4][4] = {};

    const int a_row  = wm * 64 + (lane & 15);
    const int a_koff = (lane >> 4) << 3;
    const int b_n    = wn * 32 + (lane & 7) + ((lane >> 4) << 3);
    const int b_koff = ((lane >> 3) & 1) << 3;

    int fph[2] = {0, 0};

    for (int c = 0; c < 16; c++) {
        int s = c & 1;
        mbar_wait(fullb[s], fph[s]); fph[s] ^= 1;
        uint32_t stb = dynb + (uint32_t)s * 65536u;

        #pragma unroll
        for (int ks = 0; ks < 64; ks += 16) {
            uint32_t ah[4][4], al[4][4];
            #pragma unroll
            for (int mt = 0; mt < 4; mt++) {
                uint32_t sw = swz128((uint32_t)((a_row + mt * 16) * 128 + (ks + a_koff) * 2));
                ldsm4(ah[mt][0], ah[mt][1], ah[mt][2], ah[mt][3], stb + sw);
                ldsm4(al[mt][0], al[mt][1], al[mt][2], al[mt][3], stb + 16384u + sw);
            }
            uint32_t bh[4][2], bl[4][2];
            #pragma unroll
            for (int p = 0; p < 2; p++) {
                uint32_t sw = swz128((uint32_t)((b_n + p * 16) * 128 + (ks + b_koff) * 2));
                uint32_t r0, r1, r2, r3;
                ldsm4(r0, r1, r2, r3, stb + 32768u + sw);
                bh[2 * p][0] = r0; bh[2 * p][1] = r1;
                bh[2 * p + 1][0] = r2; bh[2 * p + 1][1] = r3;
                ldsm4(r0, r1, r2, r3, stb + 49152u + sw);
                bl[2 * p][0] = r0; bl[2 * p][1] = r1;
                bl[2 * p + 1][0] = r2; bl[2 * p + 1][1] = r3;
            }
            #pragma unroll
            for (int mt = 0; mt < 4; mt++) {
                #pragma unroll
                for (int nt = 0; nt < 4; nt++) {
                    mma16816(acc[mt][nt], ah[mt][0], ah[mt][1], ah[mt][2], ah[mt][3],
                             bh[nt][0], bh[nt][1]);
                    mma16816(acc[mt][nt], ah[mt][0], ah[mt][1], ah[mt][2], ah[mt][3],
                             bl[nt][0], bl[nt][1]);
                    mma16816(acc[mt][nt], al[mt][0], al[mt][1], al[mt][2], al[mt][3],
                             bh[nt][0], bh[nt][1]);
                }
            }
        }
        __syncthreads();
        if (c + 2 < 16 && tid == 0) load_chunk(s, c + 2);
    }

    // epilogue
    const int row0 = mb * 128;
    const int col0 = nb * 128;
    const int r    = lane >> 2;
    const int cq   = (lane & 3) * 2;
    #pragma unroll
    for (int mt = 0; mt < 4; mt++) {
        int m0 = row0 + wm * 64 + mt * 16 + r;
        #pragma unroll
        for (int nt = 0; nt < 4; nt++) {
            int n = col0 + wn * 32 + nt * 8 + cq;
            float b0 = bias[n], b1 = bias[n + 1];
            float v00 = acc[mt][nt][0] + b0, v01 = acc[mt][nt][1] + b1;
            float v10 = acc[mt][nt][2] + b0, v11 = acc[mt][nt][3] + b1;
            if (EPI == 0) {
                #pragma unroll
                for (int e = 0; e < 4; e++) {
                    int m = m0 + (e >> 1) * 8;
                    int cc = n + (e & 1);
                    float val = (e == 0) ? v00 : (e == 1) ? v01 : (e == 2) ? v10 : v11;
                    int b    = m >> 10, t = m & 1023;
                    int part = cc >> 10, hc = cc & 1023;
                    int h = hc >> 6, hd = hc & 63;
                    if (part == 0) val *= SCALE;
                    __nv_bfloat16 hi = __float2bfloat16_rn(val);
                    __nv_bfloat16 lo = __float2bfloat16_rn(val - __bfloat162float(hi));
                    size_t cbase = ((size_t)((b * NHEAD + h) * 8 + (t >> 7))) * 16384;
                    uint32_t sw = swz128((uint32_t)(((t & 127) << 7) + hd * 2));
                    char *dh, *dl;
                    if (part == 0)      { dh = (char*)g_qh; dl = (char*)g_ql; }
                    else if (part == 1) { dh = (char*)g_kh; dl = (char*)g_kl; }
                    else                { dh = (char*)g_vh; dl = (char*)g_vl; }
                    *(__nv_bfloat16*)(dh + cbase + sw) = hi;
                    *(__nv_bfloat16*)(dl + cbase + sw) = lo;
                }
            } else {
                *(float2*)&out[(size_t)m0 * N + n]       = make_float2(v00, v01);
                *(float2*)&out[(size_t)(m0 + 8) * N + n] = make_float2(v10, v11);
            }
        }
    }
}

// ---------------------------------------------------------------------------
// bf16x3 flash attention (mma.sync) with cp.async.bulk loads.
// smem: Qh@0 Ql@16384 | KV stages @32768 + s*65536: Kh|Kl|Vh|Vl (16KB each).
// Total dynamic 163840 (+pad). All tiles swizzled 128x64 chunks.
// ---------------------------------------------------------------------------
__global__ __launch_bounds__(256) void mma_attn()
{
    __shared__ __align__(16) uint64_t abar[3];   // qbar, full0, full1
    extern __shared__ __align__(16) char dyn[];

    const int qb = blockIdx.x;
    const int bh = blockIdx.y;
    const int tid  = threadIdx.x;
    const int lane = tid & 31;
    const int w    = tid >> 5;

    const uint32_t dynb = (smem_u32(dyn) + 127u) & ~127u;
    const uint32_t qbar = smem_u32(&abar[0]);
    const uint32_t fullb[2] = {smem_u32(&abar[1]), smem_u32(&abar[2])};

    if (tid == 0) {
        mbar_init(qbar, 1);
        mbar_init(fullb[0], 1);
        mbar_init(fullb[1], 1);
    }
    __syncthreads();

    const size_t hbase = (size_t)bh * 8;   // chunk index base for this head

    auto load_kv = [&](int s, int kb) {
        uint32_t st = dynb + 32768u + (uint32_t)s * 65536u;
        uint32_t fb = fullb[s];
        size_t cb = (hbase + kb) * 16384;
        mbar_expect_tx(fb, 65536u);
        bulkcp(st,          (char*)g_kh + cb, 16384, fb);
        bulkcp(st + 16384u, (char*)g_kl + cb, 16384, fb);
        bulkcp(st + 32768u, (char*)g_vh + cb, 16384, fb);
        bulkcp(st + 49152u, (char*)g_vl + cb, 16384, fb);
    };

    if (tid == 0) {
        size_t qcb = (hbase + qb) * 16384;
        mbar_expect_tx(qbar, 32768u);
        bulkcp(dynb,          (char*)g_qh + qcb, 16384, qbar);
        bulkcp(dynb + 16384u, (char*)g_ql + qcb, 16384, qbar);
        load_kv(0, 0);
        load_kv(1, 1);
    }

    const int k_nloc = (lane & 7) + ((lane >> 4) << 3);
    const int k_koff = ((lane >> 3) & 1) << 3;
    const int v_krl  = (lane & 7) + (((lane >> 3) & 1) << 3);
    const int v_dc   = (lane >> 4) << 3;

    // Q fragments
    uint32_t qh[4][4], ql[4][4];
    mbar_wait(qbar, 0);
    {
        int qrow = w * 16 + (lane & 15);
        int qoff = (lane >> 4) << 3;
        #pragma unroll
        for (int kk = 0; kk < 4; kk++) {
            uint32_t sw = swz128((uint32_t)(qrow * 128 + (kk * 16 + qoff) * 2));
            ldsm4(qh[kk][0], qh[kk][1], qh[kk][2], qh[kk][3], dynb + sw);
            ldsm4(ql[kk][0], ql[kk][1], ql[kk][2], ql[kk][3], dynb + 16384u + sw);
        }
    }

    float O[8][4] = {};
    float rm0 = -INFINITY, rm1 = -INFINITY, rl0 = 0.f, rl1 = 0.f;
    int fph[2] = {0, 0};

    for (int kb = 0; kb < 8; kb++) {
        int s = kb & 1;
        mbar_wait(fullb[s], fph[s]); fph[s] ^= 1;
        uint32_t stb = dynb + 32768u + (uint32_t)s * 65536u;

        // ---- S = Q K^T ----
        float sa[16][4] = {};
        #pragma unroll
        for (int p = 0; p < 8; p++) {
            #pragma unroll
            for (int kk = 0; kk < 4; kk++) {
                uint32_t sw = swz128((uint32_t)((k_nloc + p * 16) * 128 + (kk * 16 + k_koff) * 2));
                uint32_t r0, r1, r2, r3, t0, t1, t2, t3;
                ldsm4(r0, r1, r2, r3, stb + sw);
                ldsm4(t0, t1, t2, t3, stb + 16384u + sw);
                mma16816(sa[2 * p],     qh[kk][0], qh[kk][1], qh[kk][2], qh[kk][3], r0, r1);
                mma16816(sa[2 * p],     qh[kk][0], qh[kk][1], qh[kk][2], qh[kk][3], t0, t1);
                mma16816(sa[2 * p],     ql[kk][0], ql[kk][1], ql[kk][2], ql[kk][3], r0, r1);
                mma16816(sa[2 * p + 1], qh[kk][0], qh[kk][1], qh[kk][2], qh[kk][3], r2, r3);
                mma16816(sa[2 * p + 1], qh[kk][0], qh[kk][1], qh[kk][2], qh[kk][3], t2, t3);
                mma16816(sa[2 * p + 1], ql[kk][0], ql[kk][1], ql[kk][2], ql[kk][3], r2, r3);
            }
        }

        // ---- online softmax (warp-local) ----
        float mx0 = -INFINITY, mx1 = -INFINITY;
        #pragma unroll
        for (int j = 0; j < 16; j++) {
            mx0 = fmaxf(mx0, fmaxf(sa[j][0], sa[j][1]));
            mx1 = fmaxf(mx1, fmaxf(sa[j][2], sa[j][3]));
        }
        mx0 = redmax4(mx0); mx1 = redmax4(mx1);
        float nm0 = fmaxf(rm0, mx0), nm1 = fmaxf(rm1, mx1);
        float al0 = __expf(rm0 - nm0), al1 = __expf(rm1 - nm1);
        rm0 = nm0; rm1 = nm1;
        float sm0 = 0.f, sm1 = 0.f;
        #pragma unroll
        for (int j = 0; j < 16; j++) {
            sa[j][0] = __expf(sa[j][0] - nm0);
            sa[j][1] = __expf(sa[j][1] - nm0);
            sa[j][2] = __expf(sa[j][2] - nm1);
            sa[j][3] = __expf(sa[j][3] - nm1);
            sm0 += sa[j][0] + sa[j][1];
            sm1 += sa[j][2] + sa[j][3];
        }
        sm0 = redsum4(sm0); sm1 = redsum4(sm1);
        rl0 = rl0 * al0 + sm0;
        rl1 = rl1 * al1 + sm1;
        #pragma unroll
        for (int nt = 0; nt < 8; nt++) {
            O[nt][0] *= al0; O[nt][1] *= al0;
            O[nt][2] *= al1; O[nt][3] *= al1;
        }

        // ---- O += P V ----
        #pragma unroll
        for (int kk = 0; kk < 8; kk++) {
            uint32_t ph[4], pl[4];
            splitpack(sa[2 * kk][0],     sa[2 * kk][1],     ph[0], pl[0]);
            splitpack(sa[2 * kk][2],     sa[2 * kk][3],     ph[1], pl[1]);
            splitpack(sa[2 * kk + 1][0], sa[2 * kk + 1][1], ph[2], pl[2]);
            splitpack(sa[2 * kk + 1][2], sa[2 * kk + 1][3], ph[3], pl[3]);
            #pragma unroll
            for (int pd = 0; pd < 4; pd++) {
                uint32_t sw = swz128((uint32_t)((v_krl + kk * 16) * 128 + (pd * 16 + v_dc) * 2));
                uint32_t v0, v1, v2, v3, u0, u1, u2, u3;
                ldsm4t(v0, v1, v2, v3, stb + 32768u + sw);
                ldsm4t(u0, u1, u2, u3, stb + 49152u + sw);
                mma16816(O[2 * pd],     ph[0], ph[1], ph[2], ph[3], v0, v1);
                mma16816(O[2 * pd],     ph[0], ph[1], ph[2], ph[3], u0, u1);
                mma16816(O[2 * pd],     pl[0], pl[1], pl[2], pl[3], v0, v1);
                mma16816(O[2 * pd + 1], ph[0], ph[1], ph[2], ph[3], v2, v3);
                mma16816(O[2 * pd + 1], ph[0], ph[1], ph[2], ph[3], u2, u3);
                mma16816(O[2 * pd + 1], pl[0], pl[1], pl[2], pl[3], v2, v3);
            }
        }
        __syncthreads();
        if (kb + 2 < 8 && tid == 0) load_kv(s, kb + 2);
    }

    // normalize; write z into tiled/swizzled proj A-blocks.
    float inv0 = 1.0f / rl0, inv1 = 1.0f / rl1;
    const int b = bh >> 4, h = bh & 15;
    const int t0 = qb * 128 + w * 16 + (lane >> 2);
    const int cq = (lane & 3) * 2;
    #pragma unroll
    for (int nt = 0; nt < 8; nt++) {
        int kk = nt * 8 + cq;
        #pragma unroll
        for (int e = 0; e < 2; e++) {
            int m = b * NTOK + t0 + e * 8;
            int mb2 = m >> 7, r = m & 127;
            size_t base = ((size_t)mb2 * 16 + h) * 16384;
            uint32_t sw = swz128((uint32_t)(r * 128 + kk * 2));
            uint32_t zh, zl;
            splitpack(O[nt][2 * e] * (e ? inv1 : inv0),
                      O[nt][2 * e + 1] * (e ? inv1 : inv0), zh, zl);
            *(uint32_t*)((char*)g_zh + base + sw) = zh;
            *(uint32_t*)((char*)g_zl + base + sw) = zl;
        }
    }
}

// ---------------------------------------------------------------------------
extern "C" void kernel_launch(void* const* d_in, const int* in_sizes, int n_in,
                              void* d_out, int out_size)
{
    const float* x      = (const float*)d_in[0];
    const float* qkv_w  = (const float*)d_in[1];
    const float* qkv_b  = (const float*)d_in[2];
    const float* proj_w = (const float*)d_in[3];
    const float* proj_b = (const float*)d_in[4];
    float* out = (float*)d_out;

    const int M = B_SZ * NTOK;

    cudaFuncSetAttribute(mma_attn, cudaFuncAttributeMaxDynamicSharedMemorySize, 164096);
    cudaFuncSetAttribute(blk_gemm<0>, cudaFuncAttributeMaxDynamicSharedMemorySize, 131328);
    cudaFuncSetAttribute(blk_gemm<1>, cudaFuncAttributeMaxDynamicSharedMemorySize, 131328);

    __nv_bfloat16 *xh, *xl, *qwh, *qwl, *pwh, *pwl, *zh, *zl;
    cudaGetSymbolAddress((void**)&xh,  g_xh);
    cudaGetSymbolAddress((void**)&xl,  g_xl);
    cudaGetSymbolAddress((void**)&qwh, g_qwh);
    cudaGetSymbolAddress((void**)&qwl, g_qwl);
    cudaGetSymbolAddress((void**)&pwh, g_pwh);
    cudaGetSymbolAddress((void**)&pwl, g_pwl);
    cudaGetSymbolAddress((void**)&zh,  g_zh);
    cudaGetSymbolAddress((void**)&zl,  g_zl);

    dim3 blk(256);

    // 0) pre-split inputs/weights to tiled+swizzled bf16 hi/lo
    split_tiled<<<(int)(MK / 4 / 256), blk>>>(x, xh, xl, (int)(MK / 4));
    split_tiled<<<(int)(QKV_W_N / 4 / 256), blk>>>(qkv_w, qwh, qwl, (int)(QKV_W_N / 4));
    split_tiled<<<(int)(PROJ_W_N / 4 / 256), blk>>>(proj_w, pwh, pwl, (int)(PROJ_W_N / 4));

    // 1) QKV GEMM -> q/k/v swizzled chunks
    blk_gemm<0><<<dim3(3 * DMODEL / 128, M / 128), blk, 131328>>>(
        xh, xl, qwh, qwl, qkv_b, nullptr, 3 * DMODEL);

    // 2) Flash attention -> z tiled/swizzled hi/lo
    mma_attn<<<dim3(NTOK / 128, B_SZ * NHEAD), blk, 164096>>>();

    // 3) Output projection -> out fp32
    blk_gemm<1><<<dim3(DMODEL / 128, M / 128), blk, 131328>>>(
        zh, zl, pwh, pwl, proj_b, out, DMODEL);
}

// round 7
// speedup vs baseline: 4.5033x; 1.0920x over previous
#include <cuda_runtime.h>
#include <cuda_bf16.h>
#include <math.h>
#include <stdint.h>
#include <stddef.h>

#define B_SZ   8
#define NTOK   1024
#define NHEAD  16
#define DHEAD  64
#define DMODEL 1024
#define SCALE  0.125f

#define MK ((size_t)B_SZ * NTOK * DMODEL)
#define QKV_W_N ((size_t)3 * DMODEL * DMODEL)
#define PROJ_W_N ((size_t)DMODEL * DMODEL)
#define HSZ ((size_t)B_SZ * NHEAD * NTOK * DHEAD)

// A-side operands: 128-row x 64-k SW128-swizzled 16KB blocks.
// W-side operands: 64-row x 64-k SW128-swizzled 8KB blocks.
__device__ __align__(1024) __nv_bfloat16 g_xh[MK],  g_xl[MK];
__device__ __align__(1024) __nv_bfloat16 g_qwh[QKV_W_N], g_qwl[QKV_W_N];
__device__ __align__(1024) __nv_bfloat16 g_pwh[PROJ_W_N], g_pwl[PROJ_W_N];
__device__ __align__(1024) __nv_bfloat16 g_zh[MK],  g_zl[MK];
// q/k/v: per (b,h) 8 chunks of 128 tokens x 64 d, swizzled within chunk
__device__ __align__(1024) __nv_bfloat16 g_qh[HSZ], g_ql[HSZ];
__device__ __align__(1024) __nv_bfloat16 g_kh[HSZ], g_kl[HSZ];
__device__ __align__(1024) __nv_bfloat16 g_vh[HSZ], g_vl[HSZ];

// ---------------------------------------------------------------------------
// helpers
// ---------------------------------------------------------------------------
__device__ __forceinline__ uint32_t smem_u32(const void* p) {
    return (uint32_t)__cvta_generic_to_shared(p);
}
__device__ __forceinline__ uint32_t swz128(uint32_t b) {   // Swizzle<3,4,3>
    return b ^ ((b >> 3) & 0x70);
}
__device__ __forceinline__ void bulkcp(uint32_t dst, const void* src, uint32_t bytes,
                                       uint32_t mbar) {
    asm volatile(
        "cp.async.bulk.shared::cta.global.mbarrier::complete_tx::bytes [%0], [%1], %2, [%3];"
        :: "r"(dst), "l"(src), "r"(bytes), "r"(mbar) : "memory");
}
__device__ __forceinline__ void mbar_init(uint32_t mbar, uint32_t cnt) {
    asm volatile("mbarrier.init.shared.b64 [%0], %1;" :: "r"(mbar), "r"(cnt) : "memory");
}
__device__ __forceinline__ void mbar_expect_tx(uint32_t mbar, uint32_t bytes) {
    asm volatile("mbarrier.arrive.expect_tx.shared.b64 _, [%0], %1;"
                 :: "r"(mbar), "r"(bytes) : "memory");
}
__device__ __forceinline__ void mbar_wait(uint32_t mbar, uint32_t phase) {
    asm volatile(
        "{\n\t.reg .pred P;\n\t"
        "W_%=:\n\t"
        "mbarrier.try_wait.parity.acquire.cta.shared::cta.b64 P, [%0], %1, 0x989680;\n\t"
        "@P bra D_%=;\n\t"
        "bra W_%=;\n\t"
        "D_%=:\n\t}"
        :: "r"(mbar), "r"(phase) : "memory");
}
__device__ __forceinline__ void ldsm4(uint32_t& r0, uint32_t& r1, uint32_t& r2, uint32_t& r3,
                                      uint32_t a) {
    asm volatile("ldmatrix.sync.aligned.m8n8.x4.shared.b16 {%0,%1,%2,%3}, [%4];"
                 : "=r"(r0), "=r"(r1), "=r"(r2), "=r"(r3) : "r"(a));
}
__device__ __forceinline__ void ldsm4t(uint32_t& r0, uint32_t& r1, uint32_t& r2, uint32_t& r3,
                                       uint32_t a) {
    asm volatile("ldmatrix.sync.aligned.m8n8.x4.trans.shared.b16 {%0,%1,%2,%3}, [%4];"
                 : "=r"(r0), "=r"(r1), "=r"(r2), "=r"(r3) : "r"(a));
}
__device__ __forceinline__ void mma16816(float* c,
                                         uint32_t a0, uint32_t a1, uint32_t a2, uint32_t a3,
                                         uint32_t b0, uint32_t b1) {
    asm volatile(
        "mma.sync.aligned.m16n8k16.row.col.f32.bf16.bf16.f32 "
        "{%0,%1,%2,%3},{%4,%5,%6,%7},{%8,%9},{%0,%1,%2,%3};"
        : "+f"(c[0]), "+f"(c[1]), "+f"(c[2]), "+f"(c[3])
        : "r"(a0), "r"(a1), "r"(a2), "r"(a3), "r"(b0), "r"(b1));
}
__device__ __forceinline__ void splitpack(float a, float b, uint32_t& hi, uint32_t& lo) {
    __nv_bfloat162 h = __float22bfloat162_rn(make_float2(a, b));
    float ra = a - __bfloat162float(h.x);
    float rb = b - __bfloat162float(h.y);
    __nv_bfloat162 l = __float22bfloat162_rn(make_float2(ra, rb));
    hi = *reinterpret_cast<uint32_t*>(&h);
    lo = *reinterpret_cast<uint32_t*>(&l);
}
__device__ __forceinline__ void split4(float4 v, __nv_bfloat16* hp, __nv_bfloat16* lp) {
    __nv_bfloat162 h01 = __float22bfloat162_rn(make_float2(v.x, v.y));
    __nv_bfloat162 h23 = __float22bfloat162_rn(make_float2(v.z, v.w));
    __nv_bfloat162 l01 = __float22bfloat162_rn(make_float2(v.x - __bfloat162float(h01.x),
                                                           v.y - __bfloat162float(h01.y)));
    __nv_bfloat162 l23 = __float22bfloat162_rn(make_float2(v.z - __bfloat162float(h23.x),
                                                           v.w - __bfloat162float(h23.y)));
    *reinterpret_cast<__nv_bfloat162*>(hp)     = h01;
    *reinterpret_cast<__nv_bfloat162*>(hp + 2) = h23;
    *reinterpret_cast<__nv_bfloat162*>(lp)     = l01;
    *reinterpret_cast<__nv_bfloat162*>(lp + 2) = l23;
}
__device__ __forceinline__ float redmax4(float v) {
    v = fmaxf(v, __shfl_xor_sync(0xffffffffu, v, 1));
    v = fmaxf(v, __shfl_xor_sync(0xffffffffu, v, 2));
    return v;
}
__device__ __forceinline__ float redsum4(float v) {
    v += __shfl_xor_sync(0xffffffffu, v, 1);
    v += __shfl_xor_sync(0xffffffffu, v, 2);
    return v;
}

// ---------------------------------------------------------------------------
// fp32 -> bf16 hi/lo split into tiled+swizzled RBx64 blocks (K = 1024).
// Block (rb, kc) at byte offset (rb*16 + kc)*(RB*128).
// ---------------------------------------------------------------------------
template <int RB>
__global__ __launch_bounds__(256) void split_tiled(const float* __restrict__ src,
                                                   __nv_bfloat16* __restrict__ hi,
                                                   __nv_bfloat16* __restrict__ lo,
                                                   int n4)
{
    int i = blockIdx.x * blockDim.x + threadIdx.x;
    if (i >= n4) return;
    float4 v = reinterpret_cast<const float4*>(src)[i];
    int row = i >> 8;            // 256 float4 per row
    int k4  = i & 255;
    int kc  = k4 >> 4;
    int kk  = (k4 << 2) & 63;
    int rb  = row / RB;
    int r   = row % RB;
    size_t base = ((size_t)rb * 16 + kc) * (RB * 128);
    uint32_t sw = swz128((uint32_t)(r * 128 + kk * 2));
    split4(v, (__nv_bfloat16*)((char*)hi + base + sw),
              (__nv_bfloat16*)((char*)lo + base + sw));
}

// ---------------------------------------------------------------------------
// bf16x3 GEMM (mma.sync), cp.async.bulk 2-stage pipeline, occupancy 2.
// CTA 128M x 64N, K-chunks of 64. Stage = Ah16|Al16|Wh8|Wl8 = 48KB.
// 8 warps: wm = warp&3 (32-row m-tiles), wn = warp>>2 (32-col n-tiles).
// EPI==0: bias, scatter q/k/v swizzled chunks (q pre-scaled). EPI==1: fp32 out.
// ---------------------------------------------------------------------------
template <int EPI>
__global__ __launch_bounds__(256, 2) void blk_gemm(const __nv_bfloat16* __restrict__ Ah,
                                                   const __nv_bfloat16* __restrict__ Al,
                                                   const __nv_bfloat16* __restrict__ Wh,
                                                   const __nv_bfloat16* __restrict__ Wl,
                                                   const float* __restrict__ bias,
                                                   float* __restrict__ out,
                                                   int N)
{
    __shared__ __align__(16) uint64_t mbar[2];
    extern __shared__ __align__(128) char dyn[];

    const int tid  = threadIdx.x;
    const int lane = tid & 31;
    const int warp = tid >> 5;
    const int wm   = warp & 3;
    const int wn   = warp >> 2;
    const int mb   = blockIdx.y;
    const int nb   = blockIdx.x;

    const uint32_t dynb = smem_u32(dyn);
    const uint32_t fullb[2] = {smem_u32(&mbar[0]), smem_u32(&mbar[1])};

    if (tid == 0) { mbar_init(fullb[0], 1); mbar_init(fullb[1], 1); }
    __syncthreads();

    const char* pAh = (const char*)Ah + (size_t)mb * 16 * 16384;
    const char* pAl = (const char*)Al + (size_t)mb * 16 * 16384;
    const char* pWh = (const char*)Wh + (size_t)nb * 16 * 8192;
    const char* pWl = (const char*)Wl + (size_t)nb * 16 * 8192;

    auto load_chunk = [&](int s, int c) {
        uint32_t st = dynb + (uint32_t)s * 49152u;
        uint32_t fb = fullb[s];
        mbar_expect_tx(fb, 49152u);
        bulkcp(st,          pAh + (size_t)c * 16384, 16384, fb);
        bulkcp(st + 16384u, pAl + (size_t)c * 16384, 16384, fb);
        bulkcp(st + 32768u, pWh + (size_t)c * 8192,  8192,  fb);
        bulkcp(st + 40960u, pWl + (size_t)c * 8192,  8192,  fb);
    };

    if (tid == 0) { load_chunk(0, 0); load_chunk(1, 1); }

    float acc[2][4][4] = {};

    const int a_row  = wm * 32 + (lane & 15);
    const int a_koff = (lane >> 4) << 3;
    const int b_n    = wn * 32 + (lane & 7) + ((lane >> 4) << 3);
    const int b_koff = ((lane >> 3) & 1) << 3;

    int fph[2] = {0, 0};

    for (int c = 0; c < 16; c++) {
        int s = c & 1;
        mbar_wait(fullb[s], fph[s]); fph[s] ^= 1;
        uint32_t stb = dynb + (uint32_t)s * 49152u;

        #pragma unroll
        for (int ks = 0; ks < 64; ks += 16) {
            uint32_t ah[2][4], al[2][4];
            #pragma unroll
            for (int mt = 0; mt < 2; mt++) {
                uint32_t sw = swz128((uint32_t)((a_row + mt * 16) * 128 + (ks + a_koff) * 2));
                ldsm4(ah[mt][0], ah[mt][1], ah[mt][2], ah[mt][3], stb + sw);
                ldsm4(al[mt][0], al[mt][1], al[mt][2], al[mt][3], stb + 16384u + sw);
            }
            uint32_t bh[4][2], bl[4][2];
            #pragma unroll
            for (int p = 0; p < 2; p++) {
                uint32_t sw = swz128((uint32_t)((b_n + p * 16) * 128 + (ks + b_koff) * 2));
                uint32_t r0, r1, r2, r3;
                ldsm4(r0, r1, r2, r3, stb + 32768u + sw);
                bh[2 * p][0] = r0; bh[2 * p][1] = r1;
                bh[2 * p + 1][0] = r2; bh[2 * p + 1][1] = r3;
                ldsm4(r0, r1, r2, r3, stb + 40960u + sw);
                bl[2 * p][0] = r0; bl[2 * p][1] = r1;
                bl[2 * p + 1][0] = r2; bl[2 * p + 1][1] = r3;
            }
            #pragma unroll
            for (int mt = 0; mt < 2; mt++) {
                #pragma unroll
                for (int nt = 0; nt < 4; nt++) {
                    mma16816(acc[mt][nt], ah[mt][0], ah[mt][1], ah[mt][2], ah[mt][3],
                             bh[nt][0], bh[nt][1]);
                    mma16816(acc[mt][nt], ah[mt][0], ah[mt][1], ah[mt][2], ah[mt][3],
                             bl[nt][0], bl[nt][1]);
                    mma16816(acc[mt][nt], al[mt][0], al[mt][1], al[mt][2], al[mt][3],
                             bh[nt][0], bh[nt][1]);
                }
            }
        }
        __syncthreads();
        if (c + 2 < 16 && tid == 0) load_chunk(s, c + 2);
    }

    // epilogue
    const int row0 = mb * 128;
    const int col0 = nb * 64;
    const int r    = lane >> 2;
    const int cq   = (lane & 3) * 2;
    #pragma unroll
    for (int mt = 0; mt < 2; mt++) {
        int m0 = row0 + wm * 32 + mt * 16 + r;
        #pragma unroll
        for (int nt = 0; nt < 4; nt++) {
            int n = col0 + wn * 32 + nt * 8 + cq;
            float b0 = bias[n], b1 = bias[n + 1];
            float v00 = acc[mt][nt][0] + b0, v01 = acc[mt][nt][1] + b1;
            float v10 = acc[mt][nt][2] + b0, v11 = acc[mt][nt][3] + b1;
            if (EPI == 0) {
                #pragma unroll
                for (int e = 0; e < 4; e++) {
                    int m = m0 + (e >> 1) * 8;
                    int cc = n + (e & 1);
                    float val = (e == 0) ? v00 : (e == 1) ? v01 : (e == 2) ? v10 : v11;
                    int b    = m >> 10, t = m & 1023;
                    int part = cc >> 10, hc = cc & 1023;
                    int h = hc >> 6, hd = hc & 63;
                    if (part == 0) val *= SCALE;
                    __nv_bfloat16 hi = __float2bfloat16_rn(val);
                    __nv_bfloat16 lo = __float2bfloat16_rn(val - __bfloat162float(hi));
                    size_t cbase = ((size_t)((b * NHEAD + h) * 8 + (t >> 7))) * 16384;
                    uint32_t sw = swz128((uint32_t)(((t & 127) << 7) + hd * 2));
                    char *dh, *dl;
                    if (part == 0)      { dh = (char*)g_qh; dl = (char*)g_ql; }
                    else if (part == 1) { dh = (char*)g_kh; dl = (char*)g_kl; }
                    else                { dh = (char*)g_vh; dl = (char*)g_vl; }
                    *(__nv_bfloat16*)(dh + cbase + sw) = hi;
                    *(__nv_bfloat16*)(dl + cbase + sw) = lo;
                }
            } else {
                *(float2*)&out[(size_t)m0 * N + n]       = make_float2(v00, v01);
                *(float2*)&out[(size_t)(m0 + 8) * N + n] = make_float2(v10, v11);
            }
        }
    }
}

// ---------------------------------------------------------------------------
// bf16x3 flash attention (mma.sync), 64-key tiles, occupancy 2.
// smem: Qh@0 Ql@16384 | stages @32768 + s*32768: Kh|Kl|Vh|Vl (8KB each).
// Total 98304 B. 16 KV tiles of 64 keys.
// ---------------------------------------------------------------------------
__global__ __launch_bounds__(256, 2) void mma_attn()
{
    __shared__ __align__(16) uint64_t abar[3];   // qbar, full0, full1
    extern __shared__ __align__(128) char dyn[];

    const int qb = blockIdx.x;
    const int bh = blockIdx.y;
    const int tid  = threadIdx.x;
    const int lane = tid & 31;
    const int w    = tid >> 5;

    const uint32_t dynb = smem_u32(dyn);
    const uint32_t qbar = smem_u32(&abar[0]);
    const uint32_t fullb[2] = {smem_u32(&abar[1]), smem_u32(&abar[2])};

    if (tid == 0) {
        mbar_init(qbar, 1);
        mbar_init(fullb[0], 1);
        mbar_init(fullb[1], 1);
    }
    __syncthreads();

    const size_t hbase = (size_t)bh * 8;

    auto load_kv = [&](int s, int t) {
        uint32_t st = dynb + 32768u + (uint32_t)s * 32768u;
        uint32_t fb = fullb[s];
        size_t cb = (hbase + (t >> 1)) * 16384 + (size_t)(t & 1) * 8192;
        mbar_expect_tx(fb, 32768u);
        bulkcp(st,          (char*)g_kh + cb, 8192, fb);
        bulkcp(st + 8192u,  (char*)g_kl + cb, 8192, fb);
        bulkcp(st + 16384u, (char*)g_vh + cb, 8192, fb);
        bulkcp(st + 24576u, (char*)g_vl + cb, 8192, fb);
    };

    if (tid == 0) {
        size_t qcb = (hbase + qb) * 16384;
        mbar_expect_tx(qbar, 32768u);
        bulkcp(dynb,          (char*)g_qh + qcb, 16384, qbar);
        bulkcp(dynb + 16384u, (char*)g_ql + qcb, 16384, qbar);
        load_kv(0, 0);
        load_kv(1, 1);
    }

    const int k_nloc = (lane & 7) + ((lane >> 4) << 3);
    const int k_koff = ((lane >> 3) & 1) << 3;
    const int v_krl  = (lane & 7) + (((lane >> 3) & 1) << 3);
    const int v_dc   = (lane >> 4) << 3;
    const int qrow   = w * 16 + (lane & 15);
    const int qoff   = (lane >> 4) << 3;

    float O[8][4] = {};
    float rm0 = -INFINITY, rm1 = -INFINITY, rl0 = 0.f, rl1 = 0.f;
    int fph[2] = {0, 0};

    mbar_wait(qbar, 0);

    for (int t = 0; t < 16; t++) {
        int s = t & 1;
        mbar_wait(fullb[s], fph[s]); fph[s] ^= 1;
        uint32_t stb = dynb + 32768u + (uint32_t)s * 32768u;

        // ---- S = Q K^T (kk outer: q frags transient) ----
        float sa[8][4] = {};
        #pragma unroll
        for (int kk = 0; kk < 4; kk++) {
            uint32_t qsw = swz128((uint32_t)(qrow * 128 + (kk * 16 + qoff) * 2));
            uint32_t q0, q1, q2, q3, l0, l1, l2, l3;
            ldsm4(q0, q1, q2, q3, dynb + qsw);
            ldsm4(l0, l1, l2, l3, dynb + 16384u + qsw);
            #pragma unroll
            for (int p = 0; p < 4; p++) {
                uint32_t sw = swz128((uint32_t)((k_nloc + p * 16) * 128 + (kk * 16 + k_koff) * 2));
                uint32_t r0, r1, r2, r3, t0, t1, t2, t3;
                ldsm4(r0, r1, r2, r3, stb + sw);
                ldsm4(t0, t1, t2, t3, stb + 8192u + sw);
                mma16816(sa[2 * p],     q0, q1, q2, q3, r0, r1);
                mma16816(sa[2 * p],     q0, q1, q2, q3, t0, t1);
                mma16816(sa[2 * p],     l0, l1, l2, l3, r0, r1);
                mma16816(sa[2 * p + 1], q0, q1, q2, q3, r2, r3);
                mma16816(sa[2 * p + 1], q0, q1, q2, q3, t2, t3);
                mma16816(sa[2 * p + 1], l0, l1, l2, l3, r2, r3);
            }
        }

        // ---- online softmax (warp-local) ----
        float mx0 = -INFINITY, mx1 = -INFINITY;
        #pragma unroll
        for (int j = 0; j < 8; j++) {
            mx0 = fmaxf(mx0, fmaxf(sa[j][0], sa[j][1]));
            mx1 = fmaxf(mx1, fmaxf(sa[j][2], sa[j][3]));
        }
        mx0 = redmax4(mx0); mx1 = redmax4(mx1);
        float nm0 = fmaxf(rm0, mx0), nm1 = fmaxf(rm1, mx1);
        float al0 = __expf(rm0 - nm0), al1 = __expf(rm1 - nm1);
        rm0 = nm0; rm1 = nm1;
        float sm0 = 0.f, sm1 = 0.f;
        #pragma unroll
        for (int j = 0; j < 8; j++) {
            sa[j][0] = __expf(sa[j][0] - nm0);
            sa[j][1] = __expf(sa[j][1] - nm0);
            sa[j][2] = __expf(sa[j][2] - nm1);
            sa[j][3] = __expf(sa[j][3] - nm1);
            sm0 += sa[j][0] + sa[j][1];
            sm1 += sa[j][2] + sa[j][3];
        }
        sm0 = redsum4(sm0); sm1 = redsum4(sm1);
        rl0 = rl0 * al0 + sm0;
        rl1 = rl1 * al1 + sm1;
        #pragma unroll
        for (int nt = 0; nt < 8; nt++) {
            O[nt][0] *= al0; O[nt][1] *= al0;
            O[nt][2] *= al1; O[nt][3] *= al1;
        }

        // ---- O += P V ----
        #pragma unroll
        for (int kk = 0; kk < 4; kk++) {
            uint32_t ph[4], pl[4];
            splitpack(sa[2 * kk][0],     sa[2 * kk][1],     ph[0], pl[0]);
            splitpack(sa[2 * kk][2],     sa[2 * kk][3],     ph[1], pl[1]);
            splitpack(sa[2 * kk + 1][0], sa[2 * kk + 1][1], ph[2], pl[2]);
            splitpack(sa[2 * kk + 1][2], sa[2 * kk + 1][3], ph[3], pl[3]);
            #pragma unroll
            for (int pd = 0; pd < 4; pd++) {
                uint32_t sw = swz128((uint32_t)((v_krl + kk * 16) * 128 + (pd * 16 + v_dc) * 2));
                uint32_t v0, v1, v2, v3, u0, u1, u2, u3;
                ldsm4t(v0, v1, v2, v3, stb + 16384u + sw);
                ldsm4t(u0, u1, u2, u3, stb + 24576u + sw);
                mma16816(O[2 * pd],     ph[0], ph[1], ph[2], ph[3], v0, v1);
                mma16816(O[2 * pd],     ph[0], ph[1], ph[2], ph[3], u0, u1);
                mma16816(O[2 * pd],     pl[0], pl[1], pl[2], pl[3], v0, v1);
                mma16816(O[2 * pd + 1], ph[0], ph[1], ph[2], ph[3], v2, v3);
                mma16816(O[2 * pd + 1], ph[0], ph[1], ph[2], ph[3], u2, u3);
                mma16816(O[2 * pd + 1], pl[0], pl[1], pl[2], pl[3], v2, v3);
            }
        }
        __syncthreads();
        if (t + 2 < 16 && tid == 0) load_kv(s, t + 2);
    }

    // normalize; write z into tiled/swizzled proj A-blocks.
    float inv0 = 1.0f / rl0, inv1 = 1.0f / rl1;
    const int b = bh >> 4, h = bh & 15;
    const int t0 = qb * 128 + w * 16 + (lane >> 2);
    const int cq = (lane & 3) * 2;
    #pragma unroll
    for (int nt = 0; nt < 8; nt++) {
        int kk = nt * 8 + cq;
        #pragma unroll
        for (int e = 0; e < 2; e++) {
            int m = b * NTOK + t0 + e * 8;
            int mb2 = m >> 7, r = m & 127;
            size_t base = ((size_t)mb2 * 16 + h) * 16384;
            uint32_t sw = swz128((uint32_t)(r * 128 + kk * 2));
            uint32_t zh, zl;
            splitpack(O[nt][2 * e] * (e ? inv1 : inv0),
                      O[nt][2 * e + 1] * (e ? inv1 : inv0), zh, zl);
            *(uint32_t*)((char*)g_zh + base + sw) = zh;
            *(uint32_t*)((char*)g_zl + base + sw) = zl;
        }
    }
}

// ---------------------------------------------------------------------------
extern "C" void kernel_launch(void* const* d_in, const int* in_sizes, int n_in,
                              void* d_out, int out_size)
{
    const float* x      = (const float*)d_in[0];
    const float* qkv_w  = (const float*)d_in[1];
    const float* qkv_b  = (const float*)d_in[2];
    const float* proj_w = (const float*)d_in[3];
    const float* proj_b = (const float*)d_in[4];
    float* out = (float*)d_out;

    const int M = B_SZ * NTOK;

    cudaFuncSetAttribute(mma_attn, cudaFuncAttributeMaxDynamicSharedMemorySize, 98304);
    cudaFuncSetAttribute(blk_gemm<0>, cudaFuncAttributeMaxDynamicSharedMemorySize, 98304);
    cudaFuncSetAttribute(blk_gemm<1>, cudaFuncAttributeMaxDynamicSharedMemorySize, 98304);

    __nv_bfloat16 *xh, *xl, *qwh, *qwl, *pwh, *pwl, *zh, *zl;
    cudaGetSymbolAddress((void**)&xh,  g_xh);
    cudaGetSymbolAddress((void**)&xl,  g_xl);
    cudaGetSymbolAddress((void**)&qwh, g_qwh);
    cudaGetSymbolAddress((void**)&qwl, g_qwl);
    cudaGetSymbolAddress((void**)&pwh, g_pwh);
    cudaGetSymbolAddress((void**)&pwl, g_pwl);
    cudaGetSymbolAddress((void**)&zh,  g_zh);
    cudaGetSymbolAddress((void**)&zl,  g_zl);

    dim3 blk(256);

    // 0) pre-split: A-side (x) 128-row blocks; W-side 64-row blocks
    split_tiled<128><<<(int)(MK / 4 / 256), blk>>>(x, xh, xl, (int)(MK / 4));
    split_tiled<64><<<(int)(QKV_W_N / 4 / 256), blk>>>(qkv_w, qwh, qwl, (int)(QKV_W_N / 4));
    split_tiled<64><<<(int)(PROJ_W_N / 4 / 256), blk>>>(proj_w, pwh, pwl, (int)(PROJ_W_N / 4));

    // 1) QKV GEMM -> q/k/v swizzled chunks
    blk_gemm<0><<<dim3(3 * DMODEL / 64, M / 128), blk, 98304>>>(
        xh, xl, qwh, qwl, qkv_b, nullptr, 3 * DMODEL);

    // 2) Flash attention -> z tiled/swizzled hi/lo
    mma_attn<<<dim3(NTOK / 128, B_SZ * NHEAD), blk, 98304>>>();

    // 3) Output projection -> out fp32
    blk_gemm<1><<<dim3(DMODEL / 64, M / 128), blk, 98304>>>(
        zh, zl, pwh, pwl, proj_b, out, DMODEL);
}

// round 8
// speedup vs baseline: 5.6543x; 1.2556x over previous
#include <cuda_runtime.h>
#include <cuda_fp16.h>
#include <math.h>
#include <stdint.h>
#include <stddef.h>

#define B_SZ   8
#define NTOK   1024
#define NHEAD  16
#define DHEAD  64
#define DMODEL 1024
#define SCALE  0.125f

#define MK ((size_t)B_SZ * NTOK * DMODEL)
#define QKV_W_N ((size_t)3 * DMODEL * DMODEL)
#define PROJ_W_N ((size_t)DMODEL * DMODEL)
#define HSZ ((size_t)B_SZ * NHEAD * NTOK * DHEAD)

// All operands pre-tiled into 128-row x 64-k SW128-swizzled 16KB blocks.
__device__ __align__(1024) __half g_xh[MK],  g_xl[MK];
__device__ __align__(1024) __half g_qwh[QKV_W_N];          // weights: rounded only
__device__ __align__(1024) __half g_pwh[PROJ_W_N];
__device__ __align__(1024) __half g_zh[MK],  g_zl[MK];
// q/k/v: per (b,h) 8 chunks of 128 tokens x 64 d, swizzled within chunk
__device__ __align__(1024) __half g_qh[HSZ], g_ql[HSZ];
__device__ __align__(1024) __half g_kh[HSZ], g_kl[HSZ];
__device__ __align__(1024) __half g_vh[HSZ], g_vl[HSZ];

// ---------------------------------------------------------------------------
// helpers
// ---------------------------------------------------------------------------
__device__ __forceinline__ uint32_t smem_u32(const void* p) {
    return (uint32_t)__cvta_generic_to_shared(p);
}
__device__ __forceinline__ uint32_t swz128(uint32_t b) {   // Swizzle<3,4,3>
    return b ^ ((b >> 3) & 0x70);
}
__device__ __forceinline__ void bulkcp(uint32_t dst, const void* src, uint32_t bytes,
                                       uint32_t mbar) {
    asm volatile(
        "cp.async.bulk.shared::cta.global.mbarrier::complete_tx::bytes [%0], [%1], %2, [%3];"
        :: "r"(dst), "l"(src), "r"(bytes), "r"(mbar) : "memory");
}
__device__ __forceinline__ void mbar_init(uint32_t mbar, uint32_t cnt) {
    asm volatile("mbarrier.init.shared.b64 [%0], %1;" :: "r"(mbar), "r"(cnt) : "memory");
}
__device__ __forceinline__ void mbar_expect_tx(uint32_t mbar, uint32_t bytes) {
    asm volatile("mbarrier.arrive.expect_tx.shared.b64 _, [%0], %1;"
                 :: "r"(mbar), "r"(bytes) : "memory");
}
__device__ __forceinline__ void mbar_wait(uint32_t mbar, uint32_t phase) {
    asm volatile(
        "{\n\t.reg .pred P;\n\t"
        "W_%=:\n\t"
        "mbarrier.try_wait.parity.acquire.cta.shared::cta.b64 P, [%0], %1, 0x989680;\n\t"
        "@P bra D_%=;\n\t"
        "bra W_%=;\n\t"
        "D_%=:\n\t}"
        :: "r"(mbar), "r"(phase) : "memory");
}
__device__ __forceinline__ void ldsm4(uint32_t& r0, uint32_t& r1, uint32_t& r2, uint32_t& r3,
                                      uint32_t a) {
    asm volatile("ldmatrix.sync.aligned.m8n8.x4.shared.b16 {%0,%1,%2,%3}, [%4];"
                 : "=r"(r0), "=r"(r1), "=r"(r2), "=r"(r3) : "r"(a));
}
__device__ __forceinline__ void ldsm4t(uint32_t& r0, uint32_t& r1, uint32_t& r2, uint32_t& r3,
                                       uint32_t a) {
    asm volatile("ldmatrix.sync.aligned.m8n8.x4.trans.shared.b16 {%0,%1,%2,%3}, [%4];"
                 : "=r"(r0), "=r"(r1), "=r"(r2), "=r"(r3) : "r"(a));
}
__device__ __forceinline__ void mma16816(float* c,
                                         uint32_t a0, uint32_t a1, uint32_t a2, uint32_t a3,
                                         uint32_t b0, uint32_t b1) {
    asm volatile(
        "mma.sync.aligned.m16n8k16.row.col.f32.f16.f16.f32 "
        "{%0,%1,%2,%3},{%4,%5,%6,%7},{%8,%9},{%0,%1,%2,%3};"
        : "+f"(c[0]), "+f"(c[1]), "+f"(c[2]), "+f"(c[3])
        : "r"(a0), "r"(a1), "r"(a2), "r"(a3), "r"(b0), "r"(b1));
}
__device__ __forceinline__ void splitpack(float a, float b, uint32_t& hi, uint32_t& lo) {
    __half2 h = __floats2half2_rn(a, b);
    float2 hf = __half22float2(h);
    __half2 l = __floats2half2_rn(a - hf.x, b - hf.y);
    hi = *reinterpret_cast<uint32_t*>(&h);
    lo = *reinterpret_cast<uint32_t*>(&l);
}
__device__ __forceinline__ void split4(float4 v, __half* hp, __half* lp) {
    __half2 h01 = __floats2half2_rn(v.x, v.y);
    __half2 h23 = __floats2half2_rn(v.z, v.w);
    float2 f01 = __half22float2(h01);
    float2 f23 = __half22float2(h23);
    __half2 l01 = __floats2half2_rn(v.x - f01.x, v.y - f01.y);
    __half2 l23 = __floats2half2_rn(v.z - f23.x, v.w - f23.y);
    *reinterpret_cast<__half2*>(hp)     = h01;
    *reinterpret_cast<__half2*>(hp + 2) = h23;
    *reinterpret_cast<__half2*>(lp)     = l01;
    *reinterpret_cast<__half2*>(lp + 2) = l23;
}
__device__ __forceinline__ float redmax4(float v) {
    v = fmaxf(v, __shfl_xor_sync(0xffffffffu, v, 1));
    v = fmaxf(v, __shfl_xor_sync(0xffffffffu, v, 2));
    return v;
}
__device__ __forceinline__ float redsum4(float v) {
    v += __shfl_xor_sync(0xffffffffu, v, 1);
    v += __shfl_xor_sync(0xffffffffu, v, 2);
    return v;
}

// ---------------------------------------------------------------------------
// fp32 -> fp16 hi/lo split into tiled+swizzled 128x64 blocks (K = 1024).
// ---------------------------------------------------------------------------
__global__ __launch_bounds__(256) void split_tiled(const float* __restrict__ src,
                                                   __half* __restrict__ hi,
                                                   __half* __restrict__ lo,
                                                   int n4)
{
    int i = blockIdx.x * blockDim.x + threadIdx.x;
    if (i >= n4) return;
    float4 v = reinterpret_cast<const float4*>(src)[i];
    int row = i >> 8;
    int k4  = i & 255;
    int kc  = k4 >> 4;
    int kk  = (k4 << 2) & 63;
    int rb  = row >> 7;
    int r   = row & 127;
    size_t base = ((size_t)rb * 16 + kc) * 16384;
    uint32_t sw = swz128((uint32_t)(r * 128 + kk * 2));
    split4(v, (__half*)((char*)hi + base + sw), (__half*)((char*)lo + base + sw));
}

// fp32 -> fp16 round-only (weights), same tiling
__global__ __launch_bounds__(256) void round_tiled(const float* __restrict__ src,
                                                   __half* __restrict__ hi,
                                                   int n4)
{
    int i = blockIdx.x * blockDim.x + threadIdx.x;
    if (i >= n4) return;
    float4 v = reinterpret_cast<const float4*>(src)[i];
    int row = i >> 8;
    int k4  = i & 255;
    int kc  = k4 >> 4;
    int kk  = (k4 << 2) & 63;
    int rb  = row >> 7;
    int r   = row & 127;
    size_t base = ((size_t)rb * 16 + kc) * 16384;
    uint32_t sw = swz128((uint32_t)(r * 128 + kk * 2));
    __half* hp = (__half*)((char*)hi + base + sw);
    *reinterpret_cast<__half2*>(hp)     = __floats2half2_rn(v.x, v.y);
    *reinterpret_cast<__half2*>(hp + 2) = __floats2half2_rn(v.z, v.w);
}

// ---------------------------------------------------------------------------
// fp16 2-chain GEMM (mma.sync): C = (Ah+Al) @ Wh^T + bias.
// CTA 128M x 128N, K-chunks of 64, 2-stage bulk pipeline, occupancy 2.
// Stage = Ah16|Al16|Wh16 = 48KB. 8 warps: wm=warp>>2 (64M), wn=warp&3 (32N).
// EPI==0: scatter q/k/v fp16 hi/lo swizzled chunks (q pre-scaled). EPI==1: fp32 out.
// ---------------------------------------------------------------------------
template <int EPI>
__global__ __launch_bounds__(256, 2) void blk_gemm(const __half* __restrict__ Ah,
                                                   const __half* __restrict__ Al,
                                                   const __half* __restrict__ Wh,
                                                   const float* __restrict__ bias,
                                                   float* __restrict__ out,
                                                   int N)
{
    __shared__ __align__(16) uint64_t mbar[2];
    extern __shared__ __align__(128) char dyn[];

    const int tid  = threadIdx.x;
    const int lane = tid & 31;
    const int warp = tid >> 5;
    const int wm   = warp >> 2;
    const int wn   = warp & 3;
    const int mb   = blockIdx.y;
    const int nb   = blockIdx.x;

    const uint32_t dynb = smem_u32(dyn);
    const uint32_t fullb[2] = {smem_u32(&mbar[0]), smem_u32(&mbar[1])};

    if (tid == 0) { mbar_init(fullb[0], 1); mbar_init(fullb[1], 1); }
    __syncthreads();

    const char* pAh = (const char*)Ah + (size_t)mb * 16 * 16384;
    const char* pAl = (const char*)Al + (size_t)mb * 16 * 16384;
    const char* pWh = (const char*)Wh + (size_t)nb * 16 * 16384;

    auto load_chunk = [&](int s, int c) {
        uint32_t st = dynb + (uint32_t)s * 49152u;
        uint32_t fb = fullb[s];
        mbar_expect_tx(fb, 49152u);
        bulkcp(st,          pAh + (size_t)c * 16384, 16384, fb);
        bulkcp(st + 16384u, pAl + (size_t)c * 16384, 16384, fb);
        bulkcp(st + 32768u, pWh + (size_t)c * 16384, 16384, fb);
    };

    if (tid == 0) { load_chunk(0, 0); load_chunk(1, 1); }

    float acc[4][4][4] = {};

    const int a_row  = wm * 64 + (lane & 15);
    const int a_koff = (lane >> 4) << 3;
    const int b_n    = wn * 32 + (lane & 7) + ((lane >> 4) << 3);
    const int b_koff = ((lane >> 3) & 1) << 3;

    int fph[2] = {0, 0};

    for (int c = 0; c < 16; c++) {
        int s = c & 1;
        mbar_wait(fullb[s], fph[s]); fph[s] ^= 1;
        uint32_t stb = dynb + (uint32_t)s * 49152u;

        #pragma unroll
        for (int ks = 0; ks < 64; ks += 16) {
            uint32_t bh[4][2];
            #pragma unroll
            for (int p = 0; p < 2; p++) {
                uint32_t sw = swz128((uint32_t)((b_n + p * 16) * 128 + (ks + b_koff) * 2));
                uint32_t r0, r1, r2, r3;
                ldsm4(r0, r1, r2, r3, stb + 32768u + sw);
                bh[2 * p][0] = r0; bh[2 * p][1] = r1;
                bh[2 * p + 1][0] = r2; bh[2 * p + 1][1] = r3;
            }
            #pragma unroll
            for (int mt = 0; mt < 4; mt++) {
                uint32_t sw = swz128((uint32_t)((a_row + mt * 16) * 128 + (ks + a_koff) * 2));
                uint32_t a0, a1, a2, a3, l0, l1, l2, l3;
                ldsm4(a0, a1, a2, a3, stb + sw);
                ldsm4(l0, l1, l2, l3, stb + 16384u + sw);
                #pragma unroll
                for (int nt = 0; nt < 4; nt++) {
                    mma16816(acc[mt][nt], a0, a1, a2, a3, bh[nt][0], bh[nt][1]);
                    mma16816(acc[mt][nt], l0, l1, l2, l3, bh[nt][0], bh[nt][1]);
                }
            }
        }
        __syncthreads();
        if (c + 2 < 16 && tid == 0) load_chunk(s, c + 2);
    }

    // epilogue
    const int row0 = mb * 128;
    const int col0 = nb * 128;
    const int r    = lane >> 2;
    const int cq   = (lane & 3) * 2;
    #pragma unroll
    for (int mt = 0; mt < 4; mt++) {
        int m0 = row0 + wm * 64 + mt * 16 + r;
        #pragma unroll
        for (int nt = 0; nt < 4; nt++) {
            int n = col0 + wn * 32 + nt * 8 + cq;
            float b0 = bias[n], b1 = bias[n + 1];
            float v00 = acc[mt][nt][0] + b0, v01 = acc[mt][nt][1] + b1;
            float v10 = acc[mt][nt][2] + b0, v11 = acc[mt][nt][3] + b1;
            if (EPI == 0) {
                #pragma unroll
                for (int e = 0; e < 4; e++) {
                    int m = m0 + (e >> 1) * 8;
                    int cc = n + (e & 1);
                    float val = (e == 0) ? v00 : (e == 1) ? v01 : (e == 2) ? v10 : v11;
                    int b    = m >> 10, t = m & 1023;
                    int part = cc >> 10, hc = cc & 1023;
                    int h = hc >> 6, hd = hc & 63;
                    if (part == 0) val *= SCALE;
                    __half hi = __float2half_rn(val);
                    __half lo = __float2half_rn(val - __half2float(hi));
                    size_t cbase = ((size_t)((b * NHEAD + h) * 8 + (t >> 7))) * 16384;
                    uint32_t sw = swz128((uint32_t)(((t & 127) << 7) + hd * 2));
                    char *dh, *dl;
                    if (part == 0)      { dh = (char*)g_qh; dl = (char*)g_ql; }
                    else if (part == 1) { dh = (char*)g_kh; dl = (char*)g_kl; }
                    else                { dh = (char*)g_vh; dl = (char*)g_vl; }
                    *(__half*)(dh + cbase + sw) = hi;
                    *(__half*)(dl + cbase + sw) = lo;
                }
            } else {
                *(float2*)&out[(size_t)m0 * N + n]       = make_float2(v00, v01);
                *(float2*)&out[(size_t)(m0 + 8) * N + n] = make_float2(v10, v11);
            }
        }
    }
}

// ---------------------------------------------------------------------------
// fp16x3 flash attention (mma.sync), 64-key tiles, occupancy 2.
// smem: Qh@0 Ql@16384 | stages @32768 + s*32768: Kh|Kl|Vh|Vl (8KB each).
// Total 98304 B. 16 KV tiles of 64 keys.
// ---------------------------------------------------------------------------
__global__ __launch_bounds__(256, 2) void mma_attn()
{
    __shared__ __align__(16) uint64_t abar[3];
    extern __shared__ __align__(128) char dyn[];

    const int qb = blockIdx.x;
    const int bh = blockIdx.y;
    const int tid  = threadIdx.x;
    const int lane = tid & 31;
    const int w    = tid >> 5;

    const uint32_t dynb = smem_u32(dyn);
    const uint32_t qbar = smem_u32(&abar[0]);
    const uint32_t fullb[2] = {smem_u32(&abar[1]), smem_u32(&abar[2])};

    if (tid == 0) {
        mbar_init(qbar, 1);
        mbar_init(fullb[0], 1);
        mbar_init(fullb[1], 1);
    }
    __syncthreads();

    const size_t hbase = (size_t)bh * 8;

    auto load_kv = [&](int s, int t) {
        uint32_t st = dynb + 32768u + (uint32_t)s * 32768u;
        uint32_t fb = fullb[s];
        size_t cb = (hbase + (t >> 1)) * 16384 + (size_t)(t & 1) * 8192;
        mbar_expect_tx(fb, 32768u);
        bulkcp(st,          (char*)g_kh + cb, 8192, fb);
        bulkcp(st + 8192u,  (char*)g_kl + cb, 8192, fb);
        bulkcp(st + 16384u, (char*)g_vh + cb, 8192, fb);
        bulkcp(st + 24576u, (char*)g_vl + cb, 8192, fb);
    };

    if (tid == 0) {
        size_t qcb = (hbase + qb) * 16384;
        mbar_expect_tx(qbar, 32768u);
        bulkcp(dynb,          (char*)g_qh + qcb, 16384, qbar);
        bulkcp(dynb + 16384u, (char*)g_ql + qcb, 16384, qbar);
        load_kv(0, 0);
        load_kv(1, 1);
    }

    const int k_nloc = (lane & 7) + ((lane >> 4) << 3);
    const int k_koff = ((lane >> 3) & 1) << 3;
    const int v_krl  = (lane & 7) + (((lane >> 3) & 1) << 3);
    const int v_dc   = (lane >> 4) << 3;
    const int qrow   = w * 16 + (lane & 15);
    const int qoff   = (lane >> 4) << 3;

    float O[8][4] = {};
    float rm0 = -INFINITY, rm1 = -INFINITY, rl0 = 0.f, rl1 = 0.f;
    int fph[2] = {0, 0};

    mbar_wait(qbar, 0);

    for (int t = 0; t < 16; t++) {
        int s = t & 1;
        mbar_wait(fullb[s], fph[s]); fph[s] ^= 1;
        uint32_t stb = dynb + 32768u + (uint32_t)s * 32768u;

        // ---- S = Q K^T (3 chains) ----
        float sa[8][4] = {};
        #pragma unroll
        for (int kk = 0; kk < 4; kk++) {
            uint32_t qsw = swz128((uint32_t)(qrow * 128 + (kk * 16 + qoff) * 2));
            uint32_t q0, q1, q2, q3, l0, l1, l2, l3;
            ldsm4(q0, q1, q2, q3, dynb + qsw);
            ldsm4(l0, l1, l2, l3, dynb + 16384u + qsw);
            #pragma unroll
            for (int p = 0; p < 4; p++) {
                uint32_t sw = swz128((uint32_t)((k_nloc + p * 16) * 128 + (kk * 16 + k_koff) * 2));
                uint32_t r0, r1, r2, r3, t0, t1, t2, t3;
                ldsm4(r0, r1, r2, r3, stb + sw);
                ldsm4(t0, t1, t2, t3, stb + 8192u + sw);
                mma16816(sa[2 * p],     q0, q1, q2, q3, r0, r1);
                mma16816(sa[2 * p],     q0, q1, q2, q3, t0, t1);
                mma16816(sa[2 * p],     l0, l1, l2, l3, r0, r1);
                mma16816(sa[2 * p + 1], q0, q1, q2, q3, r2, r3);
                mma16816(sa[2 * p + 1], q0, q1, q2, q3, t2, t3);
                mma16816(sa[2 * p + 1], l0, l1, l2, l3, r2, r3);
            }
        }

        // ---- online softmax (warp-local) ----
        float mx0 = -INFINITY, mx1 = -INFINITY;
        #pragma unroll
        for (int j = 0; j < 8; j++) {
            mx0 = fmaxf(mx0, fmaxf(sa[j][0], sa[j][1]));
            mx1 = fmaxf(mx1, fmaxf(sa[j][2], sa[j][3]));
        }
        mx0 = redmax4(mx0); mx1 = redmax4(mx1);
        float nm0 = fmaxf(rm0, mx0), nm1 = fmaxf(rm1, mx1);
        float al0 = __expf(rm0 - nm0), al1 = __expf(rm1 - nm1);
        rm0 = nm0; rm1 = nm1;
        float sm0 = 0.f, sm1 = 0.f;
        #pragma unroll
        for (int j = 0; j < 8; j++) {
            sa[j][0] = __expf(sa[j][0] - nm0);
            sa[j][1] = __expf(sa[j][1] - nm0);
            sa[j][2] = __expf(sa[j][2] - nm1);
            sa[j][3] = __expf(sa[j][3] - nm1);
            sm0 += sa[j][0] + sa[j][1];
            sm1 += sa[j][2] + sa[j][3];
        }
        sm0 = redsum4(sm0); sm1 = redsum4(sm1);
        rl0 = rl0 * al0 + sm0;
        rl1 = rl1 * al1 + sm1;
        #pragma unroll
        for (int nt = 0; nt < 8; nt++) {
            O[nt][0] *= al0; O[nt][1] *= al0;
            O[nt][2] *= al1; O[nt][3] *= al1;
        }

        // ---- O += P V (3 chains) ----
        #pragma unroll
        for (int kk = 0; kk < 4; kk++) {
            uint32_t ph[4], pl[4];
            splitpack(sa[2 * kk][0],     sa[2 * kk][1],     ph[0], pl[0]);
            splitpack(sa[2 * kk][2],     sa[2 * kk][3],     ph[1], pl[1]);
            splitpack(sa[2 * kk + 1][0], sa[2 * kk + 1][1], ph[2], pl[2]);
            splitpack(sa[2 * kk + 1][2], sa[2 * kk + 1][3], ph[3], pl[3]);
            #pragma unroll
            for (int pd = 0; pd < 4; pd++) {
                uint32_t sw = swz128((uint32_t)((v_krl + kk * 16) * 128 + (pd * 16 + v_dc) * 2));
                uint32_t v0, v1, v2, v3, u0, u1, u2, u3;
                ldsm4t(v0, v1, v2, v3, stb + 16384u + sw);
                ldsm4t(u0, u1, u2, u3, stb + 24576u + sw);
                mma16816(O[2 * pd],     ph[0], ph[1], ph[2], ph[3], v0, v1);
                mma16816(O[2 * pd],     ph[0], ph[1], ph[2], ph[3], u0, u1);
                mma16816(O[2 * pd],     pl[0], pl[1], pl[2], pl[3], v0, v1);
                mma16816(O[2 * pd + 1], ph[0], ph[1], ph[2], ph[3], v2, v3);
                mma16816(O[2 * pd + 1], ph[0], ph[1], ph[2], ph[3], u2, u3);
                mma16816(O[2 * pd + 1], pl[0], pl[1], pl[2], pl[3], v2, v3);
            }
        }
        __syncthreads();
        if (t + 2 < 16 && tid == 0) load_kv(s, t + 2);
    }

    // normalize; write z into tiled/swizzled proj A-blocks (fp16 hi/lo).
    float inv0 = 1.0f / rl0, inv1 = 1.0f / rl1;
    const int b = bh >> 4, h = bh & 15;
    const int t0 = qb * 128 + w * 16 + (lane >> 2);
    const int cq = (lane & 3) * 2;
    #pragma unroll
    for (int nt = 0; nt < 8; nt++) {
        int kk = nt * 8 + cq;
        #pragma unroll
        for (int e = 0; e < 2; e++) {
            int m = b * NTOK + t0 + e * 8;
            int mb2 = m >> 7, r = m & 127;
            size_t base = ((size_t)mb2 * 16 + h) * 16384;
            uint32_t sw = swz128((uint32_t)(r * 128 + kk * 2));
            uint32_t zh, zl;
            splitpack(O[nt][2 * e] * (e ? inv1 : inv0),
                      O[nt][2 * e + 1] * (e ? inv1 : inv0), zh, zl);
            *(uint32_t*)((char*)g_zh + base + sw) = zh;
            *(uint32_t*)((char*)g_zl + base + sw) = zl;
        }
    }
}

// ---------------------------------------------------------------------------
extern "C" void kernel_launch(void* const* d_in, const int* in_sizes, int n_in,
                              void* d_out, int out_size)
{
    const float* x      = (const float*)d_in[0];
    const float* qkv_w  = (const float*)d_in[1];
    const float* qkv_b  = (const float*)d_in[2];
    const float* proj_w = (const float*)d_in[3];
    const float* proj_b = (const float*)d_in[4];
    float* out = (float*)d_out;

    const int M = B_SZ * NTOK;

    cudaFuncSetAttribute(mma_attn, cudaFuncAttributeMaxDynamicSharedMemorySize, 98304);
    cudaFuncSetAttribute(blk_gemm<0>, cudaFuncAttributeMaxDynamicSharedMemorySize, 98304);
    cudaFuncSetAttribute(blk_gemm<1>, cudaFuncAttributeMaxDynamicSharedMemorySize, 98304);

    __half *xh, *xl, *qwh, *pwh, *zh, *zl;
    cudaGetSymbolAddress((void**)&xh,  g_xh);
    cudaGetSymbolAddress((void**)&xl,  g_xl);
    cudaGetSymbolAddress((void**)&qwh, g_qwh);
    cudaGetSymbolAddress((void**)&pwh, g_pwh);
    cudaGetSymbolAddress((void**)&zh,  g_zh);
    cudaGetSymbolAddress((void**)&zl,  g_zl);

    dim3 blk(256);

    // 0) pre-split x (hi/lo) and round weights to fp16 tiled blocks
    split_tiled<<<(int)(MK / 4 / 256), blk>>>(x, xh, xl, (int)(MK / 4));
    round_tiled<<<(int)(QKV_W_N / 4 / 256), blk>>>(qkv_w, qwh, (int)(QKV_W_N / 4));
    round_tiled<<<(int)(PROJ_W_N / 4 / 256), blk>>>(proj_w, pwh, (int)(PROJ_W_N / 4));

    // 1) QKV GEMM (fp16 2-chain) -> q/k/v fp16 hi/lo swizzled chunks
    blk_gemm<0><<<dim3(3 * DMODEL / 128, M / 128), blk, 98304>>>(
        xh, xl, qwh, qkv_b, nullptr, 3 * DMODEL);

    // 2) Flash attention (fp16 3-chain) -> z tiled/swizzled hi/lo
    mma_attn<<<dim3(NTOK / 128, B_SZ * NHEAD), blk, 98304>>>();

    // 3) Output projection (fp16 2-chain) -> out fp32
    blk_gemm<1><<<dim3(DMODEL / 128, M / 128), blk, 98304>>>(
        zh, zl, pwh, proj_b, out, DMODEL);
}

// round 9
// speedup vs baseline: 6.8719x; 1.2153x over previous
#include <cuda_runtime.h>
#include <cuda_fp16.h>
#include <math.h>
#include <stdint.h>
#include <stddef.h>

#define B_SZ   8
#define NTOK   1024
#define NHEAD  16
#define DHEAD  64
#define DMODEL 1024
#define SCALE  0.125f

#define MK ((size_t)B_SZ * NTOK * DMODEL)
#define QKV_W_N ((size_t)3 * DMODEL * DMODEL)
#define PROJ_W_N ((size_t)DMODEL * DMODEL)
#define HSZ ((size_t)B_SZ * NHEAD * NTOK * DHEAD)

// All operands pre-tiled into 128-row x 64-k SW128-swizzled 16KB blocks.
__device__ __align__(1024) __half g_xh[MK],  g_xl[MK];
__device__ __align__(1024) __half g_qwh[QKV_W_N];          // weights: rounded only
__device__ __align__(1024) __half g_pwh[PROJ_W_N];
__device__ __align__(1024) __half g_zh[MK],  g_zl[MK];
// q: hi/lo; k, v: hi only (single fp16). Per (b,h): 8 chunks 128tok x 64d.
__device__ __align__(1024) __half g_qh[HSZ], g_ql[HSZ];
__device__ __align__(1024) __half g_kh[HSZ];
__device__ __align__(1024) __half g_vh[HSZ];

// ---------------------------------------------------------------------------
// helpers
// ---------------------------------------------------------------------------
__device__ __forceinline__ uint32_t smem_u32(const void* p) {
    return (uint32_t)__cvta_generic_to_shared(p);
}
__device__ __forceinline__ uint32_t swz128(uint32_t b) {   // Swizzle<3,4,3>
    return b ^ ((b >> 3) & 0x70);
}
__device__ __forceinline__ void bulkcp(uint32_t dst, const void* src, uint32_t bytes,
                                       uint32_t mbar) {
    asm volatile(
        "cp.async.bulk.shared::cta.global.mbarrier::complete_tx::bytes [%0], [%1], %2, [%3];"
        :: "r"(dst), "l"(src), "r"(bytes), "r"(mbar) : "memory");
}
__device__ __forceinline__ void mbar_init(uint32_t mbar, uint32_t cnt) {
    asm volatile("mbarrier.init.shared.b64 [%0], %1;" :: "r"(mbar), "r"(cnt) : "memory");
}
__device__ __forceinline__ void mbar_expect_tx(uint32_t mbar, uint32_t bytes) {
    asm volatile("mbarrier.arrive.expect_tx.shared.b64 _, [%0], %1;"
                 :: "r"(mbar), "r"(bytes) : "memory");
}
__device__ __forceinline__ void mbar_wait(uint32_t mbar, uint32_t phase) {
    asm volatile(
        "{\n\t.reg .pred P;\n\t"
        "W_%=:\n\t"
        "mbarrier.try_wait.parity.acquire.cta.shared::cta.b64 P, [%0], %1, 0x989680;\n\t"
        "@P bra D_%=;\n\t"
        "bra W_%=;\n\t"
        "D_%=:\n\t}"
        :: "r"(mbar), "r"(phase) : "memory");
}
__device__ __forceinline__ void ldsm4(uint32_t& r0, uint32_t& r1, uint32_t& r2, uint32_t& r3,
                                      uint32_t a) {
    asm volatile("ldmatrix.sync.aligned.m8n8.x4.shared.b16 {%0,%1,%2,%3}, [%4];"
                 : "=r"(r0), "=r"(r1), "=r"(r2), "=r"(r3) : "r"(a));
}
__device__ __forceinline__ void ldsm4t(uint32_t& r0, uint32_t& r1, uint32_t& r2, uint32_t& r3,
                                       uint32_t a) {
    asm volatile("ldmatrix.sync.aligned.m8n8.x4.trans.shared.b16 {%0,%1,%2,%3}, [%4];"
                 : "=r"(r0), "=r"(r1), "=r"(r2), "=r"(r3) : "r"(a));
}
__device__ __forceinline__ void mma16816(float* c,
                                         uint32_t a0, uint32_t a1, uint32_t a2, uint32_t a3,
                                         uint32_t b0, uint32_t b1) {
    asm volatile(
        "mma.sync.aligned.m16n8k16.row.col.f32.f16.f16.f32 "
        "{%0,%1,%2,%3},{%4,%5,%6,%7},{%8,%9},{%0,%1,%2,%3};"
        : "+f"(c[0]), "+f"(c[1]), "+f"(c[2]), "+f"(c[3])
        : "r"(a0), "r"(a1), "r"(a2), "r"(a3), "r"(b0), "r"(b1));
}
__device__ __forceinline__ void splitpack(float a, float b, uint32_t& hi, uint32_t& lo) {
    __half2 h = __floats2half2_rn(a, b);
    float2 hf = __half22float2(h);
    __half2 l = __floats2half2_rn(a - hf.x, b - hf.y);
    hi = *reinterpret_cast<uint32_t*>(&h);
    lo = *reinterpret_cast<uint32_t*>(&l);
}
__device__ __forceinline__ void split4(float4 v, __half* hp, __half* lp) {
    __half2 h01 = __floats2half2_rn(v.x, v.y);
    __half2 h23 = __floats2half2_rn(v.z, v.w);
    float2 f01 = __half22float2(h01);
    float2 f23 = __half22float2(h23);
    __half2 l01 = __floats2half2_rn(v.x - f01.x, v.y - f01.y);
    __half2 l23 = __floats2half2_rn(v.z - f23.x, v.w - f23.y);
    *reinterpret_cast<__half2*>(hp)     = h01;
    *reinterpret_cast<__half2*>(hp + 2) = h23;
    *reinterpret_cast<__half2*>(lp)     = l01;
    *reinterpret_cast<__half2*>(lp + 2) = l23;
}
__device__ __forceinline__ float redmax4(float v) {
    v = fmaxf(v, __shfl_xor_sync(0xffffffffu, v, 1));
    v = fmaxf(v, __shfl_xor_sync(0xffffffffu, v, 2));
    return v;
}
__device__ __forceinline__ float redsum4(float v) {
    v += __shfl_xor_sync(0xffffffffu, v, 1);
    v += __shfl_xor_sync(0xffffffffu, v, 2);
    return v;
}

// ---------------------------------------------------------------------------
// fp32 -> fp16 hi/lo split into tiled+swizzled 128x64 blocks (K = 1024).
// ---------------------------------------------------------------------------
__global__ __launch_bounds__(256) void split_tiled(const float* __restrict__ src,
                                                   __half* __restrict__ hi,
                                                   __half* __restrict__ lo,
                                                   int n4)
{
    int i = blockIdx.x * blockDim.x + threadIdx.x;
    if (i >= n4) return;
    float4 v = reinterpret_cast<const float4*>(src)[i];
    int row = i >> 8;
    int k4  = i & 255;
    int kc  = k4 >> 4;
    int kk  = (k4 << 2) & 63;
    int rb  = row >> 7;
    int r   = row & 127;
    size_t base = ((size_t)rb * 16 + kc) * 16384;
    uint32_t sw = swz128((uint32_t)(r * 128 + kk * 2));
    split4(v, (__half*)((char*)hi + base + sw), (__half*)((char*)lo + base + sw));
}

// fp32 -> fp16 round-only (weights), same tiling
__global__ __launch_bounds__(256) void round_tiled(const float* __restrict__ src,
                                                   __half* __restrict__ hi,
                                                   int n4)
{
    int i = blockIdx.x * blockDim.x + threadIdx.x;
    if (i >= n4) return;
    float4 v = reinterpret_cast<const float4*>(src)[i];
    int row = i >> 8;
    int k4  = i & 255;
    int kc  = k4 >> 4;
    int kk  = (k4 << 2) & 63;
    int rb  = row >> 7;
    int r   = row & 127;
    size_t base = ((size_t)rb * 16 + kc) * 16384;
    uint32_t sw = swz128((uint32_t)(r * 128 + kk * 2));
    __half* hp = (__half*)((char*)hi + base + sw);
    *reinterpret_cast<__half2*>(hp)     = __floats2half2_rn(v.x, v.y);
    *reinterpret_cast<__half2*>(hp + 2) = __floats2half2_rn(v.z, v.w);
}

// ---------------------------------------------------------------------------
// fp16 2-chain GEMM (mma.sync): C = (Ah+Al) @ Wh^T + bias.
// CTA 128M x 128N, K-chunks of 64, 2-stage bulk pipeline, occupancy 2.
// EPI==0: q hi/lo, k/v hi-only swizzled chunks (q pre-scaled). EPI==1: fp32 out.
// ---------------------------------------------------------------------------
template <int EPI>
__global__ __launch_bounds__(256, 2) void blk_gemm(const __half* __restrict__ Ah,
                                                   const __half* __restrict__ Al,
                                                   const __half* __restrict__ Wh,
                                                   const float* __restrict__ bias,
                                                   float* __restrict__ out,
                                                   int N)
{
    __shared__ __align__(16) uint64_t mbar[2];
    extern __shared__ __align__(128) char dyn[];

    const int tid  = threadIdx.x;
    const int lane = tid & 31;
    const int warp = tid >> 5;
    const int wm   = warp >> 2;
    const int wn   = warp & 3;
    const int mb   = blockIdx.y;
    const int nb   = blockIdx.x;

    const uint32_t dynb = smem_u32(dyn);
    const uint32_t fullb[2] = {smem_u32(&mbar[0]), smem_u32(&mbar[1])};

    if (tid == 0) { mbar_init(fullb[0], 1); mbar_init(fullb[1], 1); }
    __syncthreads();

    const char* pAh = (const char*)Ah + (size_t)mb * 16 * 16384;
    const char* pAl = (const char*)Al + (size_t)mb * 16 * 16384;
    const char* pWh = (const char*)Wh + (size_t)nb * 16 * 16384;

    auto load_chunk = [&](int s, int c) {
        uint32_t st = dynb + (uint32_t)s * 49152u;
        uint32_t fb = fullb[s];
        mbar_expect_tx(fb, 49152u);
        bulkcp(st,          pAh + (size_t)c * 16384, 16384, fb);
        bulkcp(st + 16384u, pAl + (size_t)c * 16384, 16384, fb);
        bulkcp(st + 32768u, pWh + (size_t)c * 16384, 16384, fb);
    };

    if (tid == 0) { load_chunk(0, 0); load_chunk(1, 1); }

    float acc[4][4][4] = {};

    const int a_row  = wm * 64 + (lane & 15);
    const int a_koff = (lane >> 4) << 3;
    const int b_n    = wn * 32 + (lane & 7) + ((lane >> 4) << 3);
    const int b_koff = ((lane >> 3) & 1) << 3;

    int fph[2] = {0, 0};

    for (int c = 0; c < 16; c++) {
        int s = c & 1;
        mbar_wait(fullb[s], fph[s]); fph[s] ^= 1;
        uint32_t stb = dynb + (uint32_t)s * 49152u;

        #pragma unroll
        for (int ks = 0; ks < 64; ks += 16) {
            uint32_t bh[4][2];
            #pragma unroll
            for (int p = 0; p < 2; p++) {
                uint32_t sw = swz128((uint32_t)((b_n + p * 16) * 128 + (ks + b_koff) * 2));
                uint32_t r0, r1, r2, r3;
                ldsm4(r0, r1, r2, r3, stb + 32768u + sw);
                bh[2 * p][0] = r0; bh[2 * p][1] = r1;
                bh[2 * p + 1][0] = r2; bh[2 * p + 1][1] = r3;
            }
            #pragma unroll
            for (int mt = 0; mt < 4; mt++) {
                uint32_t sw = swz128((uint32_t)((a_row + mt * 16) * 128 + (ks + a_koff) * 2));
                uint32_t a0, a1, a2, a3, l0, l1, l2, l3;
                ldsm4(a0, a1, a2, a3, stb + sw);
                ldsm4(l0, l1, l2, l3, stb + 16384u + sw);
                #pragma unroll
                for (int nt = 0; nt < 4; nt++) {
                    mma16816(acc[mt][nt], a0, a1, a2, a3, bh[nt][0], bh[nt][1]);
                    mma16816(acc[mt][nt], l0, l1, l2, l3, bh[nt][0], bh[nt][1]);
                }
            }
        }
        __syncthreads();
        if (c + 2 < 16 && tid == 0) load_chunk(s, c + 2);
    }

    // epilogue
    const int row0 = mb * 128;
    const int col0 = nb * 128;
    const int r    = lane >> 2;
    const int cq   = (lane & 3) * 2;
    #pragma unroll
    for (int mt = 0; mt < 4; mt++) {
        int m0 = row0 + wm * 64 + mt * 16 + r;
        #pragma unroll
        for (int nt = 0; nt < 4; nt++) {
            int n = col0 + wn * 32 + nt * 8 + cq;
            float b0 = bias[n], b1 = bias[n + 1];
            float v00 = acc[mt][nt][0] + b0, v01 = acc[mt][nt][1] + b1;
            float v10 = acc[mt][nt][2] + b0, v11 = acc[mt][nt][3] + b1;
            if (EPI == 0) {
                #pragma unroll
                for (int e = 0; e < 4; e++) {
                    int m = m0 + (e >> 1) * 8;
                    int cc = n + (e & 1);
                    float val = (e == 0) ? v00 : (e == 1) ? v01 : (e == 2) ? v10 : v11;
                    int b    = m >> 10, t = m & 1023;
                    int part = cc >> 10, hc = cc & 1023;
                    int h = hc >> 6, hd = hc & 63;
                    size_t cbase = ((size_t)((b * NHEAD + h) * 8 + (t >> 7))) * 16384;
                    uint32_t sw = swz128((uint32_t)(((t & 127) << 7) + hd * 2));
                    if (part == 0) {
                        val *= SCALE;
                        __half hi = __float2half_rn(val);
                        __half lo = __float2half_rn(val - __half2float(hi));
                        *(__half*)((char*)g_qh + cbase + sw) = hi;
                        *(__half*)((char*)g_ql + cbase + sw) = lo;
                    } else if (part == 1) {
                        *(__half*)((char*)g_kh + cbase + sw) = __float2half_rn(val);
                    } else {
                        *(__half*)((char*)g_vh + cbase + sw) = __float2half_rn(val);
                    }
                }
            } else {
                *(float2*)&out[(size_t)m0 * N + n]       = make_float2(v00, v01);
                *(float2*)&out[(size_t)(m0 + 8) * N + n] = make_float2(v10, v11);
            }
        }
    }
}

// ---------------------------------------------------------------------------
// fp16 flash attention: Q hi/lo (2-chain QK), K/V single fp16, P hi/lo
// (2-chain PV). 128-key tiles, occupancy 2.
// smem: Qh@0 Ql@16384 | stages @32768 + s*32768: Kh(16KB)|Vh(16KB).
// Total 98304 B. 8 KV tiles of 128 keys.
// ---------------------------------------------------------------------------
__global__ __launch_bounds__(256, 2) void mma_attn()
{
    __shared__ __align__(16) uint64_t abar[3];
    extern __shared__ __align__(128) char dyn[];

    const int qb = blockIdx.x;
    const int bh = blockIdx.y;
    const int tid  = threadIdx.x;
    const int lane = tid & 31;
    const int w    = tid >> 5;

    const uint32_t dynb = smem_u32(dyn);
    const uint32_t qbar = smem_u32(&abar[0]);
    const uint32_t fullb[2] = {smem_u32(&abar[1]), smem_u32(&abar[2])};

    if (tid == 0) {
        mbar_init(qbar, 1);
        mbar_init(fullb[0], 1);
        mbar_init(fullb[1], 1);
    }
    __syncthreads();

    const size_t hbase = (size_t)bh * 8;

    auto load_kv = [&](int s, int t) {
        uint32_t st = dynb + 32768u + (uint32_t)s * 32768u;
        uint32_t fb = fullb[s];
        size_t cb = (hbase + t) * 16384;
        mbar_expect_tx(fb, 32768u);
        bulkcp(st,          (char*)g_kh + cb, 16384, fb);
        bulkcp(st + 16384u, (char*)g_vh + cb, 16384, fb);
    };

    if (tid == 0) {
        size_t qcb = (hbase + qb) * 16384;
        mbar_expect_tx(qbar, 32768u);
        bulkcp(dynb,          (char*)g_qh + qcb, 16384, qbar);
        bulkcp(dynb + 16384u, (char*)g_ql + qcb, 16384, qbar);
        load_kv(0, 0);
        load_kv(1, 1);
    }

    const int k_nloc = (lane & 7) + ((lane >> 4) << 3);
    const int k_koff = ((lane >> 3) & 1) << 3;
    const int v_krl  = (lane & 7) + (((lane >> 3) & 1) << 3);
    const int v_dc   = (lane >> 4) << 3;
    const int qrow   = w * 16 + (lane & 15);
    const int qoff   = (lane >> 4) << 3;

    float O[8][4] = {};
    float rm0 = -INFINITY, rm1 = -INFINITY, rl0 = 0.f, rl1 = 0.f;
    int fph[2] = {0, 0};

    mbar_wait(qbar, 0);

    for (int t = 0; t < 8; t++) {
        int s = t & 1;
        mbar_wait(fullb[s], fph[s]); fph[s] ^= 1;
        uint32_t stb = dynb + 32768u + (uint32_t)s * 32768u;

        // ---- S = Q K^T (2 chains: qh + ql, K single) ----
        float sa[16][4] = {};
        #pragma unroll
        for (int kk = 0; kk < 4; kk++) {
            uint32_t qsw = swz128((uint32_t)(qrow * 128 + (kk * 16 + qoff) * 2));
            uint32_t q0, q1, q2, q3, l0, l1, l2, l3;
            ldsm4(q0, q1, q2, q3, dynb + qsw);
            ldsm4(l0, l1, l2, l3, dynb + 16384u + qsw);
            #pragma unroll
            for (int p = 0; p < 8; p++) {
                uint32_t sw = swz128((uint32_t)((k_nloc + p * 16) * 128 + (kk * 16 + k_koff) * 2));
                uint32_t r0, r1, r2, r3;
                ldsm4(r0, r1, r2, r3, stb + sw);
                mma16816(sa[2 * p],     q0, q1, q2, q3, r0, r1);
                mma16816(sa[2 * p],     l0, l1, l2, l3, r0, r1);
                mma16816(sa[2 * p + 1], q0, q1, q2, q3, r2, r3);
                mma16816(sa[2 * p + 1], l0, l1, l2, l3, r2, r3);
            }
        }

        // ---- online softmax (warp-local) ----
        float mx0 = -INFINITY, mx1 = -INFINITY;
        #pragma unroll
        for (int j = 0; j < 16; j++) {
            mx0 = fmaxf(mx0, fmaxf(sa[j][0], sa[j][1]));
            mx1 = fmaxf(mx1, fmaxf(sa[j][2], sa[j][3]));
        }
        mx0 = redmax4(mx0); mx1 = redmax4(mx1);
        float nm0 = fmaxf(rm0, mx0), nm1 = fmaxf(rm1, mx1);
        float al0 = __expf(rm0 - nm0), al1 = __expf(rm1 - nm1);
        rm0 = nm0; rm1 = nm1;
        float sm0 = 0.f, sm1 = 0.f;
        #pragma unroll
        for (int j = 0; j < 16; j++) {
            sa[j][0] = __expf(sa[j][0] - nm0);
            sa[j][1] = __expf(sa[j][1] - nm0);
            sa[j][2] = __expf(sa[j][2] - nm1);
            sa[j][3] = __expf(sa[j][3] - nm1);
            sm0 += sa[j][0] + sa[j][1];
            sm1 += sa[j][2] + sa[j][3];
        }
        sm0 = redsum4(sm0); sm1 = redsum4(sm1);
        rl0 = rl0 * al0 + sm0;
        rl1 = rl1 * al1 + sm1;
        #pragma unroll
        for (int nt = 0; nt < 8; nt++) {
            O[nt][0] *= al0; O[nt][1] *= al0;
            O[nt][2] *= al1; O[nt][3] *= al1;
        }

        // ---- O += P V (2 chains: ph + pl, V single) ----
        #pragma unroll
        for (int kk = 0; kk < 8; kk++) {
            uint32_t ph[4], pl[4];
            splitpack(sa[2 * kk][0],     sa[2 * kk][1],     ph[0], pl[0]);
            splitpack(sa[2 * kk][2],     sa[2 * kk][3],     ph[1], pl[1]);
            splitpack(sa[2 * kk + 1][0], sa[2 * kk + 1][1], ph[2], pl[2]);
            splitpack(sa[2 * kk + 1][2], sa[2 * kk + 1][3], ph[3], pl[3]);
            #pragma unroll
            for (int pd = 0; pd < 4; pd++) {
                uint32_t sw = swz128((uint32_t)((v_krl + kk * 16) * 128 + (pd * 16 + v_dc) * 2));
                uint32_t v0, v1, v2, v3;
                ldsm4t(v0, v1, v2, v3, stb + 16384u + sw);
                mma16816(O[2 * pd],     ph[0], ph[1], ph[2], ph[3], v0, v1);
                mma16816(O[2 * pd],     pl[0], pl[1], pl[2], pl[3], v0, v1);
                mma16816(O[2 * pd + 1], ph[0], ph[1], ph[2], ph[3], v2, v3);
                mma16816(O[2 * pd + 1], pl[0], pl[1], pl[2], pl[3], v2, v3);
            }
        }
        __syncthreads();
        if (t + 2 < 8 && tid == 0) load_kv(s, t + 2);
    }

    // normalize; write z into tiled/swizzled proj A-blocks (fp16 hi/lo).
    float inv0 = 1.0f / rl0, inv1 = 1.0f / rl1;
    const int b = bh >> 4, h = bh & 15;
    const int t0 = qb * 128 + w * 16 + (lane >> 2);
    const int cq = (lane & 3) * 2;
    #pragma unroll
    for (int nt = 0; nt < 8; nt++) {
        int kk = nt * 8 + cq;
        #pragma unroll
        for (int e = 0; e < 2; e++) {
            int m = b * NTOK + t0 + e * 8;
            int mb2 = m >> 7, r = m & 127;
            size_t base = ((size_t)mb2 * 16 + h) * 16384;
            uint32_t sw = swz128((uint32_t)(r * 128 + kk * 2));
            uint32_t zh, zl;
            splitpack(O[nt][2 * e] * (e ? inv1 : inv0),
                      O[nt][2 * e + 1] * (e ? inv1 : inv0), zh, zl);
            *(uint32_t*)((char*)g_zh + base + sw) = zh;
            *(uint32_t*)((char*)g_zl + base + sw) = zl;
        }
    }
}

// ---------------------------------------------------------------------------
extern "C" void kernel_launch(void* const* d_in, const int* in_sizes, int n_in,
                              void* d_out, int out_size)
{
    const float* x      = (const float*)d_in[0];
    const float* qkv_w  = (const float*)d_in[1];
    const float* qkv_b  = (const float*)d_in[2];
    const float* proj_w = (const float*)d_in[3];
    const float* proj_b = (const float*)d_in[4];
    float* out = (float*)d_out;

    const int M = B_SZ * NTOK;

    cudaFuncSetAttribute(mma_attn, cudaFuncAttributeMaxDynamicSharedMemorySize, 98304);
    cudaFuncSetAttribute(blk_gemm<0>, cudaFuncAttributeMaxDynamicSharedMemorySize, 98304);
    cudaFuncSetAttribute(blk_gemm<1>, cudaFuncAttributeMaxDynamicSharedMemorySize, 98304);

    __half *xh, *xl, *qwh, *pwh, *zh, *zl;
    cudaGetSymbolAddress((void**)&xh,  g_xh);
    cudaGetSymbolAddress((void**)&xl,  g_xl);
    cudaGetSymbolAddress((void**)&qwh, g_qwh);
    cudaGetSymbolAddress((void**)&pwh, g_pwh);
    cudaGetSymbolAddress((void**)&zh,  g_zh);
    cudaGetSymbolAddress((void**)&zl,  g_zl);

    dim3 blk(256);

    // 0) pre-split x (hi/lo) and round weights to fp16 tiled blocks
    split_tiled<<<(int)(MK / 4 / 256), blk>>>(x, xh, xl, (int)(MK / 4));
    round_tiled<<<(int)(QKV_W_N / 4 / 256), blk>>>(qkv_w, qwh, (int)(QKV_W_N / 4));
    round_tiled<<<(int)(PROJ_W_N / 4 / 256), blk>>>(proj_w, pwh, (int)(PROJ_W_N / 4));

    // 1) QKV GEMM (fp16 2-chain) -> q hi/lo, k/v single fp16
    blk_gemm<0><<<dim3(3 * DMODEL / 128, M / 128), blk, 98304>>>(
        xh, xl, qwh, qkv_b, nullptr, 3 * DMODEL);

    // 2) Flash attention (2-chain QK, 2-chain PV) -> z tiled/swizzled hi/lo
    mma_attn<<<dim3(NTOK / 128, B_SZ * NHEAD), blk, 98304>>>();

    // 3) Output projection (fp16 2-chain) -> out fp32
    blk_gemm<1><<<dim3(DMODEL / 128, M / 128), blk, 98304>>>(
        zh, zl, pwh, proj_b, out, DMODEL);
}

// round 10
// speedup vs baseline: 7.4208x; 1.0799x over previous
#include <cuda_runtime.h>
#include <cuda_fp16.h>
#include <math.h>
#include <stdint.h>
#include <stddef.h>

#define B_SZ   8
#define NTOK   1024
#define NHEAD  16
#define DHEAD  64
#define DMODEL 1024
#define SCALE  0.125f

#define MK ((size_t)B_SZ * NTOK * DMODEL)
#define QKV_W_N ((size_t)3 * DMODEL * DMODEL)
#define PROJ_W_N ((size_t)DMODEL * DMODEL)
#define HSZ ((size_t)B_SZ * NHEAD * NTOK * DHEAD)

// All operands pre-tiled into 128-row x 64-k SW128-swizzled 16KB blocks.
__device__ __align__(1024) __half g_xh[MK],  g_xl[MK];
__device__ __align__(1024) __half g_qwh[QKV_W_N];          // weights: rounded only
__device__ __align__(1024) __half g_pwh[PROJ_W_N];
__device__ __align__(1024) __half g_zh[MK],  g_zl[MK];
// q: hi/lo; k, v: hi only. Per (b,h): 8 chunks 128tok x 64d, swizzled.
__device__ __align__(1024) __half g_qh[HSZ], g_ql[HSZ];
__device__ __align__(1024) __half g_kh[HSZ];
__device__ __align__(1024) __half g_vh[HSZ];

// ---------------------------------------------------------------------------
// helpers
// ---------------------------------------------------------------------------
__device__ __forceinline__ uint32_t smem_u32(const void* p) {
    return (uint32_t)__cvta_generic_to_shared(p);
}
__device__ __forceinline__ uint32_t swz128(uint32_t b) {   // Swizzle<3,4,3>
    return b ^ ((b >> 3) & 0x70);
}
__device__ __forceinline__ void bulkcp(uint32_t dst, const void* src, uint32_t bytes,
                                       uint32_t mbar) {
    asm volatile(
        "cp.async.bulk.shared::cta.global.mbarrier::complete_tx::bytes [%0], [%1], %2, [%3];"
        :: "r"(dst), "l"(src), "r"(bytes), "r"(mbar) : "memory");
}
__device__ __forceinline__ void mbar_init(uint32_t mbar, uint32_t cnt) {
    asm volatile("mbarrier.init.shared.b64 [%0], %1;" :: "r"(mbar), "r"(cnt) : "memory");
}
__device__ __forceinline__ void mbar_expect_tx(uint32_t mbar, uint32_t bytes) {
    asm volatile("mbarrier.arrive.expect_tx.shared.b64 _, [%0], %1;"
                 :: "r"(mbar), "r"(bytes) : "memory");
}
__device__ __forceinline__ void mbar_wait(uint32_t mbar, uint32_t phase) {
    asm volatile(
        "{\n\t.reg .pred P;\n\t"
        "W_%=:\n\t"
        "mbarrier.try_wait.parity.acquire.cta.shared::cta.b64 P, [%0], %1, 0x989680;\n\t"
        "@P bra D_%=;\n\t"
        "bra W_%=;\n\t"
        "D_%=:\n\t}"
        :: "r"(mbar), "r"(phase) : "memory");
}
__device__ __forceinline__ void ldsm4(uint32_t& r0, uint32_t& r1, uint32_t& r2, uint32_t& r3,
                                      uint32_t a) {
    asm volatile("ldmatrix.sync.aligned.m8n8.x4.shared.b16 {%0,%1,%2,%3}, [%4];"
                 : "=r"(r0), "=r"(r1), "=r"(r2), "=r"(r3) : "r"(a));
}
__device__ __forceinline__ void ldsm4t(uint32_t& r0, uint32_t& r1, uint32_t& r2, uint32_t& r3,
                                       uint32_t a) {
    asm volatile("ldmatrix.sync.aligned.m8n8.x4.trans.shared.b16 {%0,%1,%2,%3}, [%4];"
                 : "=r"(r0), "=r"(r1), "=r"(r2), "=r"(r3) : "r"(a));
}
__device__ __forceinline__ void mma16816(float* c,
                                         uint32_t a0, uint32_t a1, uint32_t a2, uint32_t a3,
                                         uint32_t b0, uint32_t b1) {
    asm volatile(
        "mma.sync.aligned.m16n8k16.row.col.f32.f16.f16.f32 "
        "{%0,%1,%2,%3},{%4,%5,%6,%7},{%8,%9},{%0,%1,%2,%3};"
        : "+f"(c[0]), "+f"(c[1]), "+f"(c[2]), "+f"(c[3])
        : "r"(a0), "r"(a1), "r"(a2), "r"(a3), "r"(b0), "r"(b1));
}
__device__ __forceinline__ void splitpack(float a, float b, uint32_t& hi, uint32_t& lo) {
    __half2 h = __floats2half2_rn(a, b);
    float2 hf = __half22float2(h);
    __half2 l = __floats2half2_rn(a - hf.x, b - hf.y);
    hi = *reinterpret_cast<uint32_t*>(&h);
    lo = *reinterpret_cast<uint32_t*>(&l);
}
__device__ __forceinline__ void split4(float4 v, __half* hp, __half* lp) {
    __half2 h01 = __floats2half2_rn(v.x, v.y);
    __half2 h23 = __floats2half2_rn(v.z, v.w);
    float2 f01 = __half22float2(h01);
    float2 f23 = __half22float2(h23);
    __half2 l01 = __floats2half2_rn(v.x - f01.x, v.y - f01.y);
    __half2 l23 = __floats2half2_rn(v.z - f23.x, v.w - f23.y);
    *reinterpret_cast<__half2*>(hp)     = h01;
    *reinterpret_cast<__half2*>(hp + 2) = h23;
    *reinterpret_cast<__half2*>(lp)     = l01;
    *reinterpret_cast<__half2*>(lp + 2) = l23;
}
__device__ __forceinline__ float redmax4(float v) {
    v = fmaxf(v, __shfl_xor_sync(0xffffffffu, v, 1));
    v = fmaxf(v, __shfl_xor_sync(0xffffffffu, v, 2));
    return v;
}
__device__ __forceinline__ float redsum4(float v) {
    v += __shfl_xor_sync(0xffffffffu, v, 1);
    v += __shfl_xor_sync(0xffffffffu, v, 2);
    return v;
}

// ---------------------------------------------------------------------------
// fp32 -> fp16 hi/lo split into tiled+swizzled 128x64 blocks (K = 1024).
// ---------------------------------------------------------------------------
__global__ __launch_bounds__(256) void split_tiled(const float* __restrict__ src,
                                                   __half* __restrict__ hi,
                                                   __half* __restrict__ lo,
                                                   int n4)
{
    int i = blockIdx.x * blockDim.x + threadIdx.x;
    if (i >= n4) return;
    float4 v = reinterpret_cast<const float4*>(src)[i];
    int row = i >> 8;
    int k4  = i & 255;
    int kc  = k4 >> 4;
    int kk  = (k4 << 2) & 63;
    int rb  = row >> 7;
    int r   = row & 127;
    size_t base = ((size_t)rb * 16 + kc) * 16384;
    uint32_t sw = swz128((uint32_t)(r * 128 + kk * 2));
    split4(v, (__half*)((char*)hi + base + sw), (__half*)((char*)lo + base + sw));
}

// fp32 -> fp16 round-only (weights), same tiling
__global__ __launch_bounds__(256) void round_tiled(const float* __restrict__ src,
                                                   __half* __restrict__ hi,
                                                   int n4)
{
    int i = blockIdx.x * blockDim.x + threadIdx.x;
    if (i >= n4) return;
    float4 v = reinterpret_cast<const float4*>(src)[i];
    int row = i >> 8;
    int k4  = i & 255;
    int kc  = k4 >> 4;
    int kk  = (k4 << 2) & 63;
    int rb  = row >> 7;
    int r   = row & 127;
    size_t base = ((size_t)rb * 16 + kc) * 16384;
    uint32_t sw = swz128((uint32_t)(r * 128 + kk * 2));
    __half* hp = (__half*)((char*)hi + base + sw);
    *reinterpret_cast<__half2*>(hp)     = __floats2half2_rn(v.x, v.y);
    *reinterpret_cast<__half2*>(hp + 2) = __floats2half2_rn(v.z, v.w);
}

// ---------------------------------------------------------------------------
// fp16 GEMM (mma.sync), CHAINS in {1,2}: C = (Ah [+ Al]) @ Wh^T + bias.
// CTA 128M x 128N, K-chunks of 64, 2-stage bulk pipeline, occupancy 2.
// Stage = Ah16|[Al16]|Wh16. col_base: global column offset of this launch.
// EPI==0: scatter q hi/lo, k/v hi-only swizzled chunks (q pre-scaled).
// EPI==1: fp32 out (full row width N = DMODEL).
// ---------------------------------------------------------------------------
template <int EPI, int CHAINS>
__global__ __launch_bounds__(256, 2) void blk_gemm(const __half* __restrict__ Ah,
                                                   const __half* __restrict__ Al,
                                                   const __half* __restrict__ Wh,
                                                   const float* __restrict__ bias,
                                                   float* __restrict__ out,
                                                   int col_base)
{
    constexpr uint32_t W_OFF = 16384u * CHAINS;           // Wh offset in stage
    constexpr uint32_t STAGE = 16384u * (CHAINS + 1);     // stage bytes

    __shared__ __align__(16) uint64_t mbar[2];
    extern __shared__ __align__(128) char dyn[];

    const int tid  = threadIdx.x;
    const int lane = tid & 31;
    const int warp = tid >> 5;
    const int wm   = warp >> 2;
    const int wn   = warp & 3;
    const int mb   = blockIdx.y;
    const int nb   = blockIdx.x;

    const uint32_t dynb = smem_u32(dyn);
    const uint32_t fullb[2] = {smem_u32(&mbar[0]), smem_u32(&mbar[1])};

    if (tid == 0) { mbar_init(fullb[0], 1); mbar_init(fullb[1], 1); }
    __syncthreads();

    const char* pAh = (const char*)Ah + (size_t)mb * 16 * 16384;
    const char* pAl = (const char*)Al + (size_t)mb * 16 * 16384;
    const char* pWh = (const char*)Wh + (size_t)nb * 16 * 16384;

    auto load_chunk = [&](int s, int c) {
        uint32_t st = dynb + (uint32_t)s * STAGE;
        uint32_t fb = fullb[s];
        mbar_expect_tx(fb, STAGE);
        bulkcp(st, pAh + (size_t)c * 16384, 16384, fb);
        if (CHAINS == 2)
            bulkcp(st + 16384u, pAl + (size_t)c * 16384, 16384, fb);
        bulkcp(st + W_OFF, pWh + (size_t)c * 16384, 16384, fb);
    };

    if (tid == 0) { load_chunk(0, 0); load_chunk(1, 1); }

    float acc[4][4][4] = {};

    const int a_row  = wm * 64 + (lane & 15);
    const int a_koff = (lane >> 4) << 3;
    const int b_n    = wn * 32 + (lane & 7) + ((lane >> 4) << 3);
    const int b_koff = ((lane >> 3) & 1) << 3;

    int fph[2] = {0, 0};

    for (int c = 0; c < 16; c++) {
        int s = c & 1;
        mbar_wait(fullb[s], fph[s]); fph[s] ^= 1;
        uint32_t stb = dynb + (uint32_t)s * STAGE;

        #pragma unroll
        for (int ks = 0; ks < 64; ks += 16) {
            uint32_t bh[4][2];
            #pragma unroll
            for (int p = 0; p < 2; p++) {
                uint32_t sw = swz128((uint32_t)((b_n + p * 16) * 128 + (ks + b_koff) * 2));
                uint32_t r0, r1, r2, r3;
                ldsm4(r0, r1, r2, r3, stb + W_OFF + sw);
                bh[2 * p][0] = r0; bh[2 * p][1] = r1;
                bh[2 * p + 1][0] = r2; bh[2 * p + 1][1] = r3;
            }
            #pragma unroll
            for (int mt = 0; mt < 4; mt++) {
                uint32_t sw = swz128((uint32_t)((a_row + mt * 16) * 128 + (ks + a_koff) * 2));
                uint32_t a0, a1, a2, a3;
                ldsm4(a0, a1, a2, a3, stb + sw);
                uint32_t l0, l1, l2, l3;
                if (CHAINS == 2) ldsm4(l0, l1, l2, l3, stb + 16384u + sw);
                #pragma unroll
                for (int nt = 0; nt < 4; nt++) {
                    mma16816(acc[mt][nt], a0, a1, a2, a3, bh[nt][0], bh[nt][1]);
                    if (CHAINS == 2)
                        mma16816(acc[mt][nt], l0, l1, l2, l3, bh[nt][0], bh[nt][1]);
                }
            }
        }
        __syncthreads();
        if (c + 2 < 16 && tid == 0) load_chunk(s, c + 2);
    }

    // epilogue
    const int row0 = mb * 128;
    const int col0 = col_base + nb * 128;
    const int r    = lane >> 2;
    const int cq   = (lane & 3) * 2;
    #pragma unroll
    for (int mt = 0; mt < 4; mt++) {
        int m0 = row0 + wm * 64 + mt * 16 + r;
        #pragma unroll
        for (int nt = 0; nt < 4; nt++) {
            int n = col0 + wn * 32 + nt * 8 + cq;
            float b0 = bias[n], b1 = bias[n + 1];
            float v00 = acc[mt][nt][0] + b0, v01 = acc[mt][nt][1] + b1;
            float v10 = acc[mt][nt][2] + b0, v11 = acc[mt][nt][3] + b1;
            if (EPI == 0) {
                #pragma unroll
                for (int e = 0; e < 4; e++) {
                    int m = m0 + (e >> 1) * 8;
                    int cc = n + (e & 1);
                    float val = (e == 0) ? v00 : (e == 1) ? v01 : (e == 2) ? v10 : v11;
                    int b    = m >> 10, t = m & 1023;
                    int part = cc >> 10, hc = cc & 1023;
                    int h = hc >> 6, hd = hc & 63;
                    size_t cbase = ((size_t)((b * NHEAD + h) * 8 + (t >> 7))) * 16384;
                    uint32_t sw = swz128((uint32_t)(((t & 127) << 7) + hd * 2));
                    if (part == 0) {
                        val *= SCALE;
                        __half hi = __float2half_rn(val);
                        __half lo = __float2half_rn(val - __half2float(hi));
                        *(__half*)((char*)g_qh + cbase + sw) = hi;
                        *(__half*)((char*)g_ql + cbase + sw) = lo;
                    } else if (part == 1) {
                        *(__half*)((char*)g_kh + cbase + sw) = __float2half_rn(val);
                    } else {
                        *(__half*)((char*)g_vh + cbase + sw) = __float2half_rn(val);
                    }
                }
            } else {
                *(float2*)&out[(size_t)m0 * DMODEL + n]       = make_float2(v00, v01);
                *(float2*)&out[(size_t)(m0 + 8) * DMODEL + n] = make_float2(v10, v11);
            }
        }
    }
}

// ---------------------------------------------------------------------------
// fp16 flash attention: Q hi/lo (2-chain QK), K/V single fp16, P hi/lo
// (2-chain PV). 128-key tiles, occupancy 2.
// smem: Qh@0 Ql@16384 | stages @32768 + s*32768: Kh(16KB)|Vh(16KB).
// ---------------------------------------------------------------------------
__global__ __launch_bounds__(256, 2) void mma_attn()
{
    __shared__ __align__(16) uint64_t abar[3];
    extern __shared__ __align__(128) char dyn[];

    const int qb = blockIdx.x;
    const int bh = blockIdx.y;
    const int tid  = threadIdx.x;
    const int lane = tid & 31;
    const int w    = tid >> 5;

    const uint32_t dynb = smem_u32(dyn);
    const uint32_t qbar = smem_u32(&abar[0]);
    const uint32_t fullb[2] = {smem_u32(&abar[1]), smem_u32(&abar[2])};

    if (tid == 0) {
        mbar_init(qbar, 1);
        mbar_init(fullb[0], 1);
        mbar_init(fullb[1], 1);
    }
    __syncthreads();

    const size_t hbase = (size_t)bh * 8;

    auto load_kv = [&](int s, int t) {
        uint32_t st = dynb + 32768u + (uint32_t)s * 32768u;
        uint32_t fb = fullb[s];
        size_t cb = (hbase + t) * 16384;
        mbar_expect_tx(fb, 32768u);
        bulkcp(st,          (char*)g_kh + cb, 16384, fb);
        bulkcp(st + 16384u, (char*)g_vh + cb, 16384, fb);
    };

    if (tid == 0) {
        size_t qcb = (hbase + qb) * 16384;
        mbar_expect_tx(qbar, 32768u);
        bulkcp(dynb,          (char*)g_qh + qcb, 16384, qbar);
        bulkcp(dynb + 16384u, (char*)g_ql + qcb, 16384, qbar);
        load_kv(0, 0);
        load_kv(1, 1);
    }

    const int k_nloc = (lane & 7) + ((lane >> 4) << 3);
    const int k_koff = ((lane >> 3) & 1) << 3;
    const int v_krl  = (lane & 7) + (((lane >> 3) & 1) << 3);
    const int v_dc   = (lane >> 4) << 3;
    const int qrow   = w * 16 + (lane & 15);
    const int qoff   = (lane >> 4) << 3;

    float O[8][4] = {};
    float rm0 = -INFINITY, rm1 = -INFINITY, rl0 = 0.f, rl1 = 0.f;
    int fph[2] = {0, 0};

    mbar_wait(qbar, 0);

    for (int t = 0; t < 8; t++) {
        int s = t & 1;
        mbar_wait(fullb[s], fph[s]); fph[s] ^= 1;
        uint32_t stb = dynb + 32768u + (uint32_t)s * 32768u;

        // ---- S = Q K^T (2 chains: qh + ql, K single) ----
        float sa[16][4] = {};
        #pragma unroll
        for (int kk = 0; kk < 4; kk++) {
            uint32_t qsw = swz128((uint32_t)(qrow * 128 + (kk * 16 + qoff) * 2));
            uint32_t q0, q1, q2, q3, l0, l1, l2, l3;
            ldsm4(q0, q1, q2, q3, dynb + qsw);
            ldsm4(l0, l1, l2, l3, dynb + 16384u + qsw);
            #pragma unroll
            for (int p = 0; p < 8; p++) {
                uint32_t sw = swz128((uint32_t)((k_nloc + p * 16) * 128 + (kk * 16 + k_koff) * 2));
                uint32_t r0, r1, r2, r3;
                ldsm4(r0, r1, r2, r3, stb + sw);
                mma16816(sa[2 * p],     q0, q1, q2, q3, r0, r1);
                mma16816(sa[2 * p],     l0, l1, l2, l3, r0, r1);
                mma16816(sa[2 * p + 1], q0, q1, q2, q3, r2, r3);
                mma16816(sa[2 * p + 1], l0, l1, l2, l3, r2, r3);
            }
        }

        // ---- online softmax (warp-local) ----
        float mx0 = -INFINITY, mx1 = -INFINITY;
        #pragma unroll
        for (int j = 0; j < 16; j++) {
            mx0 = fmaxf(mx0, fmaxf(sa[j][0], sa[j][1]));
            mx1 = fmaxf(mx1, fmaxf(sa[j][2], sa[j][3]));
        }
        mx0 = redmax4(mx0); mx1 = redmax4(mx1);
        float nm0 = fmaxf(rm0, mx0), nm1 = fmaxf(rm1, mx1);
        float al0 = __expf(rm0 - nm0), al1 = __expf(rm1 - nm1);
        rm0 = nm0; rm1 = nm1;
        float sm0 = 0.f, sm1 = 0.f;
        #pragma unroll
        for (int j = 0; j < 16; j++) {
            sa[j][0] = __expf(sa[j][0] - nm0);
            sa[j][1] = __expf(sa[j][1] - nm0);
            sa[j][2] = __expf(sa[j][2] - nm1);
            sa[j][3] = __expf(sa[j][3] - nm1);
            sm0 += sa[j][0] + sa[j][1];
            sm1 += sa[j][2] + sa[j][3];
        }
        sm0 = redsum4(sm0); sm1 = redsum4(sm1);
        rl0 = rl0 * al0 + sm0;
        rl1 = rl1 * al1 + sm1;
        #pragma unroll
        for (int nt = 0; nt < 8; nt++) {
            O[nt][0] *= al0; O[nt][1] *= al0;
            O[nt][2] *= al1; O[nt][3] *= al1;
        }

        // ---- O += P V (2 chains: ph + pl, V single) ----
        #pragma unroll
        for (int kk = 0; kk < 8; kk++) {
            uint32_t ph[4], pl[4];
            splitpack(sa[2 * kk][0],     sa[2 * kk][1],     ph[0], pl[0]);
            splitpack(sa[2 * kk][2],     sa[2 * kk][3],     ph[1], pl[1]);
            splitpack(sa[2 * kk + 1][0], sa[2 * kk + 1][1], ph[2], pl[2]);
            splitpack(sa[2 * kk + 1][2], sa[2 * kk + 1][3], ph[3], pl[3]);
            #pragma unroll
            for (int pd = 0; pd < 4; pd++) {
                uint32_t sw = swz128((uint32_t)((v_krl + kk * 16) * 128 + (pd * 16 + v_dc) * 2));
                uint32_t v0, v1, v2, v3;
                ldsm4t(v0, v1, v2, v3, stb + 16384u + sw);
                mma16816(O[2 * pd],     ph[0], ph[1], ph[2], ph[3], v0, v1);
                mma16816(O[2 * pd],     pl[0], pl[1], pl[2], pl[3], v0, v1);
                mma16816(O[2 * pd + 1], ph[0], ph[1], ph[2], ph[3], v2, v3);
                mma16816(O[2 * pd + 1], pl[0], pl[1], pl[2], pl[3], v2, v3);
            }
        }
        __syncthreads();
        if (t + 2 < 8 && tid == 0) load_kv(s, t + 2);
    }

    // normalize; write z into tiled/swizzled proj A-blocks (fp16 hi/lo).
    float inv0 = 1.0f / rl0, inv1 = 1.0f / rl1;
    const int b = bh >> 4, h = bh & 15;
    const int t0 = qb * 128 + w * 16 + (lane >> 2);
    const int cq = (lane & 3) * 2;
    #pragma unroll
    for (int nt = 0; nt < 8; nt++) {
        int kk = nt * 8 + cq;
        #pragma unroll
        for (int e = 0; e < 2; e++) {
            int m = b * NTOK + t0 + e * 8;
            int mb2 = m >> 7, r = m & 127;
            size_t base = ((size_t)mb2 * 16 + h) * 16384;
            uint32_t sw = swz128((uint32_t)(r * 128 + kk * 2));
            uint32_t zh, zl;
            splitpack(O[nt][2 * e] * (e ? inv1 : inv0),
                      O[nt][2 * e + 1] * (e ? inv1 : inv0), zh, zl);
            *(uint32_t*)((char*)g_zh + base + sw) = zh;
            *(uint32_t*)((char*)g_zl + base + sw) = zl;
        }
    }
}

// ---------------------------------------------------------------------------
extern "C" void kernel_launch(void* const* d_in, const int* in_sizes, int n_in,
                              void* d_out, int out_size)
{
    const float* x      = (const float*)d_in[0];
    const float* qkv_w  = (const float*)d_in[1];
    const float* qkv_b  = (const float*)d_in[2];
    const float* proj_w = (const float*)d_in[3];
    const float* proj_b = (const float*)d_in[4];
    float* out = (float*)d_out;

    const int M = B_SZ * NTOK;

    cudaFuncSetAttribute(mma_attn, cudaFuncAttributeMaxDynamicSharedMemorySize, 98304);
    cudaFuncSetAttribute((blk_gemm<0, 2>), cudaFuncAttributeMaxDynamicSharedMemorySize, 98304);
    cudaFuncSetAttribute((blk_gemm<0, 1>), cudaFuncAttributeMaxDynamicSharedMemorySize, 65536);
    cudaFuncSetAttribute((blk_gemm<1, 2>), cudaFuncAttributeMaxDynamicSharedMemorySize, 98304);

    __half *xh, *xl, *qwh, *pwh, *zh, *zl;
    cudaGetSymbolAddress((void**)&xh,  g_xh);
    cudaGetSymbolAddress((void**)&xl,  g_xl);
    cudaGetSymbolAddress((void**)&qwh, g_qwh);
    cudaGetSymbolAddress((void**)&pwh, g_pwh);
    cudaGetSymbolAddress((void**)&zh,  g_zh);
    cudaGetSymbolAddress((void**)&zl,  g_zl);

    dim3 blk(256);

    // 0) pre-split x (hi/lo) and round weights to fp16 tiled blocks
    split_tiled<<<(int)(MK / 4 / 256), blk>>>(x, xh, xl, (int)(MK / 4));
    round_tiled<<<(int)(QKV_W_N / 4 / 256), blk>>>(qkv_w, qwh, (int)(QKV_W_N / 4));
    round_tiled<<<(int)(PROJ_W_N / 4 / 256), blk>>>(proj_w, pwh, (int)(PROJ_W_N / 4));

    // 1a) Q part of QKV GEMM (2 chains, cols 0..1023)
    blk_gemm<0, 2><<<dim3(DMODEL / 128, M / 128), blk, 98304>>>(
        xh, xl, qwh, qkv_b, nullptr, 0);

    // 1b) K/V part of QKV GEMM (1 chain, cols 1024..3071)
    blk_gemm<0, 1><<<dim3(2 * DMODEL / 128, M / 128), blk, 65536>>>(
        xh, nullptr, qwh + (size_t)(DMODEL / 128) * 16 * 8192, qkv_b, nullptr, DMODEL);

    // 2) Flash attention (2-chain QK, 2-chain PV) -> z tiled/swizzled hi/lo
    mma_attn<<<dim3(NTOK / 128, B_SZ * NHEAD), blk, 98304>>>();

    // 3) Output projection (fp16 2-chain) -> out fp32
    blk_gemm<1, 2><<<dim3(DMODEL / 128, M / 128), blk, 98304>>>(
        zh, zl, pwh, proj_b, out, 0);
}

// round 11
// speedup vs baseline: 9.0400x; 1.2182x over previous
#include <cuda_runtime.h>
#include <cuda_fp16.h>
#include <math.h>
#include <stdint.h>
#include <stddef.h>

#define B_SZ   8
#define NTOK   1024
#define NHEAD  16
#define DHEAD  64
#define DMODEL 1024
#define SCALE  0.125f

#define MK ((size_t)B_SZ * NTOK * DMODEL)
#define QKV_W_N ((size_t)3 * DMODEL * DMODEL)
#define PROJ_W_N ((size_t)DMODEL * DMODEL)
#define HSZ ((size_t)B_SZ * NHEAD * NTOK * DHEAD)

// All operands pre-tiled into 128-row x 64-k SW128-swizzled 16KB blocks.
__device__ __align__(1024) __half g_xh[MK];                 // x rounded
__device__ __align__(1024) __half g_qwh[QKV_W_N];           // weights rounded
__device__ __align__(1024) __half g_pwh[PROJ_W_N];
__device__ __align__(1024) __half g_zh[MK];                 // z rounded
// q: hi/lo; k, v: hi only. Per (b,h): 8 chunks 128tok x 64d, swizzled.
__device__ __align__(1024) __half g_qh[HSZ], g_ql[HSZ];
__device__ __align__(1024) __half g_kh[HSZ];
__device__ __align__(1024) __half g_vh[HSZ];

// ---------------------------------------------------------------------------
// helpers
// ---------------------------------------------------------------------------
__device__ __forceinline__ uint32_t smem_u32(const void* p) {
    return (uint32_t)__cvta_generic_to_shared(p);
}
__device__ __forceinline__ uint32_t swz128(uint32_t b) {   // Swizzle<3,4,3>
    return b ^ ((b >> 3) & 0x70);
}
__device__ __forceinline__ void bulkcp(uint32_t dst, const void* src, uint32_t bytes,
                                       uint32_t mbar) {
    asm volatile(
        "cp.async.bulk.shared::cta.global.mbarrier::complete_tx::bytes [%0], [%1], %2, [%3];"
        :: "r"(dst), "l"(src), "r"(bytes), "r"(mbar) : "memory");
}
__device__ __forceinline__ void mbar_init(uint32_t mbar, uint32_t cnt) {
    asm volatile("mbarrier.init.shared.b64 [%0], %1;" :: "r"(mbar), "r"(cnt) : "memory");
}
__device__ __forceinline__ void mbar_expect_tx(uint32_t mbar, uint32_t bytes) {
    asm volatile("mbarrier.arrive.expect_tx.shared.b64 _, [%0], %1;"
                 :: "r"(mbar), "r"(bytes) : "memory");
}
__device__ __forceinline__ void mbar_wait(uint32_t mbar, uint32_t phase) {
    asm volatile(
        "{\n\t.reg .pred P;\n\t"
        "W_%=:\n\t"
        "mbarrier.try_wait.parity.acquire.cta.shared::cta.b64 P, [%0], %1, 0x989680;\n\t"
        "@P bra D_%=;\n\t"
        "bra W_%=;\n\t"
        "D_%=:\n\t}"
        :: "r"(mbar), "r"(phase) : "memory");
}
__device__ __forceinline__ void ldsm4(uint32_t& r0, uint32_t& r1, uint32_t& r2, uint32_t& r3,
                                      uint32_t a) {
    asm volatile("ldmatrix.sync.aligned.m8n8.x4.shared.b16 {%0,%1,%2,%3}, [%4];"
                 : "=r"(r0), "=r"(r1), "=r"(r2), "=r"(r3) : "r"(a));
}
__device__ __forceinline__ void ldsm4t(uint32_t& r0, uint32_t& r1, uint32_t& r2, uint32_t& r3,
                                       uint32_t a) {
    asm volatile("ldmatrix.sync.aligned.m8n8.x4.trans.shared.b16 {%0,%1,%2,%3}, [%4];"
                 : "=r"(r0), "=r"(r1), "=r"(r2), "=r"(r3) : "r"(a));
}
__device__ __forceinline__ void mma16816(float* c,
                                         uint32_t a0, uint32_t a1, uint32_t a2, uint32_t a3,
                                         uint32_t b0, uint32_t b1) {
    asm volatile(
        "mma.sync.aligned.m16n8k16.row.col.f32.f16.f16.f32 "
        "{%0,%1,%2,%3},{%4,%5,%6,%7},{%8,%9},{%0,%1,%2,%3};"
        : "+f"(c[0]), "+f"(c[1]), "+f"(c[2]), "+f"(c[3])
        : "r"(a0), "r"(a1), "r"(a2), "r"(a3), "r"(b0), "r"(b1));
}
__device__ __forceinline__ void splitpack(float a, float b, uint32_t& hi, uint32_t& lo) {
    __half2 h = __floats2half2_rn(a, b);
    float2 hf = __half22float2(h);
    __half2 l = __floats2half2_rn(a - hf.x, b - hf.y);
    hi = *reinterpret_cast<uint32_t*>(&h);
    lo = *reinterpret_cast<uint32_t*>(&l);
}
__device__ __forceinline__ float redmax4(float v) {
    v = fmaxf(v, __shfl_xor_sync(0xffffffffu, v, 1));
    v = fmaxf(v, __shfl_xor_sync(0xffffffffu, v, 2));
    return v;
}
__device__ __forceinline__ float redsum4(float v) {
    v += __shfl_xor_sync(0xffffffffu, v, 1);
    v += __shfl_xor_sync(0xffffffffu, v, 2);
    return v;
}

// ---------------------------------------------------------------------------
// fp32 -> fp16 round into tiled+swizzled 128x64 blocks (K = 1024).
// ---------------------------------------------------------------------------
__global__ __launch_bounds__(256) void round_tiled(const float* __restrict__ src,
                                                   __half* __restrict__ hi,
                                                   int n4)
{
    int i = blockIdx.x * blockDim.x + threadIdx.x;
    if (i >= n4) return;
    float4 v = reinterpret_cast<const float4*>(src)[i];
    int row = i >> 8;
    int k4  = i & 255;
    int kc  = k4 >> 4;
    int kk  = (k4 << 2) & 63;
    int rb  = row >> 7;
    int r   = row & 127;
    size_t base = ((size_t)rb * 16 + kc) * 16384;
    uint32_t sw = swz128((uint32_t)(r * 128 + kk * 2));
    __half* hp = (__half*)((char*)hi + base + sw);
    *reinterpret_cast<__half2*>(hp)     = __floats2half2_rn(v.x, v.y);
    *reinterpret_cast<__half2*>(hp + 2) = __floats2half2_rn(v.z, v.w);
}

// ---------------------------------------------------------------------------
// fp16 single-chain GEMM (mma.sync): C = Ah @ Wh^T + bias.
// CTA 128M x 128N, K-chunks of 64, 2-stage bulk pipeline, occupancy 2.
// Stage = Ah16|Wh16 = 32KB.
// EPI==0: scatter q hi/lo, k/v hi-only swizzled chunks (q pre-scaled).
// EPI==1: fp32 out (row width DMODEL).
// ---------------------------------------------------------------------------
template <int EPI>
__global__ __launch_bounds__(256, 2) void blk_gemm(const __half* __restrict__ Ah,
                                                   const __half* __restrict__ Wh,
                                                   const float* __restrict__ bias,
                                                   float* __restrict__ out)
{
    __shared__ __align__(16) uint64_t mbar[2];
    extern __shared__ __align__(128) char dyn[];

    const int tid  = threadIdx.x;
    const int lane = tid & 31;
    const int warp = tid >> 5;
    const int wm   = warp >> 2;
    const int wn   = warp & 3;
    const int mb   = blockIdx.y;
    const int nb   = blockIdx.x;

    const uint32_t dynb = smem_u32(dyn);
    const uint32_t fullb[2] = {smem_u32(&mbar[0]), smem_u32(&mbar[1])};

    if (tid == 0) { mbar_init(fullb[0], 1); mbar_init(fullb[1], 1); }
    __syncthreads();

    const char* pAh = (const char*)Ah + (size_t)mb * 16 * 16384;
    const char* pWh = (const char*)Wh + (size_t)nb * 16 * 16384;

    auto load_chunk = [&](int s, int c) {
        uint32_t st = dynb + (uint32_t)s * 32768u;
        uint32_t fb = fullb[s];
        mbar_expect_tx(fb, 32768u);
        bulkcp(st,          pAh + (size_t)c * 16384, 16384, fb);
        bulkcp(st + 16384u, pWh + (size_t)c * 16384, 16384, fb);
    };

    if (tid == 0) { load_chunk(0, 0); load_chunk(1, 1); }

    float acc[4][4][4] = {};

    const int a_row  = wm * 64 + (lane & 15);
    const int a_koff = (lane >> 4) << 3;
    const int b_n    = wn * 32 + (lane & 7) + ((lane >> 4) << 3);
    const int b_koff = ((lane >> 3) & 1) << 3;

    int fph[2] = {0, 0};

    for (int c = 0; c < 16; c++) {
        int s = c & 1;
        mbar_wait(fullb[s], fph[s]); fph[s] ^= 1;
        uint32_t stb = dynb + (uint32_t)s * 32768u;

        #pragma unroll
        for (int ks = 0; ks < 64; ks += 16) {
            uint32_t bh[4][2];
            #pragma unroll
            for (int p = 0; p < 2; p++) {
                uint32_t sw = swz128((uint32_t)((b_n + p * 16) * 128 + (ks + b_koff) * 2));
                uint32_t r0, r1, r2, r3;
                ldsm4(r0, r1, r2, r3, stb + 16384u + sw);
                bh[2 * p][0] = r0; bh[2 * p][1] = r1;
                bh[2 * p + 1][0] = r2; bh[2 * p + 1][1] = r3;
            }
            #pragma unroll
            for (int mt = 0; mt < 4; mt++) {
                uint32_t sw = swz128((uint32_t)((a_row + mt * 16) * 128 + (ks + a_koff) * 2));
                uint32_t a0, a1, a2, a3;
                ldsm4(a0, a1, a2, a3, stb + sw);
                #pragma unroll
                for (int nt = 0; nt < 4; nt++)
                    mma16816(acc[mt][nt], a0, a1, a2, a3, bh[nt][0], bh[nt][1]);
            }
        }
        __syncthreads();
        if (c + 2 < 16 && tid == 0) load_chunk(s, c + 2);
    }

    // epilogue
    const int row0 = mb * 128;
    const int col0 = nb * 128;
    const int r    = lane >> 2;
    const int cq   = (lane & 3) * 2;
    #pragma unroll
    for (int mt = 0; mt < 4; mt++) {
        int m0 = row0 + wm * 64 + mt * 16 + r;
        #pragma unroll
        for (int nt = 0; nt < 4; nt++) {
            int n = col0 + wn * 32 + nt * 8 + cq;
            float b0 = bias[n], b1 = bias[n + 1];
            float v00 = acc[mt][nt][0] + b0, v01 = acc[mt][nt][1] + b1;
            float v10 = acc[mt][nt][2] + b0, v11 = acc[mt][nt][3] + b1;
            if (EPI == 0) {
                #pragma unroll
                for (int e = 0; e < 4; e++) {
                    int m = m0 + (e >> 1) * 8;
                    int cc = n + (e & 1);
                    float val = (e == 0) ? v00 : (e == 1) ? v01 : (e == 2) ? v10 : v11;
                    int b    = m >> 10, t = m & 1023;
                    int part = cc >> 10, hc = cc & 1023;
                    int h = hc >> 6, hd = hc & 63;
                    size_t cbase = ((size_t)((b * NHEAD + h) * 8 + (t >> 7))) * 16384;
                    uint32_t sw = swz128((uint32_t)(((t & 127) << 7) + hd * 2));
                    if (part == 0) {
                        val *= SCALE;
                        __half hi = __float2half_rn(val);
                        __half lo = __float2half_rn(val - __half2float(hi));
                        *(__half*)((char*)g_qh + cbase + sw) = hi;
                        *(__half*)((char*)g_ql + cbase + sw) = lo;
                    } else if (part == 1) {
                        *(__half*)((char*)g_kh + cbase + sw) = __float2half_rn(val);
                    } else {
                        *(__half*)((char*)g_vh + cbase + sw) = __float2half_rn(val);
                    }
                }
            } else {
                *(float2*)&out[(size_t)m0 * DMODEL + n]       = make_float2(v00, v01);
                *(float2*)&out[(size_t)(m0 + 8) * DMODEL + n] = make_float2(v10, v11);
            }
        }
    }
}

// ---------------------------------------------------------------------------
// fp16 flash attention: Q hi/lo (2-chain QK), K/V single fp16, P hi/lo
// (2-chain PV). 128-key tiles, occupancy 2.
// smem: Qh@0 Ql@16384 | stages @32768 + s*32768: Kh(16KB)|Vh(16KB).
// Epilogue writes z as single fp16 (proj consumes single-chain).
// ---------------------------------------------------------------------------
__global__ __launch_bounds__(256, 2) void mma_attn()
{
    __shared__ __align__(16) uint64_t abar[3];
    extern __shared__ __align__(128) char dyn[];

    const int qb = blockIdx.x;
    const int bh = blockIdx.y;
    const int tid  = threadIdx.x;
    const int lane = tid & 31;
    const int w    = tid >> 5;

    const uint32_t dynb = smem_u32(dyn);
    const uint32_t qbar = smem_u32(&abar[0]);
    const uint32_t fullb[2] = {smem_u32(&abar[1]), smem_u32(&abar[2])};

    if (tid == 0) {
        mbar_init(qbar, 1);
        mbar_init(fullb[0], 1);
        mbar_init(fullb[1], 1);
    }
    __syncthreads();

    const size_t hbase = (size_t)bh * 8;

    auto load_kv = [&](int s, int t) {
        uint32_t st = dynb + 32768u + (uint32_t)s * 32768u;
        uint32_t fb = fullb[s];
        size_t cb = (hbase + t) * 16384;
        mbar_expect_tx(fb, 32768u);
        bulkcp(st,          (char*)g_kh + cb, 16384, fb);
        bulkcp(st + 16384u, (char*)g_vh + cb, 16384, fb);
    };

    if (tid == 0) {
        size_t qcb = (hbase + qb) * 16384;
        mbar_expect_tx(qbar, 32768u);
        bulkcp(dynb,          (char*)g_qh + qcb, 16384, qbar);
        bulkcp(dynb + 16384u, (char*)g_ql + qcb, 16384, qbar);
        load_kv(0, 0);
        load_kv(1, 1);
    }

    const int k_nloc = (lane & 7) + ((lane >> 4) << 3);
    const int k_koff = ((lane >> 3) & 1) << 3;
    const int v_krl  = (lane & 7) + (((lane >> 3) & 1) << 3);
    const int v_dc   = (lane >> 4) << 3;
    const int qrow   = w * 16 + (lane & 15);
    const int qoff   = (lane >> 4) << 3;

    float O[8][4] = {};
    float rm0 = -INFINITY, rm1 = -INFINITY, rl0 = 0.f, rl1 = 0.f;
    int fph[2] = {0, 0};

    mbar_wait(qbar, 0);

    for (int t = 0; t < 8; t++) {
        int s = t & 1;
        mbar_wait(fullb[s], fph[s]); fph[s] ^= 1;
        uint32_t stb = dynb + 32768u + (uint32_t)s * 32768u;

        // ---- S = Q K^T (2 chains: qh + ql, K single) ----
        float sa[16][4] = {};
        #pragma unroll
        for (int kk = 0; kk < 4; kk++) {
            uint32_t qsw = swz128((uint32_t)(qrow * 128 + (kk * 16 + qoff) * 2));
            uint32_t q0, q1, q2, q3, l0, l1, l2, l3;
            ldsm4(q0, q1, q2, q3, dynb + qsw);
            ldsm4(l0, l1, l2, l3, dynb + 16384u + qsw);
            #pragma unroll
            for (int p = 0; p < 8; p++) {
                uint32_t sw = swz128((uint32_t)((k_nloc + p * 16) * 128 + (kk * 16 + k_koff) * 2));
                uint32_t r0, r1, r2, r3;
                ldsm4(r0, r1, r2, r3, stb + sw);
                mma16816(sa[2 * p],     q0, q1, q2, q3, r0, r1);
                mma16816(sa[2 * p],     l0, l1, l2, l3, r0, r1);
                mma16816(sa[2 * p + 1], q0, q1, q2, q3, r2, r3);
                mma16816(sa[2 * p + 1], l0, l1, l2, l3, r2, r3);
            }
        }

        // ---- online softmax (warp-local) ----
        float mx0 = -INFINITY, mx1 = -INFINITY;
        #pragma unroll
        for (int j = 0; j < 16; j++) {
            mx0 = fmaxf(mx0, fmaxf(sa[j][0], sa[j][1]));
            mx1 = fmaxf(mx1, fmaxf(sa[j][2], sa[j][3]));
        }
        mx0 = redmax4(mx0); mx1 = redmax4(mx1);
        float nm0 = fmaxf(rm0, mx0), nm1 = fmaxf(rm1, mx1);
        float al0 = __expf(rm0 - nm0), al1 = __expf(rm1 - nm1);
        rm0 = nm0; rm1 = nm1;
        float sm0 = 0.f, sm1 = 0.f;
        #pragma unroll
        for (int j = 0; j < 16; j++) {
            sa[j][0] = __expf(sa[j][0] - nm0);
            sa[j][1] = __expf(sa[j][1] - nm0);
            sa[j][2] = __expf(sa[j][2] - nm1);
            sa[j][3] = __expf(sa[j][3] - nm1);
            sm0 += sa[j][0] + sa[j][1];
            sm1 += sa[j][2] + sa[j][3];
        }
        sm0 = redsum4(sm0); sm1 = redsum4(sm1);
        rl0 = rl0 * al0 + sm0;
        rl1 = rl1 * al1 + sm1;
        #pragma unroll
        for (int nt = 0; nt < 8; nt++) {
            O[nt][0] *= al0; O[nt][1] *= al0;
            O[nt][2] *= al1; O[nt][3] *= al1;
        }

        // ---- O += P V (2 chains: ph + pl, V single) ----
        #pragma unroll
        for (int kk = 0; kk < 8; kk++) {
            uint32_t ph[4], pl[4];
            splitpack(sa[2 * kk][0],     sa[2 * kk][1],     ph[0], pl[0]);
            splitpack(sa[2 * kk][2],     sa[2 * kk][3],     ph[1], pl[1]);
            splitpack(sa[2 * kk + 1][0], sa[2 * kk + 1][1], ph[2], pl[2]);
            splitpack(sa[2 * kk + 1][2], sa[2 * kk + 1][3], ph[3], pl[3]);
            #pragma unroll
            for (int pd = 0; pd < 4; pd++) {
                uint32_t sw = swz128((uint32_t)((v_krl + kk * 16) * 128 + (pd * 16 + v_dc) * 2));
                uint32_t v0, v1, v2, v3;
                ldsm4t(v0, v1, v2, v3, stb + 16384u + sw);
                mma16816(O[2 * pd],     ph[0], ph[1], ph[2], ph[3], v0, v1);
                mma16816(O[2 * pd],     pl[0], pl[1], pl[2], pl[3], v0, v1);
                mma16816(O[2 * pd + 1], ph[0], ph[1], ph[2], ph[3], v2, v3);
                mma16816(O[2 * pd + 1], pl[0], pl[1], pl[2], pl[3], v2, v3);
            }
        }
        __syncthreads();
        if (t + 2 < 8 && tid == 0) load_kv(s, t + 2);
    }

    // normalize; write z (single fp16) into tiled/swizzled proj A-blocks.
    float inv0 = 1.0f / rl0, inv1 = 1.0f / rl1;
    const int b = bh >> 4, h = bh & 15;
    const int t0 = qb * 128 + w * 16 + (lane >> 2);
    const int cq = (lane & 3) * 2;
    #pragma unroll
    for (int nt = 0; nt < 8; nt++) {
        int kk = nt * 8 + cq;
        #pragma unroll
        for (int e = 0; e < 2; e++) {
            int m = b * NTOK + t0 + e * 8;
            int mb2 = m >> 7, r = m & 127;
            size_t base = ((size_t)mb2 * 16 + h) * 16384;
            uint32_t sw = swz128((uint32_t)(r * 128 + kk * 2));
            float inv = e ? inv1 : inv0;
            __half2 zz = __floats2half2_rn(O[nt][2 * e] * inv, O[nt][2 * e + 1] * inv);
            *(__half2*)((char*)g_zh + base + sw) = zz;
        }
    }
}

// ---------------------------------------------------------------------------
extern "C" void kernel_launch(void* const* d_in, const int* in_sizes, int n_in,
                              void* d_out, int out_size)
{
    const float* x      = (const float*)d_in[0];
    const float* qkv_w  = (const float*)d_in[1];
    const float* qkv_b  = (const float*)d_in[2];
    const float* proj_w = (const float*)d_in[3];
    const float* proj_b = (const float*)d_in[4];
    float* out = (float*)d_out;

    const int M = B_SZ * NTOK;

    cudaFuncSetAttribute(mma_attn, cudaFuncAttributeMaxDynamicSharedMemorySize, 98304);
    cudaFuncSetAttribute(blk_gemm<0>, cudaFuncAttributeMaxDynamicSharedMemorySize, 65536);
    cudaFuncSetAttribute(blk_gemm<1>, cudaFuncAttributeMaxDynamicSharedMemorySize, 65536);

    __half *xh, *qwh, *pwh, *zh;
    cudaGetSymbolAddress((void**)&xh,  g_xh);
    cudaGetSymbolAddress((void**)&qwh, g_qwh);
    cudaGetSymbolAddress((void**)&pwh, g_pwh);
    cudaGetSymbolAddress((void**)&zh,  g_zh);

    dim3 blk(256);

    // 0) round x and weights to fp16 tiled/swizzled blocks
    round_tiled<<<(int)(MK / 4 / 256), blk>>>(x, xh, (int)(MK / 4));
    round_tiled<<<(int)(QKV_W_N / 4 / 256), blk>>>(qkv_w, qwh, (int)(QKV_W_N / 4));
    round_tiled<<<(int)(PROJ_W_N / 4 / 256), blk>>>(proj_w, pwh, (int)(PROJ_W_N / 4));

    // 1) QKV GEMM (single-chain, all 3072 cols) -> q hi/lo, k/v single fp16
    blk_gemm<0><<<dim3(3 * DMODEL / 128, M / 128), blk, 65536>>>(
        xh, qwh, qkv_b, nullptr);

    // 2) Flash attention (2-chain QK, 2-chain PV) -> z single fp16
    mma_attn<<<dim3(NTOK / 128, B_SZ * NHEAD), blk, 98304>>>();

    // 3) Output projection (single-chain) -> out fp32
    blk_gemm<1><<<dim3(DMODEL / 128, M / 128), blk, 65536>>>(
        zh, pwh, proj_b, out);
}

// round 12
// speedup vs baseline: 10.7019x; 1.1838x over previous
#include <cuda_runtime.h>
#include <cuda_fp16.h>
#include <math.h>
#include <stdint.h>
#include <stddef.h>

#define B_SZ   8
#define NTOK   1024
#define NHEAD  16
#define DHEAD  64
#define DMODEL 1024
#define SCALE  0.125f

#define MK ((size_t)B_SZ * NTOK * DMODEL)
#define QKV_W_N ((size_t)3 * DMODEL * DMODEL)
#define PROJ_W_N ((size_t)DMODEL * DMODEL)
#define HSZ ((size_t)B_SZ * NHEAD * NTOK * DHEAD)

// All operands pre-tiled into 128-row x 64-k SW128-swizzled 16KB blocks.
__device__ __align__(1024) __half g_xh[MK];                 // x rounded
__device__ __align__(1024) __half g_qwh[QKV_W_N];           // weights rounded
__device__ __align__(1024) __half g_pwh[PROJ_W_N];
__device__ __align__(1024) __half g_zh[MK];                 // z rounded
// q/k/v: single fp16. Per (b,h): 8 chunks 128tok x 64d, swizzled.
__device__ __align__(1024) __half g_qh[HSZ];
__device__ __align__(1024) __half g_kh[HSZ];
__device__ __align__(1024) __half g_vh[HSZ];

// ---------------------------------------------------------------------------
// helpers
// ---------------------------------------------------------------------------
__device__ __forceinline__ uint32_t smem_u32(const void* p) {
    return (uint32_t)__cvta_generic_to_shared(p);
}
__device__ __forceinline__ uint32_t swz128(uint32_t b) {   // Swizzle<3,4,3>
    return b ^ ((b >> 3) & 0x70);
}
__device__ __forceinline__ void bulkcp(uint32_t dst, const void* src, uint32_t bytes,
                                       uint32_t mbar) {
    asm volatile(
        "cp.async.bulk.shared::cta.global.mbarrier::complete_tx::bytes [%0], [%1], %2, [%3];"
        :: "r"(dst), "l"(src), "r"(bytes), "r"(mbar) : "memory");
}
__device__ __forceinline__ void mbar_init(uint32_t mbar, uint32_t cnt) {
    asm volatile("mbarrier.init.shared.b64 [%0], %1;" :: "r"(mbar), "r"(cnt) : "memory");
}
__device__ __forceinline__ void mbar_expect_tx(uint32_t mbar, uint32_t bytes) {
    asm volatile("mbarrier.arrive.expect_tx.shared.b64 _, [%0], %1;"
                 :: "r"(mbar), "r"(bytes) : "memory");
}
__device__ __forceinline__ void mbar_wait(uint32_t mbar, uint32_t phase) {
    asm volatile(
        "{\n\t.reg .pred P;\n\t"
        "W_%=:\n\t"
        "mbarrier.try_wait.parity.acquire.cta.shared::cta.b64 P, [%0], %1, 0x989680;\n\t"
        "@P bra D_%=;\n\t"
        "bra W_%=;\n\t"
        "D_%=:\n\t}"
        :: "r"(mbar), "r"(phase) : "memory");
}
__device__ __forceinline__ void ldsm4(uint32_t& r0, uint32_t& r1, uint32_t& r2, uint32_t& r3,
                                      uint32_t a) {
    asm volatile("ldmatrix.sync.aligned.m8n8.x4.shared.b16 {%0,%1,%2,%3}, [%4];"
                 : "=r"(r0), "=r"(r1), "=r"(r2), "=r"(r3) : "r"(a));
}
__device__ __forceinline__ void ldsm4t(uint32_t& r0, uint32_t& r1, uint32_t& r2, uint32_t& r3,
                                       uint32_t a) {
    asm volatile("ldmatrix.sync.aligned.m8n8.x4.trans.shared.b16 {%0,%1,%2,%3}, [%4];"
                 : "=r"(r0), "=r"(r1), "=r"(r2), "=r"(r3) : "r"(a));
}
__device__ __forceinline__ void mma16816(float* c,
                                         uint32_t a0, uint32_t a1, uint32_t a2, uint32_t a3,
                                         uint32_t b0, uint32_t b1) {
    asm volatile(
        "mma.sync.aligned.m16n8k16.row.col.f32.f16.f16.f32 "
        "{%0,%1,%2,%3},{%4,%5,%6,%7},{%8,%9},{%0,%1,%2,%3};"
        : "+f"(c[0]), "+f"(c[1]), "+f"(c[2]), "+f"(c[3])
        : "r"(a0), "r"(a1), "r"(a2), "r"(a3), "r"(b0), "r"(b1));
}
__device__ __forceinline__ uint32_t hpack(float a, float b) {
    __half2 h = __floats2half2_rn(a, b);
    return *reinterpret_cast<uint32_t*>(&h);
}
__device__ __forceinline__ float redmax4(float v) {
    v = fmaxf(v, __shfl_xor_sync(0xffffffffu, v, 1));
    v = fmaxf(v, __shfl_xor_sync(0xffffffffu, v, 2));
    return v;
}
__device__ __forceinline__ float redsum4(float v) {
    v += __shfl_xor_sync(0xffffffffu, v, 1);
    v += __shfl_xor_sync(0xffffffffu, v, 2);
    return v;
}

// ---------------------------------------------------------------------------
// fp32 -> fp16 round into tiled+swizzled 128x64 blocks (K = 1024).
// ---------------------------------------------------------------------------
__global__ __launch_bounds__(256) void round_tiled(const float* __restrict__ src,
                                                   __half* __restrict__ hi,
                                                   int n4)
{
    int i = blockIdx.x * blockDim.x + threadIdx.x;
    if (i >= n4) return;
    float4 v = reinterpret_cast<const float4*>(src)[i];
    int row = i >> 8;
    int k4  = i & 255;
    int kc  = k4 >> 4;
    int kk  = (k4 << 2) & 63;
    int rb  = row >> 7;
    int r   = row & 127;
    size_t base = ((size_t)rb * 16 + kc) * 16384;
    uint32_t sw = swz128((uint32_t)(r * 128 + kk * 2));
    __half* hp = (__half*)((char*)hi + base + sw);
    *reinterpret_cast<__half2*>(hp)     = __floats2half2_rn(v.x, v.y);
    *reinterpret_cast<__half2*>(hp + 2) = __floats2half2_rn(v.z, v.w);
}

// ---------------------------------------------------------------------------
// fp16 single-chain GEMM (mma.sync): C = Ah @ Wh^T + bias.
// CTA 128M x 128N, K-chunks of 64, 2-stage bulk pipeline, occupancy 2.
// Stage = Ah16|Wh16 = 32KB.
// EPI==0: scatter q/k/v single-fp16 swizzled chunks (q pre-scaled).
// EPI==1: fp32 out (row width DMODEL).
// ---------------------------------------------------------------------------
template <int EPI>
__global__ __launch_bounds__(256, 2) void blk_gemm(const __half* __restrict__ Ah,
                                                   const __half* __restrict__ Wh,
                                                   const float* __restrict__ bias,
                                                   float* __restrict__ out)
{
    __shared__ __align__(16) uint64_t mbar[2];
    extern __shared__ __align__(128) char dyn[];

    const int tid  = threadIdx.x;
    const int lane = tid & 31;
    const int warp = tid >> 5;
    const int wm   = warp >> 2;
    const int wn   = warp & 3;
    const int mb   = blockIdx.y;
    const int nb   = blockIdx.x;

    const uint32_t dynb = smem_u32(dyn);
    const uint32_t fullb[2] = {smem_u32(&mbar[0]), smem_u32(&mbar[1])};

    if (tid == 0) { mbar_init(fullb[0], 1); mbar_init(fullb[1], 1); }
    __syncthreads();

    const char* pAh = (const char*)Ah + (size_t)mb * 16 * 16384;
    const char* pWh = (const char*)Wh + (size_t)nb * 16 * 16384;

    auto load_chunk = [&](int s, int c) {
        uint32_t st = dynb + (uint32_t)s * 32768u;
        uint32_t fb = fullb[s];
        mbar_expect_tx(fb, 32768u);
        bulkcp(st,          pAh + (size_t)c * 16384, 16384, fb);
        bulkcp(st + 16384u, pWh + (size_t)c * 16384, 16384, fb);
    };

    if (tid == 0) { load_chunk(0, 0); load_chunk(1, 1); }

    float acc[4][4][4] = {};

    const int a_row  = wm * 64 + (lane & 15);
    const int a_koff = (lane >> 4) << 3;
    const int b_n    = wn * 32 + (lane & 7) + ((lane >> 4) << 3);
    const int b_koff = ((lane >> 3) & 1) << 3;

    int fph[2] = {0, 0};

    for (int c = 0; c < 16; c++) {
        int s = c & 1;
        mbar_wait(fullb[s], fph[s]); fph[s] ^= 1;
        uint32_t stb = dynb + (uint32_t)s * 32768u;

        #pragma unroll
        for (int ks = 0; ks < 64; ks += 16) {
            uint32_t bh[4][2];
            #pragma unroll
            for (int p = 0; p < 2; p++) {
                uint32_t sw = swz128((uint32_t)((b_n + p * 16) * 128 + (ks + b_koff) * 2));
                uint32_t r0, r1, r2, r3;
                ldsm4(r0, r1, r2, r3, stb + 16384u + sw);
                bh[2 * p][0] = r0; bh[2 * p][1] = r1;
                bh[2 * p + 1][0] = r2; bh[2 * p + 1][1] = r3;
            }
            #pragma unroll
            for (int mt = 0; mt < 4; mt++) {
                uint32_t sw = swz128((uint32_t)((a_row + mt * 16) * 128 + (ks + a_koff) * 2));
                uint32_t a0, a1, a2, a3;
                ldsm4(a0, a1, a2, a3, stb + sw);
                #pragma unroll
                for (int nt = 0; nt < 4; nt++)
                    mma16816(acc[mt][nt], a0, a1, a2, a3, bh[nt][0], bh[nt][1]);
            }
        }
        __syncthreads();
        if (c + 2 < 16 && tid == 0) load_chunk(s, c + 2);
    }

    // epilogue
    const int row0 = mb * 128;
    const int col0 = nb * 128;
    const int r    = lane >> 2;
    const int cq   = (lane & 3) * 2;
    #pragma unroll
    for (int mt = 0; mt < 4; mt++) {
        int m0 = row0 + wm * 64 + mt * 16 + r;
        #pragma unroll
        for (int nt = 0; nt < 4; nt++) {
            int n = col0 + wn * 32 + nt * 8 + cq;
            float b0 = bias[n], b1 = bias[n + 1];
            float v00 = acc[mt][nt][0] + b0, v01 = acc[mt][nt][1] + b1;
            float v10 = acc[mt][nt][2] + b0, v11 = acc[mt][nt][3] + b1;
            if (EPI == 0) {
                #pragma unroll
                for (int e = 0; e < 4; e++) {
                    int m = m0 + (e >> 1) * 8;
                    int cc = n + (e & 1);
                    float val = (e == 0) ? v00 : (e == 1) ? v01 : (e == 2) ? v10 : v11;
                    int b    = m >> 10, t = m & 1023;
                    int part = cc >> 10, hc = cc & 1023;
                    int h = hc >> 6, hd = hc & 63;
                    size_t cbase = ((size_t)((b * NHEAD + h) * 8 + (t >> 7))) * 16384;
                    uint32_t sw = swz128((uint32_t)(((t & 127) << 7) + hd * 2));
                    char* dst;
                    if (part == 0)      { val *= SCALE; dst = (char*)g_qh; }
                    else if (part == 1) { dst = (char*)g_kh; }
                    else                { dst = (char*)g_vh; }
                    *(__half*)(dst + cbase + sw) = __float2half_rn(val);
                }
            } else {
                *(float2*)&out[(size_t)m0 * DMODEL + n]       = make_float2(v00, v01);
                *(float2*)&out[(size_t)(m0 + 8) * DMODEL + n] = make_float2(v10, v11);
            }
        }
    }
}

// ---------------------------------------------------------------------------
// fp16 flash attention, fully single-precision fp16 operands.
// Q frags hoisted to registers; 128-key tiles, occupancy 2.
// smem: Q@0 (16KB) | stages @16384 + s*32768: Kh(16KB)|Vh(16KB). 81920 B.
// ---------------------------------------------------------------------------
__global__ __launch_bounds__(256, 2) void mma_attn()
{
    __shared__ __align__(16) uint64_t abar[3];
    extern __shared__ __align__(128) char dyn[];

    const int qb = blockIdx.x;
    const int bh = blockIdx.y;
    const int tid  = threadIdx.x;
    const int lane = tid & 31;
    const int w    = tid >> 5;

    const uint32_t dynb = smem_u32(dyn);
    const uint32_t qbar = smem_u32(&abar[0]);
    const uint32_t fullb[2] = {smem_u32(&abar[1]), smem_u32(&abar[2])};

    if (tid == 0) {
        mbar_init(qbar, 1);
        mbar_init(fullb[0], 1);
        mbar_init(fullb[1], 1);
    }
    __syncthreads();

    const size_t hbase = (size_t)bh * 8;

    auto load_kv = [&](int s, int t) {
        uint32_t st = dynb + 16384u + (uint32_t)s * 32768u;
        uint32_t fb = fullb[s];
        size_t cb = (hbase + t) * 16384;
        mbar_expect_tx(fb, 32768u);
        bulkcp(st,          (char*)g_kh + cb, 16384, fb);
        bulkcp(st + 16384u, (char*)g_vh + cb, 16384, fb);
    };

    if (tid == 0) {
        size_t qcb = (hbase + qb) * 16384;
        mbar_expect_tx(qbar, 16384u);
        bulkcp(dynb, (char*)g_qh + qcb, 16384, qbar);
        load_kv(0, 0);
        load_kv(1, 1);
    }

    const int k_nloc = (lane & 7) + ((lane >> 4) << 3);
    const int k_koff = ((lane >> 3) & 1) << 3;
    const int v_krl  = (lane & 7) + (((lane >> 3) & 1) << 3);
    const int v_dc   = (lane >> 4) << 3;
    const int qrow   = w * 16 + (lane & 15);
    const int qoff   = (lane >> 4) << 3;

    // ---- hoist Q fragments into registers (16 regs) ----
    uint32_t qf[4][4];
    mbar_wait(qbar, 0);
    #pragma unroll
    for (int kk = 0; kk < 4; kk++) {
        uint32_t qsw = swz128((uint32_t)(qrow * 128 + (kk * 16 + qoff) * 2));
        ldsm4(qf[kk][0], qf[kk][1], qf[kk][2], qf[kk][3], dynb + qsw);
    }

    float O[8][4] = {};
    float rm0 = -INFINITY, rm1 = -INFINITY, rl0 = 0.f, rl1 = 0.f;
    int fph[2] = {0, 0};

    for (int t = 0; t < 8; t++) {
        int s = t & 1;
        mbar_wait(fullb[s], fph[s]); fph[s] ^= 1;
        uint32_t stb = dynb + 16384u + (uint32_t)s * 32768u;

        // ---- S = Q K^T (single chain) ----
        float sa[16][4] = {};
        #pragma unroll
        for (int kk = 0; kk < 4; kk++) {
            #pragma unroll
            for (int p = 0; p < 8; p++) {
                uint32_t sw = swz128((uint32_t)((k_nloc + p * 16) * 128 + (kk * 16 + k_koff) * 2));
                uint32_t r0, r1, r2, r3;
                ldsm4(r0, r1, r2, r3, stb + sw);
                mma16816(sa[2 * p],     qf[kk][0], qf[kk][1], qf[kk][2], qf[kk][3], r0, r1);
                mma16816(sa[2 * p + 1], qf[kk][0], qf[kk][1], qf[kk][2], qf[kk][3], r2, r3);
            }
        }

        // ---- online softmax (warp-local) ----
        float mx0 = -INFINITY, mx1 = -INFINITY;
        #pragma unroll
        for (int j = 0; j < 16; j++) {
            mx0 = fmaxf(mx0, fmaxf(sa[j][0], sa[j][1]));
            mx1 = fmaxf(mx1, fmaxf(sa[j][2], sa[j][3]));
        }
        mx0 = redmax4(mx0); mx1 = redmax4(mx1);
        float nm0 = fmaxf(rm0, mx0), nm1 = fmaxf(rm1, mx1);
        float al0 = __expf(rm0 - nm0), al1 = __expf(rm1 - nm1);
        rm0 = nm0; rm1 = nm1;
        float sm0 = 0.f, sm1 = 0.f;
        #pragma unroll
        for (int j = 0; j < 16; j++) {
            sa[j][0] = __expf(sa[j][0] - nm0);
            sa[j][1] = __expf(sa[j][1] - nm0);
            sa[j][2] = __expf(sa[j][2] - nm1);
            sa[j][3] = __expf(sa[j][3] - nm1);
            sm0 += sa[j][0] + sa[j][1];
            sm1 += sa[j][2] + sa[j][3];
        }
        sm0 = redsum4(sm0); sm1 = redsum4(sm1);
        rl0 = rl0 * al0 + sm0;
        rl1 = rl1 * al1 + sm1;
        #pragma unroll
        for (int nt = 0; nt < 8; nt++) {
            O[nt][0] *= al0; O[nt][1] *= al0;
            O[nt][2] *= al1; O[nt][3] *= al1;
        }

        // ---- O += P V (single chain: P rounded) ----
        #pragma unroll
        for (int kk = 0; kk < 8; kk++) {
            uint32_t p0 = hpack(sa[2 * kk][0],     sa[2 * kk][1]);
            uint32_t p1 = hpack(sa[2 * kk][2],     sa[2 * kk][3]);
            uint32_t p2 = hpack(sa[2 * kk + 1][0], sa[2 * kk + 1][1]);
            uint32_t p3 = hpack(sa[2 * kk + 1][2], sa[2 * kk + 1][3]);
            #pragma unroll
            for (int pd = 0; pd < 4; pd++) {
                uint32_t sw = swz128((uint32_t)((v_krl + kk * 16) * 128 + (pd * 16 + v_dc) * 2));
                uint32_t v0, v1, v2, v3;
                ldsm4t(v0, v1, v2, v3, stb + 16384u + sw);
                mma16816(O[2 * pd],     p0, p1, p2, p3, v0, v1);
                mma16816(O[2 * pd + 1], p0, p1, p2, p3, v2, v3);
            }
        }
        __syncthreads();
        if (t + 2 < 8 && tid == 0) load_kv(s, t + 2);
    }

    // normalize; write z (single fp16) into tiled/swizzled proj A-blocks.
    float inv0 = 1.0f / rl0, inv1 = 1.0f / rl1;
    const int b = bh >> 4, h = bh & 15;
    const int t0 = qb * 128 + w * 16 + (lane >> 2);
    const int cq = (lane & 3) * 2;
    #pragma unroll
    for (int nt = 0; nt < 8; nt++) {
        int kk = nt * 8 + cq;
        #pragma unroll
        for (int e = 0; e < 2; e++) {
            int m = b * NTOK + t0 + e * 8;
            int mb2 = m >> 7, r = m & 127;
            size_t base = ((size_t)mb2 * 16 + h) * 16384;
            uint32_t sw = swz128((uint32_t)(r * 128 + kk * 2));
            float inv = e ? inv1 : inv0;
            __half2 zz = __floats2half2_rn(O[nt][2 * e] * inv, O[nt][2 * e + 1] * inv);
            *(__half2*)((char*)g_zh + base + sw) = zz;
        }
    }
}

// ---------------------------------------------------------------------------
extern "C" void kernel_launch(void* const* d_in, const int* in_sizes, int n_in,
                              void* d_out, int out_size)
{
    const float* x      = (const float*)d_in[0];
    const float* qkv_w  = (const float*)d_in[1];
    const float* qkv_b  = (const float*)d_in[2];
    const float* proj_w = (const float*)d_in[3];
    const float* proj_b = (const float*)d_in[4];
    float* out = (float*)d_out;

    const int M = B_SZ * NTOK;

    cudaFuncSetAttribute(mma_attn, cudaFuncAttributeMaxDynamicSharedMemorySize, 81920);
    cudaFuncSetAttribute(blk_gemm<0>, cudaFuncAttributeMaxDynamicSharedMemorySize, 65536);
    cudaFuncSetAttribute(blk_gemm<1>, cudaFuncAttributeMaxDynamicSharedMemorySize, 65536);

    __half *xh, *qwh, *pwh, *zh;
    cudaGetSymbolAddress((void**)&xh,  g_xh);
    cudaGetSymbolAddress((void**)&qwh, g_qwh);
    cudaGetSymbolAddress((void**)&pwh, g_pwh);
    cudaGetSymbolAddress((void**)&zh,  g_zh);

    dim3 blk(256);

    // 0) round x and weights to fp16 tiled/swizzled blocks
    round_tiled<<<(int)(MK / 4 / 256), blk>>>(x, xh, (int)(MK / 4));
    round_tiled<<<(int)(QKV_W_N / 4 / 256), blk>>>(qkv_w, qwh, (int)(QKV_W_N / 4));
    round_tiled<<<(int)(PROJ_W_N / 4 / 256), blk>>>(proj_w, pwh, (int)(PROJ_W_N / 4));

    // 1) QKV GEMM (single-chain) -> q/k/v single fp16 swizzled chunks
    blk_gemm<0><<<dim3(3 * DMODEL / 128, M / 128), blk, 65536>>>(
        xh, qwh, qkv_b, nullptr);

    // 2) Flash attention (single-chain QK and PV) -> z single fp16
    mma_attn<<<dim3(NTOK / 128, B_SZ * NHEAD), blk, 81920>>>();

    // 3) Output projection (single-chain) -> out fp32
    blk_gemm<1><<<dim3(DMODEL / 128, M / 128), blk, 65536>>>(
        zh, pwh, proj_b, out);
}